// round 3
// baseline (speedup 1.0000x reference)
#include <cuda_runtime.h>
#include <math.h>

#define Hd 64
#define Wd 64
#define HW 4096
#define Cc 128
#define Bn 4
#define OUTC 256
#define EPSf 1e-5f

// ---------------- scratch (device globals: allocation-free) ----------------
__device__ float g_dw[2][Bn][Cc][HW];        // Fi_dw, Fw_dw           16 MB
__device__ float g_qkv[6][Bn][Cc][HW];       // Qi,Ki,Vi,Qw,Kw,Vw      48 MB
__device__ float g_S[2][Bn][HW][HW];         // S1, S2                536 MB
__device__ float g_mx[2][Bn][HW];
__device__ float g_rs[2][Bn][HW];
__device__ float g_xcat[Bn][512][HW];        // [A_i; A_w; F_i; F_w]   32 MB
__device__ float g_wcat[OUTC][512];
__device__ float g_bcat[OUTC];

// ---------------- BN (eval) + depthwise 3x3 SAME, fused ----------------
__global__ void __launch_bounds__(256) bn_dw_kernel(
    const float* __restrict__ x, const float* __restrict__ gamma,
    const float* __restrict__ beta, const float* __restrict__ mean,
    const float* __restrict__ var, const float* __restrict__ wdw,
    const float* __restrict__ bdw, float* __restrict__ y)
{
    __shared__ float tile[66 * 66];
    int bc = blockIdx.x;            // b*128 + c
    int c = bc & 127;
    const float* xp = x + (size_t)bc * HW;
    float sc = gamma[c] * rsqrtf(var[c] + EPSf);
    float sh = beta[c] - mean[c] * sc;
    for (int idx = threadIdx.x; idx < 66 * 66; idx += 256) {
        int r = idx / 66 - 1, col = idx % 66 - 1;
        float v = 0.f;
        if (r >= 0 && r < 64 && col >= 0 && col < 64)
            v = xp[r * 64 + col] * sc + sh;   // pad zeros AFTER normalize (matches SAME conv of Fn)
        tile[idx] = v;
    }
    __syncthreads();
    float w0 = wdw[c*9+0], w1 = wdw[c*9+1], w2 = wdw[c*9+2];
    float w3 = wdw[c*9+3], w4 = wdw[c*9+4], w5 = wdw[c*9+5];
    float w6 = wdw[c*9+6], w7 = wdw[c*9+7], w8 = wdw[c*9+8];
    float bb = bdw[c];
    float* yp = y + (size_t)bc * HW;
    for (int idx = threadIdx.x; idx < HW; idx += 256) {
        int r = idx >> 6, col = idx & 63;
        const float* t = &tile[r * 66 + col];
        float s = bb;
        s += t[0]   * w0 + t[1]   * w1 + t[2]   * w2;
        s += t[66]  * w3 + t[67]  * w4 + t[68]  * w5;
        s += t[132] * w6 + t[133] * w7 + t[134] * w8;
        yp[idx] = s;
    }
}

// ---------------- generic 128x128x8 SGEMM, NN (A row-major [M,K]) ----------------
// C[b][m][n] = sum_k A[m][k] * f(B[b][k][n]) + bias[m]
// f = exp(x - mx[k]) * rs[k] when mx != nullptr (softmax-normalize applied to B rows).
__global__ void __launch_bounds__(256) gemm_nn(
    const float* __restrict__ A, const float* __restrict__ B,
    float* __restrict__ Cp, const float* __restrict__ bias,
    const float* __restrict__ mx, const float* __restrict__ rs,
    int N, int K,
    long long bsA, long long bsB, long long bsC)
{
    int b = blockIdx.z;
    A += (long long)b * bsA;
    B += (long long)b * bsB;
    Cp += (long long)b * bsC;
    const float* mxp = mx ? mx + (long long)b * HW : nullptr;
    const float* rsp = rs ? rs + (long long)b * HW : nullptr;
    int m0 = blockIdx.y * 128, n0 = blockIdx.x * 128;

    __shared__ float As[8][128];
    __shared__ float Bs[8][128];
    float acc[8][8];
#pragma unroll
    for (int i = 0; i < 8; i++)
#pragma unroll
        for (int j = 0; j < 8; j++) acc[i][j] = 0.f;

    int tid = threadIdx.x;
    int tx = tid & 15, ty = tid >> 4;
    int ra = tid >> 1, ka = (tid & 1) * 4;     // A: 128 rows x 8 k
    int kb = tid >> 5, cb = (tid & 31) * 4;    // B: 8 k x 128 n

    for (int k0 = 0; k0 < K; k0 += 8) {
        float4 av = *(const float4*)(A + (long long)(m0 + ra) * K + k0 + ka);
        float4 bv = *(const float4*)(B + (long long)(k0 + kb) * N + n0 + cb);
        if (mxp) {
            float mm = mxp[k0 + kb], rr = rsp[k0 + kb];
            bv.x = __expf(bv.x - mm) * rr;
            bv.y = __expf(bv.y - mm) * rr;
            bv.z = __expf(bv.z - mm) * rr;
            bv.w = __expf(bv.w - mm) * rr;
        }
        __syncthreads();
        As[ka + 0][ra] = av.x; As[ka + 1][ra] = av.y;
        As[ka + 2][ra] = av.z; As[ka + 3][ra] = av.w;
        *(float4*)&Bs[kb][cb] = bv;
        __syncthreads();
#pragma unroll
        for (int kk = 0; kk < 8; kk++) {
            float a[8], bb2[8];
            *(float4*)a        = *(const float4*)&As[kk][ty * 8];
            *(float4*)(a + 4)  = *(const float4*)&As[kk][ty * 8 + 4];
            *(float4*)bb2      = *(const float4*)&Bs[kk][tx * 8];
            *(float4*)(bb2+4)  = *(const float4*)&Bs[kk][tx * 8 + 4];
#pragma unroll
            for (int i = 0; i < 8; i++)
#pragma unroll
                for (int j = 0; j < 8; j++)
                    acc[i][j] = fmaf(a[i], bb2[j], acc[i][j]);
        }
    }
#pragma unroll
    for (int i = 0; i < 8; i++) {
        float bi = bias ? bias[m0 + ty * 8 + i] : 0.f;
        float* crow = Cp + (long long)(m0 + ty * 8 + i) * N + n0 + tx * 8;
        float4 o0 = make_float4(acc[i][0] + bi, acc[i][1] + bi, acc[i][2] + bi, acc[i][3] + bi);
        float4 o1 = make_float4(acc[i][4] + bi, acc[i][5] + bi, acc[i][6] + bi, acc[i][7] + bi);
        *(float4*)crow = o0;
        *(float4*)(crow + 4) = o1;
    }
}

// ---------------- 128x128x8 SGEMM, TN: C[b][n][m] = sum_c A[b][c][n] * B[b][c][m] ----------------
__global__ void __launch_bounds__(256) gemm_tn(
    const float* __restrict__ A, const float* __restrict__ B,
    float* __restrict__ Cp, int N, int K, int lda,
    long long bsA, long long bsB, long long bsC)
{
    int b = blockIdx.z;
    A += (long long)b * bsA;
    B += (long long)b * bsB;
    Cp += (long long)b * bsC;
    int m0 = blockIdx.y * 128, n0 = blockIdx.x * 128;

    __shared__ float As[8][128];
    __shared__ float Bs[8][128];
    float acc[8][8];
#pragma unroll
    for (int i = 0; i < 8; i++)
#pragma unroll
        for (int j = 0; j < 8; j++) acc[i][j] = 0.f;

    int tid = threadIdx.x;
    int tx = tid & 15, ty = tid >> 4;
    int kb = tid >> 5, cb = (tid & 31) * 4;

    for (int k0 = 0; k0 < K; k0 += 8) {
        float4 av = *(const float4*)(A + (long long)(k0 + kb) * lda + m0 + cb);
        float4 bv = *(const float4*)(B + (long long)(k0 + kb) * N + n0 + cb);
        __syncthreads();
        *(float4*)&As[kb][cb] = av;
        *(float4*)&Bs[kb][cb] = bv;
        __syncthreads();
#pragma unroll
        for (int kk = 0; kk < 8; kk++) {
            float a[8], bb2[8];
            *(float4*)a        = *(const float4*)&As[kk][ty * 8];
            *(float4*)(a + 4)  = *(const float4*)&As[kk][ty * 8 + 4];
            *(float4*)bb2      = *(const float4*)&Bs[kk][tx * 8];
            *(float4*)(bb2+4)  = *(const float4*)&Bs[kk][tx * 8 + 4];
#pragma unroll
            for (int i = 0; i < 8; i++)
#pragma unroll
                for (int j = 0; j < 8; j++)
                    acc[i][j] = fmaf(a[i], bb2[j], acc[i][j]);
        }
    }
#pragma unroll
    for (int i = 0; i < 8; i++) {
        float* crow = Cp + (long long)(m0 + ty * 8 + i) * N + n0 + tx * 8;
        float4 o0 = make_float4(acc[i][0], acc[i][1], acc[i][2], acc[i][3]);
        float4 o1 = make_float4(acc[i][4], acc[i][5], acc[i][6], acc[i][7]);
        *(float4*)crow = o0;
        *(float4*)(crow + 4) = o1;
    }
}

// ---------------- per-row softmax stats: max + 1/sum(exp) ----------------
__global__ void __launch_bounds__(256) rowstats(
    const float* __restrict__ S, float* __restrict__ mx, float* __restrict__ rs)
{
    long long row = (long long)blockIdx.y * 4096 + blockIdx.x;  // y in [0,8): (attn,b)
    const float4* p = (const float4*)(S + row * 4096);
    __shared__ float red[256];
    float m = -1e30f;
    for (int i = threadIdx.x; i < 1024; i += 256) {
        float4 v = p[i];
        m = fmaxf(fmaxf(m, v.x), fmaxf(v.y, fmaxf(v.z, v.w)));
    }
    red[threadIdx.x] = m; __syncthreads();
    for (int s = 128; s > 0; s >>= 1) {
        if (threadIdx.x < s) red[threadIdx.x] = fmaxf(red[threadIdx.x], red[threadIdx.x + s]);
        __syncthreads();
    }
    m = red[0];
    __syncthreads();
    float sum = 0.f;
    for (int i = threadIdx.x; i < 1024; i += 256) {
        float4 v = p[i];
        sum += __expf(v.x - m) + __expf(v.y - m) + __expf(v.z - m) + __expf(v.w - m);
    }
    red[threadIdx.x] = sum; __syncthreads();
    for (int s = 128; s > 0; s >>= 1) {
        if (threadIdx.x < s) red[threadIdx.x] += red[threadIdx.x + s];
        __syncthreads();
    }
    if (threadIdx.x == 0) { mx[row] = m; rs[row] = 1.f / red[0]; }
}

// ---------------- pack F_i, F_w into xcat rows [256:384) and [384:512) ----------------
__global__ void __launch_bounds__(256) packx(
    const float* __restrict__ Fi, const float* __restrict__ Fw, float* __restrict__ xcat)
{
    int idx = blockIdx.x * 256 + threadIdx.x;
    const int per = Bn * Cc * HW / 4;    // 524288 float4 per tensor
    if (idx >= 2 * per) return;
    int t = idx / per, r = idx % per;
    int b = r / (Cc * HW / 4);
    int rem = r % (Cc * HW / 4);
    int c = rem / (HW / 4);
    int m4 = rem % (HW / 4);
    const float4* src = (const float4*)(t ? Fw : Fi);
    float4* dst = (float4*)xcat;
    dst[(long long)b * (512 * HW / 4) + (long long)(256 + t * Cc + c) * (HW / 4) + m4] = src[r];
}

// ---------------- pack fused output weight [256,512] and bias ----------------
__global__ void __launch_bounds__(256) packw(
    const float* __restrict__ wproj, const float* __restrict__ bproj,
    const float* __restrict__ wres1, const float* __restrict__ bres1,
    const float* __restrict__ wres2, const float* __restrict__ bres2,
    float* __restrict__ wcat, float* __restrict__ bcat)
{
    int idx = blockIdx.x * 256 + threadIdx.x;   // 256*512 total
    if (idx >= OUTC * 512) return;
    int o = idx >> 9, k = idx & 511;
    float v;
    if (k < 256)      v = wproj[o * 256 + k];
    else if (k < 384) v = wres1[o * 128 + k - 256];
    else              v = wres2[o * 128 + k - 384];
    wcat[idx] = v;
    if (k == 0) bcat[o] = bproj[o] + bres1[o] + bres2[o];
}

// ---------------- launch ----------------
extern "C" void kernel_launch(void* const* d_in, const int* in_sizes, int n_in,
                              void* d_out, int out_size)
{
    const float* F_i   = (const float*)d_in[0];
    const float* F_w   = (const float*)d_in[1];
    const float* bn1_g = (const float*)d_in[2];
    const float* bn1_b = (const float*)d_in[3];
    const float* bn1_m = (const float*)d_in[4];
    const float* bn1_v = (const float*)d_in[5];
    const float* bn2_g = (const float*)d_in[6];
    const float* bn2_b = (const float*)d_in[7];
    const float* bn2_m = (const float*)d_in[8];
    const float* bn2_v = (const float*)d_in[9];
    const float* wq1 = (const float*)d_in[10];  const float* bq1 = (const float*)d_in[11];
    const float* wk1 = (const float*)d_in[12];  const float* bk1 = (const float*)d_in[13];
    const float* wv1 = (const float*)d_in[14];  const float* bv1 = (const float*)d_in[15];
    const float* wq2 = (const float*)d_in[16];  const float* bq2 = (const float*)d_in[17];
    const float* wk2 = (const float*)d_in[18];  const float* bk2 = (const float*)d_in[19];
    const float* wv2 = (const float*)d_in[20];  const float* bv2 = (const float*)d_in[21];
    const float* wdw1 = (const float*)d_in[22]; const float* bdw1 = (const float*)d_in[23];
    const float* wdw2 = (const float*)d_in[24]; const float* bdw2 = (const float*)d_in[25];
    const float* wproj = (const float*)d_in[26]; const float* bproj = (const float*)d_in[27];
    const float* wres1 = (const float*)d_in[28]; const float* bres1 = (const float*)d_in[29];
    const float* wres2 = (const float*)d_in[30]; const float* bres2 = (const float*)d_in[31];

    float *dw, *qkv, *S, *mx, *rs, *xcat, *wcat, *bcat;
    cudaGetSymbolAddress((void**)&dw,   g_dw);
    cudaGetSymbolAddress((void**)&qkv,  g_qkv);
    cudaGetSymbolAddress((void**)&S,    g_S);
    cudaGetSymbolAddress((void**)&mx,   g_mx);
    cudaGetSymbolAddress((void**)&rs,   g_rs);
    cudaGetSymbolAddress((void**)&xcat, g_xcat);
    cudaGetSymbolAddress((void**)&wcat, g_wcat);
    cudaGetSymbolAddress((void**)&bcat, g_bcat);

    const long long szT = (long long)Bn * Cc * HW;      // 2,097,152 floats (one [B,C,HW] tensor)
    const long long szS = (long long)Bn * HW * HW;      // one attention's S, all batches

    // 1. pack fused output weights
    packw<<<512, 256>>>(wproj, bproj, wres1, bres1, wres2, bres2, wcat, bcat);

    // 2. BN + depthwise
    bn_dw_kernel<<<Bn * Cc, 256>>>(F_i, bn1_g, bn1_b, bn1_m, bn1_v, wdw1, bdw1, dw);
    bn_dw_kernel<<<Bn * Cc, 256>>>(F_w, bn2_g, bn2_b, bn2_m, bn2_v, wdw2, bdw2, dw + szT);

    // 3. pack raw F_i/F_w into xcat residual slots
    packx<<<4096, 256>>>(F_i, F_w, xcat);

    // 4. QKV 1x1 convs (GEMM M=128,N=4096,K=128). buffers: 0=Qi 1=Ki 2=Vi 3=Qw 4=Kw 5=Vw
    dim3 gq(32, 1, Bn);
    long long bsT = (long long)Cc * HW;
    gemm_nn<<<gq, 256>>>(wq1, dw,        qkv + 0 * szT, bq1, nullptr, nullptr, HW, Cc, 0, bsT, bsT);
    gemm_nn<<<gq, 256>>>(wk1, dw,        qkv + 1 * szT, bk1, nullptr, nullptr, HW, Cc, 0, bsT, bsT);
    gemm_nn<<<gq, 256>>>(wv1, dw,        qkv + 2 * szT, bv1, nullptr, nullptr, HW, Cc, 0, bsT, bsT);
    gemm_nn<<<gq, 256>>>(wq2, dw + szT,  qkv + 3 * szT, bq2, nullptr, nullptr, HW, Cc, 0, bsT, bsT);
    gemm_nn<<<gq, 256>>>(wk2, dw + szT,  qkv + 4 * szT, bk2, nullptr, nullptr, HW, Cc, 0, bsT, bsT);
    gemm_nn<<<gq, 256>>>(wv2, dw + szT,  qkv + 5 * szT, bv2, nullptr, nullptr, HW, Cc, 0, bsT, bsT);

    // 5. S1 = Qi^T Kw ; S2 = Qw^T Ki   (TN GEMM, M=N=4096, K=128)
    dim3 gs(32, 32, Bn);
    gemm_tn<<<gs, 256>>>(qkv + 0 * szT, qkv + 4 * szT, S,       HW, Cc, HW, bsT, bsT, (long long)HW * HW);
    gemm_tn<<<gs, 256>>>(qkv + 3 * szT, qkv + 1 * szT, S + szS, HW, Cc, HW, bsT, bsT, (long long)HW * HW);

    // 6. softmax row stats for both attentions
    dim3 gst(4096, 8);
    rowstats<<<gst, 256>>>(S, mx, rs);

    // 7. A_i = Vw @ softmax(S1) -> xcat[:,0:128] ; A_w = Vi @ softmax(S2) -> xcat[:,128:256]
    dim3 gav(32, 1, Bn);
    gemm_nn<<<gav, 256>>>(qkv + 5 * szT, S,       xcat,            nullptr, mx,            rs,
                          HW, HW, bsT, (long long)HW * HW, 512LL * HW);
    gemm_nn<<<gav, 256>>>(qkv + 2 * szT, S + szS, xcat + 128 * HW, nullptr, mx + Bn * HW, rs + Bn * HW,
                          HW, HW, bsT, (long long)HW * HW, 512LL * HW);

    // 8. out = Wcat @ xcat + bcat   (M=256, N=4096, K=512)
    dim3 gf(32, 2, Bn);
    gemm_nn<<<gf, 256>>>(wcat, xcat, (float*)d_out, bcat, nullptr, nullptr,
                         HW, 512, 0, 512LL * HW, (long long)OUTC * HW);
}

// round 5
// speedup vs baseline: 2.7048x; 2.7048x over previous
#include <cuda_runtime.h>
#include <cstdint>
#include <math.h>

#define HW 4096
#define Cc 128
#define Bn 4
#define OUTC 256
#define EPSf 1e-5f
#define SMEMSZ 81920

// ---------------- scratch ----------------
__device__ float g_dw [2*Bn*Cc*HW];
__device__ unsigned short g_dwTh[2*Bn*Cc*HW];
__device__ unsigned short g_dwTl[2*Bn*Cc*HW];
__device__ unsigned short g_qth[4*Bn*Cc*HW];   // Qi,Kw,Qw,Ki  [B][HW][128]
__device__ unsigned short g_qtl[4*Bn*Cc*HW];
__device__ float g_v  [2*Bn*Cc*HW];
__device__ unsigned short g_vh[2*Bn*Cc*HW];
__device__ unsigned short g_vl[2*Bn*Cc*HW];
__device__ unsigned short g_Eh[134217728];     // Et[key][query] bf16 hi
__device__ unsigned short g_El[134217728];
__device__ float g_part[2*64*Bn*HW];
__device__ float g_sum [2*Bn*HW];
__device__ float g_xT  [Bn*HW*512];            // [pix][A_i|A_w|F_i|F_w]
__device__ unsigned short g_wch[OUTC*512], g_wcl[OUTC*512];
__device__ float g_bcat[OUTC];

__device__ __forceinline__ uint32_t smem_u32(const void* p) {
    uint32_t a;
    asm("{ .reg .u64 t; cvta.to.shared.u64 t, %1; cvt.u32.u64 %0, t; }" : "=r"(a) : "l"(p));
    return a;
}
// bf16 RNE, bits in high half
__device__ __forceinline__ uint32_t bfh(float x) {
    uint32_t u = __float_as_uint(x);
    return (u + 0x7FFFu + ((u >> 16) & 1)) & 0xFFFF0000u;
}
__device__ __forceinline__ void ldmx4(uint32_t* r, uint32_t a) {
    asm volatile("ldmatrix.sync.aligned.m8n8.x4.shared.b16 {%0,%1,%2,%3}, [%4];"
        : "=r"(r[0]), "=r"(r[1]), "=r"(r[2]), "=r"(r[3]) : "r"(a));
}
__device__ __forceinline__ void mma16816(float* d, const uint32_t* a, const uint32_t* b) {
    asm volatile("mma.sync.aligned.m16n8k16.row.col.f32.bf16.bf16.f32 "
        "{%0,%1,%2,%3}, {%4,%5,%6,%7}, {%8,%9}, {%0,%1,%2,%3};"
        : "+f"(d[0]), "+f"(d[1]), "+f"(d[2]), "+f"(d[3])
        : "r"(a[0]), "r"(a[1]), "r"(a[2]), "r"(a[3]), "r"(b[0]), "r"(b[1]));
}
__device__ __forceinline__ void st_split(char* p, float4 v) {
    uint32_t h0 = bfh(v.x), h1 = bfh(v.y), h2 = bfh(v.z), h3 = bfh(v.w);
    *(uint2*)p = make_uint2((h0 >> 16) | h1, (h2 >> 16) | h3);
    uint32_t g0 = bfh(v.x - __int_as_float(h0)), g1 = bfh(v.y - __int_as_float(h1));
    uint32_t g2 = bfh(v.z - __int_as_float(h2)), g3 = bfh(v.w - __int_as_float(h3));
    *(uint2*)(p + 10240) = make_uint2((g0 >> 16) | g1, (g2 >> 16) | g3);
}

// ===== warp-MMA split-bf16 GEMM: D[m][n] = sum_k A[m][k]*B[n][k] =====
// FLG: 1=bias per M, 2=exp+colsum, 4=split-bf16 trans store, 8=fp32 trans store
template <int APK, int BPK, int FLG>
__global__ void __launch_bounds__(256, 1) mma_k(
    const void* __restrict__ Ap, const void* __restrict__ Alp,
    const void* __restrict__ Bp, const void* __restrict__ Blp,
    float* __restrict__ C, unsigned short* __restrict__ Ch, unsigned short* __restrict__ Cl,
    const float* __restrict__ bias, float* __restrict__ part,
    int lda, int ldb, int ldc, int K,
    long long bsA, long long bsB, long long bsC)
{
    extern __shared__ char sm[];
    float* smf = (float*)sm;
    uint32_t su = smem_u32(sm);
    int tid = threadIdx.x, lane = tid & 31, w = tid >> 5;
    int wm = w & 3, wn = w >> 2;
    int m0 = blockIdx.y * 128, n0 = blockIdx.x * 128;
    long long z = blockIdx.z;

    const float* Af = (const float*)Ap + z * bsA;
    const unsigned short* Auh = (const unsigned short*)Ap + z * bsA;
    const unsigned short* Aul = (const unsigned short*)Alp + z * bsA;
    const float* Bf = (const float*)Bp + z * bsB;
    const unsigned short* Buh = (const unsigned short*)Bp + z * bsB;
    const unsigned short* Bul = (const unsigned short*)Blp + z * bsB;
    if (C) C += z * bsC;
    if (Ch) { Ch += z * bsC; Cl += z * bsC; }

    float acc[2][8][4];
#pragma unroll
    for (int a = 0; a < 2; a++)
#pragma unroll
        for (int b = 0; b < 8; b++)
#pragma unroll
            for (int c = 0; c < 4; c++) acc[a][b][c] = 0.f;

    float4 fa[4], fb[4];
    uint4 ua[4], ub[4];
    int nch = K >> 5;

    auto ldg = [&](int ch) {
        int k0 = ch << 5;
        if (APK == 0) {
#pragma unroll
            for (int i = 0; i < 4; i++) { int id = tid + (i << 8), r = id >> 3, c4 = (id & 7) << 2;
                fa[i] = *(const float4*)(Af + (long long)(m0 + r) * lda + k0 + c4); }
        } else {
#pragma unroll
            for (int i = 0; i < 2; i++) { int id = tid + (i << 8), r = id >> 2, c8 = (id & 3) << 3;
                ua[i]     = *(const uint4*)(Auh + (long long)(m0 + r) * lda + k0 + c8);
                ua[i + 2] = *(const uint4*)(Aul + (long long)(m0 + r) * lda + k0 + c8); }
        }
        if (BPK == 0) {
#pragma unroll
            for (int i = 0; i < 4; i++) { int id = tid + (i << 8), r = id >> 3, c4 = (id & 7) << 2;
                fb[i] = *(const float4*)(Bf + (long long)(n0 + r) * ldb + k0 + c4); }
        } else {
#pragma unroll
            for (int i = 0; i < 2; i++) { int id = tid + (i << 8), r = id >> 2, c8 = (id & 3) << 3;
                ub[i]     = *(const uint4*)(Buh + (long long)(n0 + r) * ldb + k0 + c8);
                ub[i + 2] = *(const uint4*)(Bul + (long long)(n0 + r) * ldb + k0 + c8); }
        }
    };
    auto sts = [&](int ch) {
        char* stg = sm + (ch & 1) * 40960;
        if (APK == 0) {
#pragma unroll
            for (int i = 0; i < 4; i++) { int id = tid + (i << 8), r = id >> 3, c4 = (id & 7) << 2;
                st_split(stg + r * 80 + c4 * 2, fa[i]); }
        } else {
#pragma unroll
            for (int i = 0; i < 2; i++) { int id = tid + (i << 8), r = id >> 2, c8 = (id & 3) << 3;
                *(uint4*)(stg + r * 80 + c8 * 2) = ua[i];
                *(uint4*)(stg + 10240 + r * 80 + c8 * 2) = ua[i + 2]; }
        }
        if (BPK == 0) {
#pragma unroll
            for (int i = 0; i < 4; i++) { int id = tid + (i << 8), r = id >> 3, c4 = (id & 7) << 2;
                st_split(stg + 20480 + r * 80 + c4 * 2, fb[i]); }
        } else {
#pragma unroll
            for (int i = 0; i < 2; i++) { int id = tid + (i << 8), r = id >> 2, c8 = (id & 3) << 3;
                *(uint4*)(stg + 20480 + r * 80 + c8 * 2) = ub[i];
                *(uint4*)(stg + 30720 + r * 80 + c8 * 2) = ub[i + 2]; }
        }
    };
    auto consume = [&](int ch) {
        uint32_t sst = su + (ch & 1) * 40960;
#pragma unroll
        for (int kk = 0; kk < 32; kk += 16) {
            uint32_t ah[2][4], al[2][4], bh[4][4], bl[4][4];
            int rA = (lane & 7) + ((lane >> 3) & 1) * 8;
            int kA = kk + (lane >> 4) * 8;
#pragma unroll
            for (int mt = 0; mt < 2; mt++) {
                uint32_t ad = sst + (wm * 32 + mt * 16 + rA) * 80 + kA * 2;
                ldmx4(ah[mt], ad);
                ldmx4(al[mt], ad + 10240);
            }
            int rB = (lane & 7) + (lane >> 4) * 8;
            int kB = kk + ((lane >> 3) & 1) * 8;
#pragma unroll
            for (int nt2 = 0; nt2 < 4; nt2++) {
                uint32_t bd = sst + 20480 + (wn * 64 + nt2 * 16 + rB) * 80 + kB * 2;
                ldmx4(bh[nt2], bd);
                ldmx4(bl[nt2], bd + 10240);
            }
#pragma unroll
            for (int mt = 0; mt < 2; mt++)
#pragma unroll
                for (int nt = 0; nt < 8; nt++) {
                    const uint32_t* ph = &bh[nt >> 1][(nt & 1) * 2];
                    const uint32_t* pl = &bl[nt >> 1][(nt & 1) * 2];
                    mma16816(acc[mt][nt], ah[mt], ph);
                    mma16816(acc[mt][nt], ah[mt], pl);
                    mma16816(acc[mt][nt], al[mt], ph);
                }
        }
    };

    ldg(0); sts(0);
    __syncthreads();
    for (int ch = 0; ch < nch; ch++) {
        if (ch + 1 < nch) ldg(ch + 1);
        consume(ch);
        if (ch + 1 < nch) sts(ch + 1);
        __syncthreads();
    }

    // acc -> smem fp32 tile (stride 130)
#pragma unroll
    for (int mt = 0; mt < 2; mt++)
#pragma unroll
        for (int nt = 0; nt < 8; nt++) {
            int r = wm * 32 + mt * 16 + (lane >> 2);
            int c = wn * 64 + nt * 8 + 2 * (lane & 3);
            *(float2*)&smf[r * 130 + c]       = make_float2(acc[mt][nt][0], acc[mt][nt][1]);
            *(float2*)&smf[(r + 8) * 130 + c] = make_float2(acc[mt][nt][2], acc[mt][nt][3]);
        }
    __syncthreads();

    if (FLG & (2 | 4 | 8)) {
        int r = tid & 127, hf = tid >> 7;
        float bm = (FLG & 1) ? bias[m0 + r] : 0.f;
        float lsum = 0.f;
        long long colo = m0 + r;
        int j0 = hf * 64;
#pragma unroll 4
        for (int j = j0; j < j0 + 64; j++) {
            float v = smf[r * 130 + j] + bm;
            long long idx = (long long)(n0 + j) * ldc + colo;
            if (FLG & 2) { v = __expf(fminf(v, 60.f)); lsum += v; }
            if (FLG & 4) {
                uint32_t hb = bfh(v);
                Ch[idx] = (unsigned short)(hb >> 16);
                Cl[idx] = (unsigned short)(bfh(v - __int_as_float(hb)) >> 16);
            } else {
                C[idx] = v;
            }
        }
        if (FLG & 2)
            part[(long long)(blockIdx.x * 2 + hf) * (Bn * HW) + z * HW + m0 + r] = lsum;
    } else {
#pragma unroll 4
        for (int i = tid; i < 16384; i += 256) {
            int r = i >> 7, c = i & 127;
            float v = smf[r * 130 + c] + ((FLG & 1) ? bias[m0 + r] : 0.f);
            C[(long long)(m0 + r) * ldc + n0 + c] = v;
        }
    }
}

// ---- BN(eval) + depthwise 3x3 SAME ----
__global__ void __launch_bounds__(256) bn_dw_kernel(
    const float* __restrict__ x, const float* __restrict__ g, const float* __restrict__ b,
    const float* __restrict__ m, const float* __restrict__ v,
    const float* __restrict__ wdw, const float* __restrict__ bdw, float* __restrict__ y)
{
    __shared__ float tile[66 * 66];
    int bc = blockIdx.x, c = bc & 127;
    const float* xp = x + (size_t)bc * HW;
    float sc = g[c] * rsqrtf(v[c] + EPSf), sh = b[c] - m[c] * sc;
    for (int i = threadIdx.x; i < 66 * 66; i += 256) {
        int r = i / 66 - 1, cl = i % 66 - 1;
        tile[i] = (r >= 0 && r < 64 && cl >= 0 && cl < 64) ? xp[r * 64 + cl] * sc + sh : 0.f;
    }
    __syncthreads();
    float w0 = wdw[c*9], w1 = wdw[c*9+1], w2 = wdw[c*9+2], w3 = wdw[c*9+3], w4 = wdw[c*9+4];
    float w5 = wdw[c*9+5], w6 = wdw[c*9+6], w7 = wdw[c*9+7], w8 = wdw[c*9+8], bb = bdw[c];
    float* yp = y + (size_t)bc * HW;
    for (int i = threadIdx.x; i < HW; i += 256) {
        const float* t = &tile[(i >> 6) * 66 + (i & 63)];
        yp[i] = bb + t[0]*w0 + t[1]*w1 + t[2]*w2 + t[66]*w3 + t[67]*w4 + t[68]*w5
                   + t[132]*w6 + t[133]*w7 + t[134]*w8;
    }
}

// ---- transpose [128][HW] -> split bf16 [HW][128] ----
__global__ void __launch_bounds__(256) tsplit_k(
    const float* __restrict__ src, unsigned short* __restrict__ dh,
    unsigned short* __restrict__ dl, long long bs)
{
    __shared__ float t[32][33];
    src += blockIdx.z * bs; dh += blockIdx.z * bs; dl += blockIdx.z * bs;
    int p0 = blockIdx.x * 32, c0 = blockIdx.y * 32;
    int x = threadIdx.x & 31, y = threadIdx.x >> 5;
#pragma unroll
    for (int i = 0; i < 32; i += 8) t[y + i][x] = src[(long long)(c0 + y + i) * HW + p0 + x];
    __syncthreads();
#pragma unroll
    for (int i = 0; i < 32; i += 8) {
        float v = t[x][y + i];
        long long o = (long long)(p0 + y + i) * 128 + c0 + x;
        uint32_t hb = bfh(v);
        dh[o] = (unsigned short)(hb >> 16);
        dl[o] = (unsigned short)(bfh(v - __int_as_float(hb)) >> 16);
    }
}

// ---- transpose fp32 [128][HW] -> [HW][512] slice (residuals) ----
__global__ void __launch_bounds__(256) transpose_k(
    const float* __restrict__ src, float* __restrict__ dst, long long bsS, long long bsD)
{
    __shared__ float t[32][33];
    src += blockIdx.z * bsS; dst += blockIdx.z * bsD;
    int p0 = blockIdx.x * 32, c0 = blockIdx.y * 32;
    int x = threadIdx.x & 31, y = threadIdx.x >> 5;
#pragma unroll
    for (int i = 0; i < 32; i += 8) t[y + i][x] = src[(long long)(c0 + y + i) * HW + p0 + x];
    __syncthreads();
#pragma unroll
    for (int i = 0; i < 32; i += 8)
        dst[(long long)(p0 + y + i) * 512 + c0 + x] = t[x][y + i];
}

// ---- reduce 64 partial colsums -> reciprocal ----
__global__ void __launch_bounds__(256) rcpsum(const float* __restrict__ part, float* __restrict__ sums)
{
    int i = blockIdx.x * 256 + threadIdx.x;          // 32768
    int a = i >> 14, r = i & 16383;
    const float* p = part + (long long)a * 64 * 16384 + r;
    float s = 0.f;
#pragma unroll
    for (int k = 0; k < 64; k++) s += p[(long long)k * 16384];
    sums[i] = 1.f / s;
}

// ---- fold rs into V, split to bf16 ----
__global__ void __launch_bounds__(256) vscale(
    const float4* __restrict__ v, const float4* __restrict__ rs4,
    unsigned short* __restrict__ vh, unsigned short* __restrict__ vl)
{
    int i = blockIdx.x * 256 + threadIdx.x;          // 1,048,576 float4
    int n4 = i & 1023, tensor = i >> 19, batch = (i >> 17) & 3;
    float4 a = v[i];
    float4 r = rs4[((((tensor ^ 1) << 2) | batch) << 10) + n4];
    a.x *= r.x; a.y *= r.y; a.z *= r.z; a.w *= r.w;
    uint32_t h0 = bfh(a.x), h1 = bfh(a.y), h2 = bfh(a.z), h3 = bfh(a.w);
    ((uint2*)vh)[i] = make_uint2((h0 >> 16) | h1, (h2 >> 16) | h3);
    uint32_t g0 = bfh(a.x - __int_as_float(h0)), g1 = bfh(a.y - __int_as_float(h1));
    uint32_t g2 = bfh(a.z - __int_as_float(h2)), g3 = bfh(a.w - __int_as_float(h3));
    ((uint2*)vl)[i] = make_uint2((g0 >> 16) | g1, (g2 >> 16) | g3);
}

// ---- pack fused output weight (split bf16) + bias ----
__global__ void __launch_bounds__(256) packw(
    const float* __restrict__ wp, const float* __restrict__ bp,
    const float* __restrict__ w1, const float* __restrict__ b1,
    const float* __restrict__ w2, const float* __restrict__ b2,
    unsigned short* __restrict__ wh, unsigned short* __restrict__ wl, float* __restrict__ bc)
{
    int i = blockIdx.x * 256 + threadIdx.x;
    if (i >= OUTC * 512) return;
    int o = i >> 9, k = i & 511;
    float v = (k < 256) ? wp[o * 256 + k] : (k < 384) ? w1[o * 128 + k - 256] : w2[o * 128 + k - 384];
    uint32_t hb = bfh(v);
    wh[i] = (unsigned short)(hb >> 16);
    wl[i] = (unsigned short)(bfh(v - __int_as_float(hb)) >> 16);
    if (k == 0) bc[o] = bp[o] + b1[o] + b2[o];
}

extern "C" void kernel_launch(void* const* d_in, const int* in_sizes, int n_in,
                              void* d_out, int out_size)
{
    const float *F_i = (const float*)d_in[0], *F_w = (const float*)d_in[1];
    const float *bn1g = (const float*)d_in[2], *bn1b = (const float*)d_in[3];
    const float *bn1m = (const float*)d_in[4], *bn1v = (const float*)d_in[5];
    const float *bn2g = (const float*)d_in[6], *bn2b = (const float*)d_in[7];
    const float *bn2m = (const float*)d_in[8], *bn2v = (const float*)d_in[9];
    const float *wq1 = (const float*)d_in[10], *bq1 = (const float*)d_in[11];
    const float *wk1 = (const float*)d_in[12], *bk1 = (const float*)d_in[13];
    const float *wv1 = (const float*)d_in[14], *bv1 = (const float*)d_in[15];
    const float *wq2 = (const float*)d_in[16], *bq2 = (const float*)d_in[17];
    const float *wk2 = (const float*)d_in[18], *bk2 = (const float*)d_in[19];
    const float *wv2 = (const float*)d_in[20], *bv2 = (const float*)d_in[21];
    const float *wd1 = (const float*)d_in[22], *bd1 = (const float*)d_in[23];
    const float *wd2 = (const float*)d_in[24], *bd2 = (const float*)d_in[25];
    const float *wpj = (const float*)d_in[26], *bpj = (const float*)d_in[27];
    const float *wr1 = (const float*)d_in[28], *br1 = (const float*)d_in[29];
    const float *wr2 = (const float*)d_in[30], *br2 = (const float*)d_in[31];

    float *dw, *v, *part, *sum, *xT, *bc;
    unsigned short *dwTh, *dwTl, *qth, *qtl, *vh, *vl, *Eh, *El, *wch, *wcl;
    cudaGetSymbolAddress((void**)&dw, g_dw);
    cudaGetSymbolAddress((void**)&dwTh, g_dwTh); cudaGetSymbolAddress((void**)&dwTl, g_dwTl);
    cudaGetSymbolAddress((void**)&qth, g_qth);   cudaGetSymbolAddress((void**)&qtl, g_qtl);
    cudaGetSymbolAddress((void**)&v, g_v);
    cudaGetSymbolAddress((void**)&vh, g_vh);     cudaGetSymbolAddress((void**)&vl, g_vl);
    cudaGetSymbolAddress((void**)&Eh, g_Eh);     cudaGetSymbolAddress((void**)&El, g_El);
    cudaGetSymbolAddress((void**)&part, g_part); cudaGetSymbolAddress((void**)&sum, g_sum);
    cudaGetSymbolAddress((void**)&xT, g_xT);
    cudaGetSymbolAddress((void**)&wch, g_wch);   cudaGetSymbolAddress((void**)&wcl, g_wcl);
    cudaGetSymbolAddress((void**)&bc, g_bcat);

    cudaFuncSetAttribute(mma_k<0,1,5>, cudaFuncAttributeMaxDynamicSharedMemorySize, SMEMSZ);
    cudaFuncSetAttribute(mma_k<0,1,1>, cudaFuncAttributeMaxDynamicSharedMemorySize, SMEMSZ);
    cudaFuncSetAttribute(mma_k<1,1,6>, cudaFuncAttributeMaxDynamicSharedMemorySize, SMEMSZ);
    cudaFuncSetAttribute(mma_k<1,1,8>, cudaFuncAttributeMaxDynamicSharedMemorySize, SMEMSZ);
    cudaFuncSetAttribute(mma_k<1,0,1>, cudaFuncAttributeMaxDynamicSharedMemorySize, SMEMSZ);

    const long long TT = (long long)HW * Cc;      // 524288
    const long long BR = (long long)Bn * TT;      // 2097152
    const long long SS = (long long)HW * HW;
    const long long ES = (long long)Bn * SS;

    packw<<<512, 256>>>(wpj, bpj, wr1, br1, wr2, br2, wch, wcl, bc);
    bn_dw_kernel<<<512, 256>>>(F_i, bn1g, bn1b, bn1m, bn1v, wd1, bd1, dw);
    bn_dw_kernel<<<512, 256>>>(F_w, bn2g, bn2b, bn2m, bn2v, wd2, bd2, dw + BR);
    tsplit_k<<<dim3(128, 4, 8), 256>>>(dw, dwTh, dwTl, TT);
    transpose_k<<<dim3(128, 4, 4), 256>>>(F_i, xT + 256, TT, (long long)HW * 512);
    transpose_k<<<dim3(128, 4, 4), 256>>>(F_w, xT + 384, TT, (long long)HW * 512);

    // QKV: M=128, N=4096, K=128
    dim3 gq(32, 1, Bn);
    mma_k<0,1,5><<<gq, 256, SMEMSZ>>>(wq1, 0, dwTh,      dwTl,      0, qth,        qtl,        bq1, 0, 128, 128, 128, 128, 0, TT, TT);
    mma_k<0,1,5><<<gq, 256, SMEMSZ>>>(wk2, 0, dwTh + BR, dwTl + BR, 0, qth + BR,   qtl + BR,   bk2, 0, 128, 128, 128, 128, 0, TT, TT);
    mma_k<0,1,5><<<gq, 256, SMEMSZ>>>(wq2, 0, dwTh + BR, dwTl + BR, 0, qth + 2*BR, qtl + 2*BR, bq2, 0, 128, 128, 128, 128, 0, TT, TT);
    mma_k<0,1,5><<<gq, 256, SMEMSZ>>>(wk1, 0, dwTh,      dwTl,      0, qth + 3*BR, qtl + 3*BR, bk1, 0, 128, 128, 128, 128, 0, TT, TT);
    mma_k<0,1,1><<<gq, 256, SMEMSZ>>>(wv1, 0, dwTh,      dwTl,      v,      0, 0, bv1, 0, 128, 128, HW, 128, 0, TT, TT);
    mma_k<0,1,1><<<gq, 256, SMEMSZ>>>(wv2, 0, dwTh + BR, dwTl + BR, v + BR, 0, 0, bv2, 0, 128, 128, HW, 128, 0, TT, TT);

    // S: exp + colsum partials + split-bf16 transposed store Et[key][query]
    dim3 gs(32, 32, Bn);
    mma_k<1,1,6><<<gs, 256, SMEMSZ>>>(qth,        qtl,        qth + BR,   qtl + BR,   0, Eh,      El,      0, part,                  128, 128, HW, 128, TT, TT, SS);
    mma_k<1,1,6><<<gs, 256, SMEMSZ>>>(qth + 2*BR, qtl + 2*BR, qth + 3*BR, qtl + 3*BR, 0, Eh + ES, El + ES, 0, part + 64LL*Bn*HW,     128, 128, HW, 128, TT, TT, SS);

    rcpsum<<<128, 256>>>(part, sum);
    vscale<<<4096, 256>>>((const float4*)v, (const float4*)sum, vh, vl);

    // AV: M=128(ch), N=4096(pix), K=4096 -> fp32 trans store into xT
    dim3 ga(32, 1, Bn);
    mma_k<1,1,8><<<ga, 256, SMEMSZ>>>(vh + BR, vl + BR, Eh,      El,      xT,       0, 0, 0, 0, HW, HW, 512, HW, TT, SS, (long long)HW * 512);
    mma_k<1,1,8><<<ga, 256, SMEMSZ>>>(vh,      vl,      Eh + ES, El + ES, xT + 128, 0, 0, 0, 0, HW, HW, 512, HW, TT, SS, (long long)HW * 512);

    // out = wcat @ xT^T + bcat : M=256, N=4096, K=512
    dim3 gf(32, 2, Bn);
    mma_k<1,0,1><<<gf, 256, SMEMSZ>>>(wch, wcl, xT, 0, (float*)d_out, 0, 0, bc, 0, 512, 512, HW, 512, 0, (long long)HW * 512, (long long)OUTC * HW);
}

// round 6
// speedup vs baseline: 3.1004x; 1.1462x over previous
#include <cuda_runtime.h>
#include <cstdint>
#include <math.h>

typedef unsigned short ush;
#define HW 4096
#define Cc 128
#define Bn 4
#define OUTC 256
#define EPSf 1e-5f
#define NSTG 4
#define STG 40960
#define SMEMSZ (NSTG*STG)

// ---------------- scratch ----------------
__device__ float g_dw [2*Bn*Cc*HW];
__device__ ush   g_dwTh[2*Bn*Cc*HW], g_dwTl[2*Bn*Cc*HW];
__device__ ush   g_wAh[2*384*128],   g_wAl[2*384*128];
__device__ float g_bqkv[2*384];
__device__ ush   g_qkvTh[2ll*Bn*HW*384], g_qkvTl[2ll*Bn*HW*384];  // [br][B][pix][Q|K|V]
__device__ float g_v [2*Bn*Cc*HW];
__device__ ush   g_vh[2*Bn*Cc*HW], g_vl[2*Bn*Cc*HW];
__device__ ush   g_Eh[134217728];                 // [attn][B][key][query] bf16
__device__ float g_part[64*8*HW];
__device__ float g_sum[8*HW];
__device__ ush   g_xTh[Bn*HW*512], g_xTl[Bn*HW*512];
__device__ ush   g_wch[OUTC*512], g_wcl[OUTC*512];
__device__ float g_bcat[OUTC];

__device__ __forceinline__ uint32_t smem_u32(const void* p) {
    uint32_t a;
    asm("{ .reg .u64 t; cvta.to.shared.u64 t, %1; cvt.u32.u64 %0, t; }" : "=r"(a) : "l"(p));
    return a;
}
__device__ __forceinline__ uint32_t bfh(float x) {
    uint32_t u = __float_as_uint(x);
    return (u + 0x7FFFu + ((u >> 16) & 1)) & 0xFFFF0000u;
}
__device__ __forceinline__ void ldmx4(uint32_t* r, uint32_t a) {
    asm volatile("ldmatrix.sync.aligned.m8n8.x4.shared.b16 {%0,%1,%2,%3}, [%4];"
        : "=r"(r[0]), "=r"(r[1]), "=r"(r[2]), "=r"(r[3]) : "r"(a));
}
__device__ __forceinline__ void mma16816(float* d, const uint32_t* a, const uint32_t* b) {
    asm volatile("mma.sync.aligned.m16n8k16.row.col.f32.bf16.bf16.f32 "
        "{%0,%1,%2,%3}, {%4,%5,%6,%7}, {%8,%9}, {%0,%1,%2,%3};"
        : "+f"(d[0]), "+f"(d[1]), "+f"(d[2]), "+f"(d[3])
        : "r"(a[0]), "r"(a[1]), "r"(a[2]), "r"(a[3]), "r"(b[0]), "r"(b[1]));
}
#define CP16(d, s) asm volatile("cp.async.cg.shared.global [%0], [%1], 16;" :: "r"(d), "l"(s))
#define CPCOMMIT() asm volatile("cp.async.commit_group;" ::: "memory")
#define CPWAIT2()  asm volatile("cp.async.wait_group 2;" ::: "memory")

// ===== cp.async pipelined split-bf16 warp-MMA GEMM: D[m][n] = sum_k A[m][k]*B[n][k] =====
// FLG: 2=exp+colsum+bf16hi trans store(E) | 16=QKV mixed | 32=row split store(AV) | 8=fp32 row store
template <int UAL, int FLG>
__global__ void __launch_bounds__(256, 1) mma_k(
    const ush* __restrict__ Ah, const ush* __restrict__ Al,
    const ush* __restrict__ Bh, const ush* __restrict__ Bl,
    float* __restrict__ Cf, ush* __restrict__ Ch, ush* __restrict__ Cl,
    const float* __restrict__ bias, float* __restrict__ part,
    int lda, int ldb, int ldc, int K,
    long long bsA, long long bsB, long long bsC,
    int zshA, int zxB, int zmC, int cshift,
    long long bsC2, int ldc2, int bstride)
{
    extern __shared__ char sm[];
    float* smf = (float*)sm;
    uint32_t su = smem_u32(sm);
    int tid = threadIdx.x, lane = tid & 31, w = tid >> 5;
    int wm = w & 3, wn = w >> 2;
    int m0 = blockIdx.y * 128, n0 = blockIdx.x * 128;
    long long z = blockIdx.z;

    const ush* pAh = Ah + (z >> zshA) * bsA;
    const ush* pAl = Al + (z >> zshA) * bsA;
    long long zB = z ^ zxB;
    const ush* pBh = Bh + zB * bsB;
    const ush* pBl = Bl + zB * bsB;
    long long zC = z & zmC;
    int colofs = (int)(z >> 2) * cshift;

    float acc[2][8][4];
#pragma unroll
    for (int a = 0; a < 2; a++)
#pragma unroll
        for (int b = 0; b < 8; b++)
#pragma unroll
            for (int c = 0; c < 4; c++) acc[a][b][c] = 0.f;

    int nch = K >> 5;

    auto cpstage = [&](int ch) {
        uint32_t dst = su + (ch & (NSTG - 1)) * STG;
        int k0 = ch << 5;
#pragma unroll
        for (int i = 0; i < 2; i++) {
            int idx = tid + (i << 8);
            int r = idx >> 2, c8 = (idx & 3) << 3;
            uint32_t doff = r * 80 + (c8 << 1);
            CP16(dst + doff,         pAh + (long long)(m0 + r) * lda + k0 + c8);
            if (UAL)
                CP16(dst + 10240 + doff, pAl + (long long)(m0 + r) * lda + k0 + c8);
            CP16(dst + 20480 + doff, pBh + (long long)(n0 + r) * ldb + k0 + c8);
            CP16(dst + 30720 + doff, pBl + (long long)(n0 + r) * ldb + k0 + c8);
        }
    };
    auto consume = [&](uint32_t sst) {
#pragma unroll
        for (int kk = 0; kk < 32; kk += 16) {
            uint32_t ah[2][4], al[2][4], bh[4][4], bl[4][4];
            int rA = (lane & 7) + ((lane >> 3) & 1) * 8;
            int kA = kk + (lane >> 4) * 8;
#pragma unroll
            for (int mt = 0; mt < 2; mt++) {
                uint32_t ad = sst + (wm * 32 + mt * 16 + rA) * 80 + kA * 2;
                ldmx4(ah[mt], ad);
                if (UAL) ldmx4(al[mt], ad + 10240);
            }
            int rB = (lane & 7) + (lane >> 4) * 8;
            int kB = kk + ((lane >> 3) & 1) * 8;
#pragma unroll
            for (int nt = 0; nt < 4; nt++) {
                uint32_t bd = sst + 20480 + (wn * 64 + nt * 16 + rB) * 80 + kB * 2;
                ldmx4(bh[nt], bd);
                ldmx4(bl[nt], bd + 10240);
            }
#pragma unroll
            for (int mt = 0; mt < 2; mt++)
#pragma unroll
                for (int nt = 0; nt < 8; nt++) {
                    const uint32_t* ph = &bh[nt >> 1][(nt & 1) * 2];
                    const uint32_t* pl = &bl[nt >> 1][(nt & 1) * 2];
                    mma16816(acc[mt][nt], ah[mt], ph);
                    mma16816(acc[mt][nt], ah[mt], pl);
                    if (UAL) mma16816(acc[mt][nt], al[mt], ph);
                }
        }
    };

    cpstage(0); CPCOMMIT();
    cpstage(1); CPCOMMIT();
    cpstage(2); CPCOMMIT();
    CPWAIT2();
    __syncthreads();
    for (int ch = 0; ch < nch; ch++) {
        consume(su + (ch & (NSTG - 1)) * STG);
        __syncthreads();
        if (ch + 3 < nch) cpstage(ch + 3);
        CPCOMMIT();
        if (ch + 1 < nch) { CPWAIT2(); __syncthreads(); }
    }

    // acc -> smem fp32 tile (stride 130)
    __syncthreads();
#pragma unroll
    for (int mt = 0; mt < 2; mt++)
#pragma unroll
        for (int nt = 0; nt < 8; nt++) {
            int r = wm * 32 + mt * 16 + (lane >> 2);
            int c = wn * 64 + nt * 8 + 2 * (lane & 3);
            *(float2*)&smf[r * 130 + c]       = make_float2(acc[mt][nt][0], acc[mt][nt][1]);
            *(float2*)&smf[(r + 8) * 130 + c] = make_float2(acc[mt][nt][2], acc[mt][nt][3]);
        }
    __syncthreads();

    if (FLG & 2) {               // S: exp + colsum + bf16-hi trans store
        int r = tid & 127, hf = tid >> 7;
        float lsum = 0.f;
        ush* co = Ch + zC * bsC;
        int j0 = hf * 64;
#pragma unroll 4
        for (int j = j0; j < j0 + 64; j++) {
            float e = __expf(fminf(smf[r * 130 + j], 60.f));
            lsum += e;
            co[(long long)(n0 + j) * ldc + m0 + r] = (ush)(bfh(e) >> 16);
        }
        part[((long long)blockIdx.x * 2 + hf) * (8 * HW) + z * HW + m0 + r] = lsum;
    } else if (FLG & 32) {       // AV: row split store
        ush* ch2 = Ch + zC * bsC;
        ush* cl2 = Cl + zC * bsC;
#pragma unroll 4
        for (int i = tid; i < 16384; i += 256) {
            int r = i >> 7, c = i & 127;
            float v = smf[r * 130 + c];
            long long o = (long long)(m0 + r) * ldc + colofs + n0 + c;
            uint32_t hb = bfh(v);
            ch2[o] = (ush)(hb >> 16);
            cl2[o] = (ush)(bfh(v - __int_as_float(hb)) >> 16);
        }
    } else if (FLG & 16) {       // QKV mixed
        if (blockIdx.y == 2) {   // V rows: fp32 row store
            float* cf = Cf + z * bsC2;
#pragma unroll 4
            for (int i = tid; i < 16384; i += 256) {
                int r = i >> 7, c = i & 127;
                cf[(long long)r * ldc2 + n0 + c] =
                    smf[r * 130 + c] + bias[(z >> zshA) * bstride + m0 + r];
            }
        } else {                 // Q/K: trans split store + bias
            int r = tid & 127, hf = tid >> 7;
            float bb = bias[(z >> zshA) * bstride + m0 + r];
            ush* ch2 = Ch + zC * bsC;
            ush* cl2 = Cl + zC * bsC;
            int j0 = hf * 64;
#pragma unroll 4
            for (int j = j0; j < j0 + 64; j++) {
                float v = smf[r * 130 + j] + bb;
                long long o = (long long)(n0 + j) * ldc + m0 + r;
                uint32_t hb = bfh(v);
                ch2[o] = (ush)(hb >> 16);
                cl2[o] = (ush)(bfh(v - __int_as_float(hb)) >> 16);
            }
        }
    } else {                     // fp32 row store + bias
        float* cf = Cf + zC * bsC;
#pragma unroll 4
        for (int i = tid; i < 16384; i += 256) {
            int r = i >> 7, c = i & 127;
            cf[(long long)(m0 + r) * ldc + n0 + c] =
                smf[r * 130 + c] + bias[(z >> zshA) * bstride + m0 + r];
        }
    }
}

// ---- BN(eval) + depthwise 3x3 SAME ----
__global__ void __launch_bounds__(256) bn_dw_kernel(
    const float* __restrict__ x, const float* __restrict__ g, const float* __restrict__ b,
    const float* __restrict__ m, const float* __restrict__ v,
    const float* __restrict__ wdw, const float* __restrict__ bdw, float* __restrict__ y)
{
    __shared__ float tile[66 * 66];
    int bc = blockIdx.x, c = bc & 127;
    const float* xp = x + (size_t)bc * HW;
    float sc = g[c] * rsqrtf(v[c] + EPSf), sh = b[c] - m[c] * sc;
    for (int i = threadIdx.x; i < 66 * 66; i += 256) {
        int r = i / 66 - 1, cl = i % 66 - 1;
        tile[i] = (r >= 0 && r < 64 && cl >= 0 && cl < 64) ? xp[r * 64 + cl] * sc + sh : 0.f;
    }
    __syncthreads();
    float w0 = wdw[c*9], w1 = wdw[c*9+1], w2 = wdw[c*9+2], w3 = wdw[c*9+3], w4 = wdw[c*9+4];
    float w5 = wdw[c*9+5], w6 = wdw[c*9+6], w7 = wdw[c*9+7], w8 = wdw[c*9+8], bb = bdw[c];
    float* yp = y + (size_t)bc * HW;
    for (int i = threadIdx.x; i < HW; i += 256) {
        const float* t = &tile[(i >> 6) * 66 + (i & 63)];
        yp[i] = bb + t[0]*w0 + t[1]*w1 + t[2]*w2 + t[66]*w3 + t[67]*w4 + t[68]*w5
                   + t[132]*w6 + t[133]*w7 + t[134]*w8;
    }
}

// ---- transpose [128][HW] -> split bf16 [HW][ldd] ----
__global__ void __launch_bounds__(256) tsplit_k(
    const float* __restrict__ src, ush* __restrict__ dh, ush* __restrict__ dl,
    int ldd, long long bsS, long long bsD)
{
    __shared__ float t[32][33];
    src += blockIdx.z * bsS; dh += blockIdx.z * bsD; dl += blockIdx.z * bsD;
    int p0 = blockIdx.x * 32, c0 = blockIdx.y * 32;
    int x = threadIdx.x & 31, y = threadIdx.x >> 5;
#pragma unroll
    for (int i = 0; i < 32; i += 8) t[y + i][x] = src[(long long)(c0 + y + i) * HW + p0 + x];
    __syncthreads();
#pragma unroll
    for (int i = 0; i < 32; i += 8) {
        float v = t[x][y + i];
        long long o = (long long)(p0 + y + i) * ldd + c0 + x;
        uint32_t hb = bfh(v);
        dh[o] = (ush)(hb >> 16);
        dl[o] = (ush)(bfh(v - __int_as_float(hb)) >> 16);
    }
}

// ---- pack stacked QKV weights [2][384][128] split + bias [2][384] ----
__global__ void __launch_bounds__(256) pack_wqkv(
    const float* wq1, const float* wk1, const float* wv1,
    const float* wq2, const float* wk2, const float* wv2,
    const float* bq1, const float* bk1, const float* bv1,
    const float* bq2, const float* bk2, const float* bv2,
    ush* wAh, ush* wAl, float* bqkv)
{
    int i = blockIdx.x * 256 + threadIdx.x;   // 98304
    if (i >= 2 * 384 * 128) return;
    int br = i / 49152, rem = i % 49152, r = rem >> 7, c = rem & 127;
    const float* w; const float* bs;
    if (br == 0) { w = r < 128 ? wq1 : r < 256 ? wk1 : wv1; bs = r < 128 ? bq1 : r < 256 ? bk1 : bv1; }
    else         { w = r < 128 ? wq2 : r < 256 ? wk2 : wv2; bs = r < 128 ? bq2 : r < 256 ? bk2 : bv2; }
    float v = w[(r & 127) * 128 + c];
    uint32_t hb = bfh(v);
    wAh[i] = (ush)(hb >> 16);
    wAl[i] = (ush)(bfh(v - __int_as_float(hb)) >> 16);
    if (c == 0) bqkv[br * 384 + r] = bs[r & 127];
}

// ---- reduce 64 partial colsums -> reciprocal ----
__global__ void __launch_bounds__(256) rcpsum(const float* __restrict__ part, float* __restrict__ sums)
{
    int i = blockIdx.x * 256 + threadIdx.x;    // 32768
    float s = 0.f;
#pragma unroll
    for (int k = 0; k < 64; k++) s += part[(long long)k * 32768 + i];
    sums[i] = 1.f / s;
}

// ---- fold rs into V, split to bf16 ----
__global__ void __launch_bounds__(256) vscale(
    const float4* __restrict__ v, const float4* __restrict__ rs4,
    ush* __restrict__ vh, ush* __restrict__ vl)
{
    int i = blockIdx.x * 256 + threadIdx.x;    // 1,048,576 float4
    int n4 = i & 1023, tb = i >> 17;
    float4 a = v[i], r = rs4[((tb ^ 4) << 10) + n4];
    a.x *= r.x; a.y *= r.y; a.z *= r.z; a.w *= r.w;
    uint32_t h0 = bfh(a.x), h1 = bfh(a.y), h2 = bfh(a.z), h3 = bfh(a.w);
    ((uint2*)vh)[i] = make_uint2((h0 >> 16) | h1, (h2 >> 16) | h3);
    uint32_t g0 = bfh(a.x - __int_as_float(h0)), g1 = bfh(a.y - __int_as_float(h1));
    uint32_t g2 = bfh(a.z - __int_as_float(h2)), g3 = bfh(a.w - __int_as_float(h3));
    ((uint2*)vl)[i] = make_uint2((g0 >> 16) | g1, (g2 >> 16) | g3);
}

// ---- pack fused output weight (split bf16) + bias ----
__global__ void __launch_bounds__(256) packw(
    const float* __restrict__ wp, const float* __restrict__ bp,
    const float* __restrict__ w1, const float* __restrict__ b1,
    const float* __restrict__ w2, const float* __restrict__ b2,
    ush* __restrict__ wh, ush* __restrict__ wl, float* __restrict__ bc)
{
    int i = blockIdx.x * 256 + threadIdx.x;
    if (i >= OUTC * 512) return;
    int o = i >> 9, k = i & 511;
    float v = (k < 256) ? wp[o * 256 + k] : (k < 384) ? w1[o * 128 + k - 256] : w2[o * 128 + k - 384];
    uint32_t hb = bfh(v);
    wh[i] = (ush)(hb >> 16);
    wl[i] = (ush)(bfh(v - __int_as_float(hb)) >> 16);
    if (k == 0) bc[o] = bp[o] + b1[o] + b2[o];
}

extern "C" void kernel_launch(void* const* d_in, const int* in_sizes, int n_in,
                              void* d_out, int out_size)
{
    const float *F_i = (const float*)d_in[0], *F_w = (const float*)d_in[1];
    const float *bn1g = (const float*)d_in[2], *bn1b = (const float*)d_in[3];
    const float *bn1m = (const float*)d_in[4], *bn1v = (const float*)d_in[5];
    const float *bn2g = (const float*)d_in[6], *bn2b = (const float*)d_in[7];
    const float *bn2m = (const float*)d_in[8], *bn2v = (const float*)d_in[9];
    const float *wq1 = (const float*)d_in[10], *bq1 = (const float*)d_in[11];
    const float *wk1 = (const float*)d_in[12], *bk1 = (const float*)d_in[13];
    const float *wv1 = (const float*)d_in[14], *bv1 = (const float*)d_in[15];
    const float *wq2 = (const float*)d_in[16], *bq2 = (const float*)d_in[17];
    const float *wk2 = (const float*)d_in[18], *bk2 = (const float*)d_in[19];
    const float *wv2 = (const float*)d_in[20], *bv2 = (const float*)d_in[21];
    const float *wd1 = (const float*)d_in[22], *bd1 = (const float*)d_in[23];
    const float *wd2 = (const float*)d_in[24], *bd2 = (const float*)d_in[25];
    const float *wpj = (const float*)d_in[26], *bpj = (const float*)d_in[27];
    const float *wr1 = (const float*)d_in[28], *br1 = (const float*)d_in[29];
    const float *wr2 = (const float*)d_in[30], *br2 = (const float*)d_in[31];

    float *dw, *v, *part, *sum, *bqkv, *bc;
    ush *dwTh, *dwTl, *wAh, *wAl, *qTh, *qTl, *vh, *vl, *Eh, *xTh, *xTl, *wch, *wcl;
    cudaGetSymbolAddress((void**)&dw, g_dw);
    cudaGetSymbolAddress((void**)&dwTh, g_dwTh); cudaGetSymbolAddress((void**)&dwTl, g_dwTl);
    cudaGetSymbolAddress((void**)&wAh, g_wAh);   cudaGetSymbolAddress((void**)&wAl, g_wAl);
    cudaGetSymbolAddress((void**)&bqkv, g_bqkv);
    cudaGetSymbolAddress((void**)&qTh, g_qkvTh); cudaGetSymbolAddress((void**)&qTl, g_qkvTl);
    cudaGetSymbolAddress((void**)&v, g_v);
    cudaGetSymbolAddress((void**)&vh, g_vh);     cudaGetSymbolAddress((void**)&vl, g_vl);
    cudaGetSymbolAddress((void**)&Eh, g_Eh);
    cudaGetSymbolAddress((void**)&part, g_part); cudaGetSymbolAddress((void**)&sum, g_sum);
    cudaGetSymbolAddress((void**)&xTh, g_xTh);   cudaGetSymbolAddress((void**)&xTl, g_xTl);
    cudaGetSymbolAddress((void**)&wch, g_wch);   cudaGetSymbolAddress((void**)&wcl, g_wcl);
    cudaGetSymbolAddress((void**)&bc, g_bcat);

    cudaFuncSetAttribute(mma_k<1,16>, cudaFuncAttributeMaxDynamicSharedMemorySize, SMEMSZ);
    cudaFuncSetAttribute(mma_k<1,2>,  cudaFuncAttributeMaxDynamicSharedMemorySize, SMEMSZ);
    cudaFuncSetAttribute(mma_k<0,32>, cudaFuncAttributeMaxDynamicSharedMemorySize, SMEMSZ);
    cudaFuncSetAttribute(mma_k<1,8>,  cudaFuncAttributeMaxDynamicSharedMemorySize, SMEMSZ);

    const long long TT = (long long)HW * Cc;            // 524288
    const long long BR = (long long)Bn * TT;            // 2097152
    const long long TT384 = (long long)HW * 384;        // 1572864
    const long long SS = (long long)HW * HW;
    const long long XS = (long long)HW * 512;

    pack_wqkv<<<384, 256>>>(wq1, wk1, wv1, wq2, wk2, wv2,
                            bq1, bk1, bv1, bq2, bk2, bv2, wAh, wAl, bqkv);
    packw<<<512, 256>>>(wpj, bpj, wr1, br1, wr2, br2, wch, wcl, bc);
    bn_dw_kernel<<<512, 256>>>(F_i, bn1g, bn1b, bn1m, bn1v, wd1, bd1, dw);
    bn_dw_kernel<<<512, 256>>>(F_w, bn2g, bn2b, bn2m, bn2v, wd2, bd2, dw + BR);
    tsplit_k<<<dim3(128, 4, 8), 256>>>(dw, dwTh, dwTl, 128, TT, TT);
    tsplit_k<<<dim3(128, 4, 4), 256>>>(F_i, xTh + 256, xTl + 256, 512, TT, XS);
    tsplit_k<<<dim3(128, 4, 4), 256>>>(F_w, xTh + 384, xTl + 384, 512, TT, XS);

    // QKV merged: M=384 (Q|K|V), N=4096, K=128, z = branch*4+batch
    mma_k<1,16><<<dim3(32, 3, 8), 256, SMEMSZ>>>(
        wAh, wAl, dwTh, dwTl, v, qTh, qTl, bqkv, 0,
        128, 128, 384, 128, 49152, TT, TT384,
        2, 0, 255, 0, TT, HW, 384);

    // S merged: z = attn*4+batch; A=Q(own branch), B=K(other branch, +128 col)
    mma_k<1,2><<<dim3(32, 32, 8), 256, SMEMSZ>>>(
        qTh, qTl, qTh + 128, qTl + 128, 0, Eh, 0, 0, part,
        384, 384, HW, 128, TT384, TT384, SS,
        0, 4, 255, 0, 0, 0, 0);

    rcpsum<<<128, 256>>>(part, sum);
    vscale<<<4096, 256>>>((const float4*)v, (const float4*)sum, vh, vl);

    // AV merged (flipped): D[m][c] = sum_n Eh[m][n]*Vs[c][n]; M=4096, N=128, K=4096
    mma_k<0,32><<<dim3(1, 32, 8), 256, SMEMSZ>>>(
        Eh, 0, vh, vl, 0, xTh, xTl, 0, 0,
        HW, HW, 512, HW, SS, TT, XS,
        0, 4, 3, 128, 0, 0, 0);

    // out = wcat @ xT^T + bcat : M=256, N=4096, K=512
    mma_k<1,8><<<dim3(32, 2, 4), 256, SMEMSZ>>>(
        wch, wcl, xTh, xTl, (float*)d_out, 0, 0, bc, 0,
        512, 512, HW, 512, 0, XS, (long long)OUTC * HW,
        0, 0, 255, 0, 0, 0, 0);
}

// round 7
// speedup vs baseline: 3.8302x; 1.2354x over previous
#include <cuda_runtime.h>
#include <cstdint>
#include <math.h>

typedef unsigned short ush;
#define HW 4096
#define Cc 128
#define Bn 4
#define OUTC 256
#define EPSf 1e-5f
#define NSTG 4
#define STG 40960
#define SMEMSZ (NSTG*STG)

// ---------------- scratch ----------------
__device__ float g_dw [2*Bn*Cc*HW];
__device__ ush   g_dwTh[2*Bn*Cc*HW], g_dwTl[2*Bn*Cc*HW];
__device__ ush   g_wAh[2*384*128],   g_wAl[2*384*128];
__device__ float g_bqkv[2*384];
__device__ ush   g_qkvTh[2ll*Bn*HW*384], g_qkvTl[2ll*Bn*HW*384];  // [br][B][pix][Q|K|V]
__device__ float g_v [2*Bn*Cc*HW];
__device__ ush   g_vh[2*Bn*Cc*HW];
__device__ ush   g_Eh[134217728];                 // [attn][B][key][query] bf16
__device__ float g_part[64*8*HW];
__device__ float g_sum[8*HW];
__device__ ush   g_xTh[Bn*HW*512], g_xTl[Bn*HW*512];
__device__ ush   g_wch[OUTC*512], g_wcl[OUTC*512];
__device__ float g_bcat[OUTC];

__device__ __forceinline__ uint32_t smem_u32(const void* p) {
    uint32_t a;
    asm("{ .reg .u64 t; cvta.to.shared.u64 t, %1; cvt.u32.u64 %0, t; }" : "=r"(a) : "l"(p));
    return a;
}
__device__ __forceinline__ uint32_t bfh(float x) {
    uint32_t u = __float_as_uint(x);
    return (u + 0x7FFFu + ((u >> 16) & 1)) & 0xFFFF0000u;
}
__device__ __forceinline__ void ldmx4(uint32_t* r, uint32_t a) {
    asm volatile("ldmatrix.sync.aligned.m8n8.x4.shared.b16 {%0,%1,%2,%3}, [%4];"
        : "=r"(r[0]), "=r"(r[1]), "=r"(r[2]), "=r"(r[3]) : "r"(a));
}
__device__ __forceinline__ void mma16816(float* d, const uint32_t* a, const uint32_t* b) {
    asm volatile("mma.sync.aligned.m16n8k16.row.col.f32.bf16.bf16.f32 "
        "{%0,%1,%2,%3}, {%4,%5,%6,%7}, {%8,%9}, {%0,%1,%2,%3};"
        : "+f"(d[0]), "+f"(d[1]), "+f"(d[2]), "+f"(d[3])
        : "r"(a[0]), "r"(a[1]), "r"(a[2]), "r"(a[3]), "r"(b[0]), "r"(b[1]));
}
#define CP16(d, s) asm volatile("cp.async.cg.shared.global [%0], [%1], 16;" :: "r"(d), "l"(s))
#define CPCOMMIT() asm volatile("cp.async.commit_group;" ::: "memory")
#define CPWAIT2()  asm volatile("cp.async.wait_group 2;" ::: "memory")

// ===== cp.async pipelined split-bf16 warp-MMA GEMM: D[m][n] = sum_k A[m][k]*B[n][k] =====
// AL: include al*bh pass; BL: include ah*bl pass.
// FLG: 2=exp+colsum+bf16hi trans store(E) | 16=QKV mixed | 32=row split store(AV) | 8=fp32 row store
template <int AL, int BL, int FLG>
__global__ void __launch_bounds__(256, 1) mma_k(
    const ush* __restrict__ Ah, const ush* __restrict__ Al,
    const ush* __restrict__ Bh, const ush* __restrict__ Bl,
    float* __restrict__ Cf, ush* __restrict__ Ch, ush* __restrict__ Cl,
    const float* __restrict__ bias, float* __restrict__ part,
    int lda, int ldb, int ldc, int K,
    long long bsA, long long bsB, long long bsC,
    int zshA, int zxB, int zmC, int cshift,
    long long bsC2, int ldc2, int bstride)
{
    extern __shared__ char sm[];
    float* smf = (float*)sm;
    uint32_t su = smem_u32(sm);
    int tid = threadIdx.x, lane = tid & 31, w = tid >> 5;
    int wm = w & 3, wn = w >> 2;
    int m0 = blockIdx.y * 128, n0 = blockIdx.x * 128;
    long long z = blockIdx.z;

    const ush* pAh = Ah + (z >> zshA) * bsA;
    const ush* pAl = Al + (z >> zshA) * bsA;
    long long zB = z ^ zxB;
    const ush* pBh = Bh + zB * bsB;
    const ush* pBl = Bl + zB * bsB;
    long long zC = z & zmC;
    int colofs = (int)(z >> 2) * cshift;

    float acc[2][8][4];
#pragma unroll
    for (int a = 0; a < 2; a++)
#pragma unroll
        for (int b = 0; b < 8; b++)
#pragma unroll
            for (int c = 0; c < 4; c++) acc[a][b][c] = 0.f;

    int nch = K >> 5;

    auto cpstage = [&](int ch) {
        uint32_t dst = su + (ch & (NSTG - 1)) * STG;
        int k0 = ch << 5;
#pragma unroll
        for (int i = 0; i < 2; i++) {
            int idx = tid + (i << 8);
            int r = idx >> 2, c8 = (idx & 3) << 3;
            uint32_t doff = r * 80 + (c8 << 1);
            CP16(dst + doff,         pAh + (long long)(m0 + r) * lda + k0 + c8);
            if (AL)
                CP16(dst + 10240 + doff, pAl + (long long)(m0 + r) * lda + k0 + c8);
            CP16(dst + 20480 + doff, pBh + (long long)(n0 + r) * ldb + k0 + c8);
            if (BL)
                CP16(dst + 30720 + doff, pBl + (long long)(n0 + r) * ldb + k0 + c8);
        }
    };
    auto consume = [&](uint32_t sst) {
#pragma unroll
        for (int kk = 0; kk < 32; kk += 16) {
            uint32_t ah[2][4], al[2][4], bh[4][4], bl[4][4];
            int rA = (lane & 7) + ((lane >> 3) & 1) * 8;
            int kA = kk + (lane >> 4) * 8;
#pragma unroll
            for (int mt = 0; mt < 2; mt++) {
                uint32_t ad = sst + (wm * 32 + mt * 16 + rA) * 80 + kA * 2;
                ldmx4(ah[mt], ad);
                if (AL) ldmx4(al[mt], ad + 10240);
            }
            int rB = (lane & 7) + (lane >> 4) * 8;
            int kB = kk + ((lane >> 3) & 1) * 8;
#pragma unroll
            for (int nt = 0; nt < 4; nt++) {
                uint32_t bd = sst + 20480 + (wn * 64 + nt * 16 + rB) * 80 + kB * 2;
                ldmx4(bh[nt], bd);
                if (BL) ldmx4(bl[nt], bd + 10240);
            }
#pragma unroll
            for (int mt = 0; mt < 2; mt++)
#pragma unroll
                for (int nt = 0; nt < 8; nt++) {
                    const uint32_t* ph = &bh[nt >> 1][(nt & 1) * 2];
                    const uint32_t* pl = &bl[nt >> 1][(nt & 1) * 2];
                    mma16816(acc[mt][nt], ah[mt], ph);
                    if (BL) mma16816(acc[mt][nt], ah[mt], pl);
                    if (AL) mma16816(acc[mt][nt], al[mt], ph);
                }
        }
    };

    cpstage(0); CPCOMMIT();
    cpstage(1); CPCOMMIT();
    cpstage(2); CPCOMMIT();
    CPWAIT2();
    __syncthreads();
    for (int ch = 0; ch < nch; ch++) {
        consume(su + (ch & (NSTG - 1)) * STG);
        __syncthreads();
        if (ch + 3 < nch) cpstage(ch + 3);
        CPCOMMIT();
        if (ch + 1 < nch) { CPWAIT2(); __syncthreads(); }
    }

    // acc -> smem fp32 tile (stride 130)
    __syncthreads();
#pragma unroll
    for (int mt = 0; mt < 2; mt++)
#pragma unroll
        for (int nt = 0; nt < 8; nt++) {
            int r = wm * 32 + mt * 16 + (lane >> 2);
            int c = wn * 64 + nt * 8 + 2 * (lane & 3);
            *(float2*)&smf[r * 130 + c]       = make_float2(acc[mt][nt][0], acc[mt][nt][1]);
            *(float2*)&smf[(r + 8) * 130 + c] = make_float2(acc[mt][nt][2], acc[mt][nt][3]);
        }
    __syncthreads();

    if (FLG & 2) {               // S: exp + colsum + bf16-hi trans store
        int r = tid & 127, hf = tid >> 7;
        float lsum = 0.f;
        ush* co = Ch + zC * bsC;
        int j0 = hf * 64;
#pragma unroll 4
        for (int j = j0; j < j0 + 64; j++) {
            float e = __expf(fminf(smf[r * 130 + j], 60.f));
            lsum += e;
            co[(long long)(n0 + j) * ldc + m0 + r] = (ush)(bfh(e) >> 16);
        }
        part[((long long)blockIdx.x * 2 + hf) * (8 * HW) + z * HW + m0 + r] = lsum;
    } else if (FLG & 32) {       // AV: row split store
        ush* ch2 = Ch + zC * bsC;
        ush* cl2 = Cl + zC * bsC;
#pragma unroll 4
        for (int i = tid; i < 16384; i += 256) {
            int r = i >> 7, c = i & 127;
            float v = smf[r * 130 + c];
            long long o = (long long)(m0 + r) * ldc + colofs + n0 + c;
            uint32_t hb = bfh(v);
            ch2[o] = (ush)(hb >> 16);
            cl2[o] = (ush)(bfh(v - __int_as_float(hb)) >> 16);
        }
    } else if (FLG & 16) {       // QKV mixed
        if (blockIdx.y == 2) {   // V rows: fp32 row store
            float* cf = Cf + z * bsC2;
#pragma unroll 4
            for (int i = tid; i < 16384; i += 256) {
                int r = i >> 7, c = i & 127;
                cf[(long long)r * ldc2 + n0 + c] =
                    smf[r * 130 + c] + bias[(z >> zshA) * bstride + m0 + r];
            }
        } else {                 // Q/K: trans split store + bias
            int r = tid & 127, hf = tid >> 7;
            float bb = bias[(z >> zshA) * bstride + m0 + r];
            ush* ch2 = Ch + zC * bsC;
            ush* cl2 = Cl + zC * bsC;
            int j0 = hf * 64;
#pragma unroll 4
            for (int j = j0; j < j0 + 64; j++) {
                float v = smf[r * 130 + j] + bb;
                long long o = (long long)(n0 + j) * ldc + m0 + r;
                uint32_t hb = bfh(v);
                ch2[o] = (ush)(hb >> 16);
                cl2[o] = (ush)(bfh(v - __int_as_float(hb)) >> 16);
            }
        }
    } else {                     // fp32 row store + bias
        float* cf = Cf + zC * bsC;
#pragma unroll 4
        for (int i = tid; i < 16384; i += 256) {
            int r = i >> 7, c = i & 127;
            cf[(long long)(m0 + r) * ldc + n0 + c] =
                smf[r * 130 + c] + bias[(z >> zshA) * bstride + m0 + r];
        }
    }
}

// ---- BN(eval) + depthwise 3x3 SAME, both branches in one launch ----
__global__ void __launch_bounds__(256) bn_dw_kernel(
    const float* __restrict__ x0, const float* __restrict__ x1,
    const float* __restrict__ g0, const float* __restrict__ g1,
    const float* __restrict__ b0, const float* __restrict__ b1,
    const float* __restrict__ m0p, const float* __restrict__ m1p,
    const float* __restrict__ v0, const float* __restrict__ v1,
    const float* __restrict__ w0p, const float* __restrict__ w1p,
    const float* __restrict__ d0, const float* __restrict__ d1,
    float* __restrict__ y)
{
    __shared__ float tile[66 * 66];
    int bc = blockIdx.x, sel = bc >> 9, lc = bc & 511, c = bc & 127;
    const float* xp = (sel ? x1 : x0) + (size_t)lc * HW;
    const float* g = sel ? g1 : g0; const float* b = sel ? b1 : b0;
    const float* m = sel ? m1p : m0p; const float* v = sel ? v1 : v0;
    const float* wdw = sel ? w1p : w0p; const float* bdw = sel ? d1 : d0;
    float sc = g[c] * rsqrtf(v[c] + EPSf), sh = b[c] - m[c] * sc;
    for (int i = threadIdx.x; i < 66 * 66; i += 256) {
        int r = i / 66 - 1, cl = i % 66 - 1;
        tile[i] = (r >= 0 && r < 64 && cl >= 0 && cl < 64) ? xp[r * 64 + cl] * sc + sh : 0.f;
    }
    __syncthreads();
    float w0 = wdw[c*9], w1 = wdw[c*9+1], w2 = wdw[c*9+2], w3 = wdw[c*9+3], w4 = wdw[c*9+4];
    float w5 = wdw[c*9+5], w6 = wdw[c*9+6], w7 = wdw[c*9+7], w8 = wdw[c*9+8], bb = bdw[c];
    float* yp = y + (size_t)bc * HW;
    for (int i = threadIdx.x; i < HW; i += 256) {
        const float* t = &tile[(i >> 6) * 66 + (i & 63)];
        yp[i] = bb + t[0]*w0 + t[1]*w1 + t[2]*w2 + t[66]*w3 + t[67]*w4 + t[68]*w5
                   + t[132]*w6 + t[133]*w7 + t[134]*w8;
    }
}

// ---- transpose [128][HW] -> split bf16 [HW][ldd] ----
__global__ void __launch_bounds__(256) tsplit_k(
    const float* __restrict__ src, ush* __restrict__ dh, ush* __restrict__ dl,
    int ldd, long long bsS, long long bsD)
{
    __shared__ float t[32][33];
    src += blockIdx.z * bsS; dh += blockIdx.z * bsD; dl += blockIdx.z * bsD;
    int p0 = blockIdx.x * 32, c0 = blockIdx.y * 32;
    int x = threadIdx.x & 31, y = threadIdx.x >> 5;
#pragma unroll
    for (int i = 0; i < 32; i += 8) t[y + i][x] = src[(long long)(c0 + y + i) * HW + p0 + x];
    __syncthreads();
#pragma unroll
    for (int i = 0; i < 32; i += 8) {
        float v = t[x][y + i];
        long long o = (long long)(p0 + y + i) * ldd + c0 + x;
        uint32_t hb = bfh(v);
        dh[o] = (ush)(hb >> 16);
        dl[o] = (ush)(bfh(v - __int_as_float(hb)) >> 16);
    }
}

// ---- pack stacked QKV weights [2][384][128] split + bias [2][384] ----
__global__ void __launch_bounds__(256) pack_wqkv(
    const float* wq1, const float* wk1, const float* wv1,
    const float* wq2, const float* wk2, const float* wv2,
    const float* bq1, const float* bk1, const float* bv1,
    const float* bq2, const float* bk2, const float* bv2,
    ush* wAh, ush* wAl, float* bqkv)
{
    int i = blockIdx.x * 256 + threadIdx.x;   // 98304
    if (i >= 2 * 384 * 128) return;
    int br = i / 49152, rem = i % 49152, r = rem >> 7, c = rem & 127;
    const float* w; const float* bs;
    if (br == 0) { w = r < 128 ? wq1 : r < 256 ? wk1 : wv1; bs = r < 128 ? bq1 : r < 256 ? bk1 : bv1; }
    else         { w = r < 128 ? wq2 : r < 256 ? wk2 : wv2; bs = r < 128 ? bq2 : r < 256 ? bk2 : bv2; }
    float v = w[(r & 127) * 128 + c];
    uint32_t hb = bfh(v);
    wAh[i] = (ush)(hb >> 16);
    wAl[i] = (ush)(bfh(v - __int_as_float(hb)) >> 16);
    if (c == 0) bqkv[br * 384 + r] = bs[r & 127];
}

// ---- reduce 64 partial colsums -> reciprocal ----
__global__ void __launch_bounds__(256) rcpsum(const float* __restrict__ part, float* __restrict__ sums)
{
    int i = blockIdx.x * 256 + threadIdx.x;    // 32768
    float s = 0.f;
#pragma unroll
    for (int k = 0; k < 64; k++) s += part[(long long)k * 32768 + i];
    sums[i] = 1.f / s;
}

// ---- fold rs into V, bf16-hi only ----
__global__ void __launch_bounds__(256) vscale(
    const float4* __restrict__ v, const float4* __restrict__ rs4,
    ush* __restrict__ vh)
{
    int i = blockIdx.x * 256 + threadIdx.x;    // 1,048,576 float4
    int n4 = i & 1023, tb = i >> 17;
    float4 a = v[i], r = rs4[((tb ^ 4) << 10) + n4];
    a.x *= r.x; a.y *= r.y; a.z *= r.z; a.w *= r.w;
    uint32_t h0 = bfh(a.x), h1 = bfh(a.y), h2 = bfh(a.z), h3 = bfh(a.w);
    ((uint2*)vh)[i] = make_uint2((h0 >> 16) | h1, (h2 >> 16) | h3);
}

// ---- pack fused output weight (split bf16) + bias ----
__global__ void __launch_bounds__(256) packw(
    const float* __restrict__ wp, const float* __restrict__ bp,
    const float* __restrict__ w1, const float* __restrict__ b1,
    const float* __restrict__ w2, const float* __restrict__ b2,
    ush* __restrict__ wh, ush* __restrict__ wl, float* __restrict__ bc)
{
    int i = blockIdx.x * 256 + threadIdx.x;
    if (i >= OUTC * 512) return;
    int o = i >> 9, k = i & 511;
    float v = (k < 256) ? wp[o * 256 + k] : (k < 384) ? w1[o * 128 + k - 256] : w2[o * 128 + k - 384];
    uint32_t hb = bfh(v);
    wh[i] = (ush)(hb >> 16);
    wl[i] = (ush)(bfh(v - __int_as_float(hb)) >> 16);
    if (k == 0) bc[o] = bp[o] + b1[o] + b2[o];
}

extern "C" void kernel_launch(void* const* d_in, const int* in_sizes, int n_in,
                              void* d_out, int out_size)
{
    const float *F_i = (const float*)d_in[0], *F_w = (const float*)d_in[1];
    const float *bn1g = (const float*)d_in[2], *bn1b = (const float*)d_in[3];
    const float *bn1m = (const float*)d_in[4], *bn1v = (const float*)d_in[5];
    const float *bn2g = (const float*)d_in[6], *bn2b = (const float*)d_in[7];
    const float *bn2m = (const float*)d_in[8], *bn2v = (const float*)d_in[9];
    const float *wq1 = (const float*)d_in[10], *bq1 = (const float*)d_in[11];
    const float *wk1 = (const float*)d_in[12], *bk1 = (const float*)d_in[13];
    const float *wv1 = (const float*)d_in[14], *bv1 = (const float*)d_in[15];
    const float *wq2 = (const float*)d_in[16], *bq2 = (const float*)d_in[17];
    const float *wk2 = (const float*)d_in[18], *bk2 = (const float*)d_in[19];
    const float *wv2 = (const float*)d_in[20], *bv2 = (const float*)d_in[21];
    const float *wd1 = (const float*)d_in[22], *bd1 = (const float*)d_in[23];
    const float *wd2 = (const float*)d_in[24], *bd2 = (const float*)d_in[25];
    const float *wpj = (const float*)d_in[26], *bpj = (const float*)d_in[27];
    const float *wr1 = (const float*)d_in[28], *br1 = (const float*)d_in[29];
    const float *wr2 = (const float*)d_in[30], *br2 = (const float*)d_in[31];

    float *dw, *v, *part, *sum, *bqkv, *bc;
    ush *dwTh, *dwTl, *wAh, *wAl, *qTh, *qTl, *vh, *Eh, *xTh, *xTl, *wch, *wcl;
    cudaGetSymbolAddress((void**)&dw, g_dw);
    cudaGetSymbolAddress((void**)&dwTh, g_dwTh); cudaGetSymbolAddress((void**)&dwTl, g_dwTl);
    cudaGetSymbolAddress((void**)&wAh, g_wAh);   cudaGetSymbolAddress((void**)&wAl, g_wAl);
    cudaGetSymbolAddress((void**)&bqkv, g_bqkv);
    cudaGetSymbolAddress((void**)&qTh, g_qkvTh); cudaGetSymbolAddress((void**)&qTl, g_qkvTl);
    cudaGetSymbolAddress((void**)&v, g_v);
    cudaGetSymbolAddress((void**)&vh, g_vh);
    cudaGetSymbolAddress((void**)&Eh, g_Eh);
    cudaGetSymbolAddress((void**)&part, g_part); cudaGetSymbolAddress((void**)&sum, g_sum);
    cudaGetSymbolAddress((void**)&xTh, g_xTh);   cudaGetSymbolAddress((void**)&xTl, g_xTl);
    cudaGetSymbolAddress((void**)&wch, g_wch);   cudaGetSymbolAddress((void**)&wcl, g_wcl);
    cudaGetSymbolAddress((void**)&bc, g_bcat);

    cudaFuncSetAttribute(mma_k<1,1,16>, cudaFuncAttributeMaxDynamicSharedMemorySize, SMEMSZ);
    cudaFuncSetAttribute(mma_k<0,1,2>,  cudaFuncAttributeMaxDynamicSharedMemorySize, SMEMSZ);
    cudaFuncSetAttribute(mma_k<0,0,32>, cudaFuncAttributeMaxDynamicSharedMemorySize, SMEMSZ);
    cudaFuncSetAttribute(mma_k<1,1,8>,  cudaFuncAttributeMaxDynamicSharedMemorySize, SMEMSZ);

    const long long TT = (long long)HW * Cc;            // 524288
    const long long TT384 = (long long)HW * 384;        // 1572864
    const long long SS = (long long)HW * HW;
    const long long XS = (long long)HW * 512;

    pack_wqkv<<<384, 256>>>(wq1, wk1, wv1, wq2, wk2, wv2,
                            bq1, bk1, bv1, bq2, bk2, bv2, wAh, wAl, bqkv);
    packw<<<512, 256>>>(wpj, bpj, wr1, br1, wr2, br2, wch, wcl, bc);
    bn_dw_kernel<<<1024, 256>>>(F_i, F_w, bn1g, bn2g, bn1b, bn2b, bn1m, bn2m,
                                bn1v, bn2v, wd1, wd2, bd1, bd2, dw);
    tsplit_k<<<dim3(128, 4, 8), 256>>>(dw, dwTh, dwTl, 128, TT, TT);
    tsplit_k<<<dim3(128, 4, 4), 256>>>(F_i, xTh + 256, xTl + 256, 512, TT, XS);
    tsplit_k<<<dim3(128, 4, 4), 256>>>(F_w, xTh + 384, xTl + 384, 512, TT, XS);

    // QKV merged: M=384 (Q|K|V), N=4096, K=128, z = branch*4+batch  (3-pass)
    mma_k<1,1,16><<<dim3(32, 3, 8), 256, SMEMSZ>>>(
        wAh, wAl, dwTh, dwTl, v, qTh, qTl, bqkv, 0,
        128, 128, 384, 128, 49152, TT, TT384,
        2, 0, 255, 0, TT, HW, 384);

    // S merged: z = attn*4+batch; A=Q hi (own branch), B=K hi+lo (other branch)  (2-pass)
    mma_k<0,1,2><<<dim3(32, 32, 8), 256, SMEMSZ>>>(
        qTh, qTh, qTh + 128, qTl + 128, 0, Eh, 0, 0, part,
        384, 384, HW, 128, TT384, TT384, SS,
        0, 4, 255, 0, 0, 0, 0);

    rcpsum<<<128, 256>>>(part, sum);
    vscale<<<4096, 256>>>((const float4*)v, (const float4*)sum, vh);

    // AV merged (flipped): D[m][c] = sum_n Eh[m][n]*Vh[c][n]; M=4096, N=128, K=4096  (1-pass)
    mma_k<0,0,32><<<dim3(1, 32, 8), 256, SMEMSZ>>>(
        Eh, Eh, vh, vh, 0, xTh, xTl, 0, 0,
        HW, HW, 512, HW, SS, TT, XS,
        0, 4, 3, 128, 0, 0, 0);

    // out = wcat @ xT^T + bcat : M=256, N=4096, K=512  (3-pass)
    mma_k<1,1,8><<<dim3(32, 2, 4), 256, SMEMSZ>>>(
        wch, wcl, xTh, xTl, (float*)d_out, 0, 0, bc, 0,
        512, 512, HW, 512, 0, XS, (long long)OUTC * HW,
        0, 0, 255, 0, 0, 0, 0);
}

// round 8
// speedup vs baseline: 4.2612x; 1.1125x over previous
#include <cuda_runtime.h>
#include <cstdint>
#include <math.h>

typedef unsigned short ush;
#define HW 4096
#define Cc 128
#define Bn 4
#define OUTC 256
#define EPSf 1e-5f
#define NSTG 4
#define STG 40960
#define SMEMSZ (NSTG*STG)

// ---------------- scratch ----------------
__device__ float g_dw [2*Bn*Cc*HW];
__device__ ush   g_dwTh[2*Bn*Cc*HW], g_dwTl[2*Bn*Cc*HW];
__device__ ush   g_wAh[2*384*128],   g_wAl[2*384*128];
__device__ float g_bqkv[2*384];
__device__ ush   g_qkvTh[2ll*Bn*HW*384], g_qkvTl[2ll*Bn*HW*384];  // [br][B][pix][Q|K|V]
__device__ float g_v [2*Bn*Cc*HW];
__device__ ush   g_vh[2*Bn*Cc*HW];
__device__ ush   g_Eh[134217728];                 // [attn][B][key][query] bf16
__device__ float g_part[64*8*HW];
__device__ float g_sum[8*HW];
__device__ ush   g_xTh[Bn*HW*512], g_xTl[Bn*HW*512];
__device__ ush   g_wch[OUTC*512], g_wcl[OUTC*512];
__device__ float g_bcat[OUTC];

__device__ __forceinline__ uint32_t smem_u32(const void* p) {
    uint32_t a;
    asm("{ .reg .u64 t; cvta.to.shared.u64 t, %1; cvt.u32.u64 %0, t; }" : "=r"(a) : "l"(p));
    return a;
}
__device__ __forceinline__ uint32_t bfh(float x) {
    uint32_t u = __float_as_uint(x);
    return (u + 0x7FFFu + ((u >> 16) & 1)) & 0xFFFF0000u;
}
__device__ __forceinline__ void ldmx4(uint32_t* r, uint32_t a) {
    asm volatile("ldmatrix.sync.aligned.m8n8.x4.shared.b16 {%0,%1,%2,%3}, [%4];"
        : "=r"(r[0]), "=r"(r[1]), "=r"(r[2]), "=r"(r[3]) : "r"(a));
}
__device__ __forceinline__ void mma16816(float* d, const uint32_t* a, const uint32_t* b) {
    asm volatile("mma.sync.aligned.m16n8k16.row.col.f32.bf16.bf16.f32 "
        "{%0,%1,%2,%3}, {%4,%5,%6,%7}, {%8,%9}, {%0,%1,%2,%3};"
        : "+f"(d[0]), "+f"(d[1]), "+f"(d[2]), "+f"(d[3])
        : "r"(a[0]), "r"(a[1]), "r"(a[2]), "r"(a[3]), "r"(b[0]), "r"(b[1]));
}
#define CP16(d, s) asm volatile("cp.async.cg.shared.global [%0], [%1], 16;" :: "r"(d), "l"(s))
#define CPCOMMIT() asm volatile("cp.async.commit_group;" ::: "memory")
#define CPWAIT2()  asm volatile("cp.async.wait_group 2;" ::: "memory")

// ===== cp.async pipelined split-bf16 warp-MMA GEMM: D[m][n] = sum_k A[m][k]*B[n][k] =====
// AL: include al*bh pass; BL: include ah*bl pass.
// FLG: 2=exp+colsum+bf16hi trans store(E) | 16=QKV mixed | 32=row split store(AV)
//      | 8=fp32 row store | 64=skip lo-plane store in QKV Q/K epilogue
template <int AL, int BL, int FLG>
__global__ void __launch_bounds__(256, 1) mma_k(
    const ush* __restrict__ Ah, const ush* __restrict__ Al,
    const ush* __restrict__ Bh, const ush* __restrict__ Bl,
    float* __restrict__ Cf, ush* __restrict__ Ch, ush* __restrict__ Cl,
    const float* __restrict__ bias, float* __restrict__ part,
    int lda, int ldb, int ldc, int K,
    long long bsA, long long bsB, long long bsC,
    int zshA, int zxB, int zmC, int cshift,
    long long bsC2, int ldc2, int bstride)
{
    extern __shared__ char sm[];
    float* smf = (float*)sm;
    uint32_t su = smem_u32(sm);
    int tid = threadIdx.x, lane = tid & 31, w = tid >> 5;
    int wm = w & 3, wn = w >> 2;
    int m0 = blockIdx.y * 128, n0 = blockIdx.x * 128;
    long long z = blockIdx.z;

    const ush* pAh = Ah + (z >> zshA) * bsA;
    const ush* pAl = Al + (z >> zshA) * bsA;
    long long zB = z ^ zxB;
    const ush* pBh = Bh + zB * bsB;
    const ush* pBl = Bl + zB * bsB;
    long long zC = z & zmC;
    int colofs = (int)(z >> 2) * cshift;

    float acc[2][8][4];
#pragma unroll
    for (int a = 0; a < 2; a++)
#pragma unroll
        for (int b = 0; b < 8; b++)
#pragma unroll
            for (int c = 0; c < 4; c++) acc[a][b][c] = 0.f;

    int nch = K >> 5;

    auto cpstage = [&](int ch) {
        uint32_t dst = su + (ch & (NSTG - 1)) * STG;
        int k0 = ch << 5;
#pragma unroll
        for (int i = 0; i < 2; i++) {
            int idx = tid + (i << 8);
            int r = idx >> 2, c8 = (idx & 3) << 3;
            uint32_t doff = r * 80 + (c8 << 1);
            CP16(dst + doff,         pAh + (long long)(m0 + r) * lda + k0 + c8);
            if (AL)
                CP16(dst + 10240 + doff, pAl + (long long)(m0 + r) * lda + k0 + c8);
            CP16(dst + 20480 + doff, pBh + (long long)(n0 + r) * ldb + k0 + c8);
            if (BL)
                CP16(dst + 30720 + doff, pBl + (long long)(n0 + r) * ldb + k0 + c8);
        }
    };
    auto consume = [&](uint32_t sst) {
#pragma unroll
        for (int kk = 0; kk < 32; kk += 16) {
            uint32_t ah[2][4], al[2][4], bh[4][4], bl[4][4];
            int rA = (lane & 7) + ((lane >> 3) & 1) * 8;
            int kA = kk + (lane >> 4) * 8;
#pragma unroll
            for (int mt = 0; mt < 2; mt++) {
                uint32_t ad = sst + (wm * 32 + mt * 16 + rA) * 80 + kA * 2;
                ldmx4(ah[mt], ad);
                if (AL) ldmx4(al[mt], ad + 10240);
            }
            int rB = (lane & 7) + (lane >> 4) * 8;
            int kB = kk + ((lane >> 3) & 1) * 8;
#pragma unroll
            for (int nt = 0; nt < 4; nt++) {
                uint32_t bd = sst + 20480 + (wn * 64 + nt * 16 + rB) * 80 + kB * 2;
                ldmx4(bh[nt], bd);
                if (BL) ldmx4(bl[nt], bd + 10240);
            }
#pragma unroll
            for (int mt = 0; mt < 2; mt++)
#pragma unroll
                for (int nt = 0; nt < 8; nt++) {
                    const uint32_t* ph = &bh[nt >> 1][(nt & 1) * 2];
                    const uint32_t* pl = &bl[nt >> 1][(nt & 1) * 2];
                    mma16816(acc[mt][nt], ah[mt], ph);
                    if (BL) mma16816(acc[mt][nt], ah[mt], pl);
                    if (AL) mma16816(acc[mt][nt], al[mt], ph);
                }
        }
    };

    cpstage(0); CPCOMMIT();
    cpstage(1); CPCOMMIT();
    cpstage(2); CPCOMMIT();
    CPWAIT2();
    __syncthreads();
    for (int ch = 0; ch < nch; ch++) {
        consume(su + (ch & (NSTG - 1)) * STG);
        __syncthreads();
        if (ch + 3 < nch) cpstage(ch + 3);
        CPCOMMIT();
        if (ch + 1 < nch) { CPWAIT2(); __syncthreads(); }
    }

    // acc -> smem fp32 tile (stride 130)
    __syncthreads();
#pragma unroll
    for (int mt = 0; mt < 2; mt++)
#pragma unroll
        for (int nt = 0; nt < 8; nt++) {
            int r = wm * 32 + mt * 16 + (lane >> 2);
            int c = wn * 64 + nt * 8 + 2 * (lane & 3);
            *(float2*)&smf[r * 130 + c]       = make_float2(acc[mt][nt][0], acc[mt][nt][1]);
            *(float2*)&smf[(r + 8) * 130 + c] = make_float2(acc[mt][nt][2], acc[mt][nt][3]);
        }
    __syncthreads();

    if (FLG & 2) {               // S: exp + colsum + bf16-hi trans store
        int r = tid & 127, hf = tid >> 7;
        float lsum = 0.f;
        ush* co = Ch + zC * bsC;
        int j0 = hf * 64;
#pragma unroll 4
        for (int j = j0; j < j0 + 64; j++) {
            float e = __expf(fminf(smf[r * 130 + j], 60.f));
            lsum += e;
            co[(long long)(n0 + j) * ldc + m0 + r] = (ush)(bfh(e) >> 16);
        }
        part[((long long)blockIdx.x * 2 + hf) * (8 * HW) + z * HW + m0 + r] = lsum;
    } else if (FLG & 32) {       // AV: row split store
        ush* ch2 = Ch + zC * bsC;
        ush* cl2 = Cl + zC * bsC;
#pragma unroll 4
        for (int i = tid; i < 16384; i += 256) {
            int r = i >> 7, c = i & 127;
            float v = smf[r * 130 + c];
            long long o = (long long)(m0 + r) * ldc + colofs + n0 + c;
            uint32_t hb = bfh(v);
            ch2[o] = (ush)(hb >> 16);
            cl2[o] = (ush)(bfh(v - __int_as_float(hb)) >> 16);
        }
    } else if (FLG & 16) {       // QKV mixed
        if (blockIdx.y == 2) {   // V rows: fp32 row store
            float* cf = Cf + z * bsC2;
#pragma unroll 4
            for (int i = tid; i < 16384; i += 256) {
                int r = i >> 7, c = i & 127;
                cf[(long long)r * ldc2 + n0 + c] =
                    smf[r * 130 + c] + bias[(z >> zshA) * bstride + m0 + r];
            }
        } else {                 // Q/K: trans store + bias (hi, optional lo)
            int r = tid & 127, hf = tid >> 7;
            float bb = bias[(z >> zshA) * bstride + m0 + r];
            ush* ch2 = Ch + zC * bsC;
            ush* cl2 = Cl + zC * bsC;
            int j0 = hf * 64;
#pragma unroll 4
            for (int j = j0; j < j0 + 64; j++) {
                float v = smf[r * 130 + j] + bb;
                long long o = (long long)(n0 + j) * ldc + m0 + r;
                uint32_t hb = bfh(v);
                ch2[o] = (ush)(hb >> 16);
                if (!(FLG & 64))
                    cl2[o] = (ush)(bfh(v - __int_as_float(hb)) >> 16);
            }
        }
    } else {                     // fp32 row store + bias
        float* cf = Cf + zC * bsC;
#pragma unroll 4
        for (int i = tid; i < 16384; i += 256) {
            int r = i >> 7, c = i & 127;
            cf[(long long)(m0 + r) * ldc + n0 + c] =
                smf[r * 130 + c] + bias[(z >> zshA) * bstride + m0 + r];
        }
    }
}

// ---- BN(eval) + depthwise 3x3 SAME, both branches in one launch ----
__global__ void __launch_bounds__(256) bn_dw_kernel(
    const float* __restrict__ x0, const float* __restrict__ x1,
    const float* __restrict__ g0, const float* __restrict__ g1,
    const float* __restrict__ b0, const float* __restrict__ b1,
    const float* __restrict__ m0p, const float* __restrict__ m1p,
    const float* __restrict__ v0, const float* __restrict__ v1,
    const float* __restrict__ w0p, const float* __restrict__ w1p,
    const float* __restrict__ d0, const float* __restrict__ d1,
    float* __restrict__ y)
{
    __shared__ float tile[66 * 66];
    int bc = blockIdx.x, sel = bc >> 9, lc = bc & 511, c = bc & 127;
    const float* xp = (sel ? x1 : x0) + (size_t)lc * HW;
    const float* g = sel ? g1 : g0; const float* b = sel ? b1 : b0;
    const float* m = sel ? m1p : m0p; const float* v = sel ? v1 : v0;
    const float* wdw = sel ? w1p : w0p; const float* bdw = sel ? d1 : d0;
    float sc = g[c] * rsqrtf(v[c] + EPSf), sh = b[c] - m[c] * sc;
    for (int i = threadIdx.x; i < 66 * 66; i += 256) {
        int r = i / 66 - 1, cl = i % 66 - 1;
        tile[i] = (r >= 0 && r < 64 && cl >= 0 && cl < 64) ? xp[r * 64 + cl] * sc + sh : 0.f;
    }
    __syncthreads();
    float w0 = wdw[c*9], w1 = wdw[c*9+1], w2 = wdw[c*9+2], w3 = wdw[c*9+3], w4 = wdw[c*9+4];
    float w5 = wdw[c*9+5], w6 = wdw[c*9+6], w7 = wdw[c*9+7], w8 = wdw[c*9+8], bb = bdw[c];
    float* yp = y + (size_t)bc * HW;
    for (int i = threadIdx.x; i < HW; i += 256) {
        const float* t = &tile[(i >> 6) * 66 + (i & 63)];
        yp[i] = bb + t[0]*w0 + t[1]*w1 + t[2]*w2 + t[66]*w3 + t[67]*w4 + t[68]*w5
                   + t[132]*w6 + t[133]*w7 + t[134]*w8;
    }
}

// ---- transpose [128][HW] -> split bf16 [HW][ldd] ----
__global__ void __launch_bounds__(256) tsplit_k(
    const float* __restrict__ src, ush* __restrict__ dh, ush* __restrict__ dl,
    int ldd, long long bsS, long long bsD)
{
    __shared__ float t[32][33];
    src += blockIdx.z * bsS; dh += blockIdx.z * bsD; dl += blockIdx.z * bsD;
    int p0 = blockIdx.x * 32, c0 = blockIdx.y * 32;
    int x = threadIdx.x & 31, y = threadIdx.x >> 5;
#pragma unroll
    for (int i = 0; i < 32; i += 8) t[y + i][x] = src[(long long)(c0 + y + i) * HW + p0 + x];
    __syncthreads();
#pragma unroll
    for (int i = 0; i < 32; i += 8) {
        float v = t[x][y + i];
        long long o = (long long)(p0 + y + i) * ldd + c0 + x;
        uint32_t hb = bfh(v);
        dh[o] = (ush)(hb >> 16);
        dl[o] = (ush)(bfh(v - __int_as_float(hb)) >> 16);
    }
}

// ---- pack stacked QKV weights [2][384][128] split + bias [2][384] ----
__global__ void __launch_bounds__(256) pack_wqkv(
    const float* wq1, const float* wk1, const float* wv1,
    const float* wq2, const float* wk2, const float* wv2,
    const float* bq1, const float* bk1, const float* bv1,
    const float* bq2, const float* bk2, const float* bv2,
    ush* wAh, ush* wAl, float* bqkv)
{
    int i = blockIdx.x * 256 + threadIdx.x;   // 98304
    if (i >= 2 * 384 * 128) return;
    int br = i / 49152, rem = i % 49152, r = rem >> 7, c = rem & 127;
    const float* w; const float* bs;
    if (br == 0) { w = r < 128 ? wq1 : r < 256 ? wk1 : wv1; bs = r < 128 ? bq1 : r < 256 ? bk1 : bv1; }
    else         { w = r < 128 ? wq2 : r < 256 ? wk2 : wv2; bs = r < 128 ? bq2 : r < 256 ? bk2 : bv2; }
    float v = w[(r & 127) * 128 + c];
    uint32_t hb = bfh(v);
    wAh[i] = (ush)(hb >> 16);
    wAl[i] = (ush)(bfh(v - __int_as_float(hb)) >> 16);
    if (c == 0) bqkv[br * 384 + r] = bs[r & 127];
}

// ---- reduce 64 partial colsums -> reciprocal ----
__global__ void __launch_bounds__(256) rcpsum(const float* __restrict__ part, float* __restrict__ sums)
{
    int i = blockIdx.x * 256 + threadIdx.x;    // 32768
    float s = 0.f;
#pragma unroll
    for (int k = 0; k < 64; k++) s += part[(long long)k * 32768 + i];
    sums[i] = 1.f / s;
}

// ---- fold rs into V, bf16-hi only ----
__global__ void __launch_bounds__(256) vscale(
    const float4* __restrict__ v, const float4* __restrict__ rs4,
    ush* __restrict__ vh)
{
    int i = blockIdx.x * 256 + threadIdx.x;    // 1,048,576 float4
    int n4 = i & 1023, tb = i >> 17;
    float4 a = v[i], r = rs4[((tb ^ 4) << 10) + n4];
    a.x *= r.x; a.y *= r.y; a.z *= r.z; a.w *= r.w;
    uint32_t h0 = bfh(a.x), h1 = bfh(a.y), h2 = bfh(a.z), h3 = bfh(a.w);
    ((uint2*)vh)[i] = make_uint2((h0 >> 16) | h1, (h2 >> 16) | h3);
}

// ---- pack fused output weight (split bf16) + bias ----
__global__ void __launch_bounds__(256) packw(
    const float* __restrict__ wp, const float* __restrict__ bp,
    const float* __restrict__ w1, const float* __restrict__ b1,
    const float* __restrict__ w2, const float* __restrict__ b2,
    ush* __restrict__ wh, ush* __restrict__ wl, float* __restrict__ bc)
{
    int i = blockIdx.x * 256 + threadIdx.x;
    if (i >= OUTC * 512) return;
    int o = i >> 9, k = i & 511;
    float v = (k < 256) ? wp[o * 256 + k] : (k < 384) ? w1[o * 128 + k - 256] : w2[o * 128 + k - 384];
    uint32_t hb = bfh(v);
    wh[i] = (ush)(hb >> 16);
    wl[i] = (ush)(bfh(v - __int_as_float(hb)) >> 16);
    if (k == 0) bc[o] = bp[o] + b1[o] + b2[o];
}

extern "C" void kernel_launch(void* const* d_in, const int* in_sizes, int n_in,
                              void* d_out, int out_size)
{
    const float *F_i = (const float*)d_in[0], *F_w = (const float*)d_in[1];
    const float *bn1g = (const float*)d_in[2], *bn1b = (const float*)d_in[3];
    const float *bn1m = (const float*)d_in[4], *bn1v = (const float*)d_in[5];
    const float *bn2g = (const float*)d_in[6], *bn2b = (const float*)d_in[7];
    const float *bn2m = (const float*)d_in[8], *bn2v = (const float*)d_in[9];
    const float *wq1 = (const float*)d_in[10], *bq1 = (const float*)d_in[11];
    const float *wk1 = (const float*)d_in[12], *bk1 = (const float*)d_in[13];
    const float *wv1 = (const float*)d_in[14], *bv1 = (const float*)d_in[15];
    const float *wq2 = (const float*)d_in[16], *bq2 = (const float*)d_in[17];
    const float *wk2 = (const float*)d_in[18], *bk2 = (const float*)d_in[19];
    const float *wv2 = (const float*)d_in[20], *bv2 = (const float*)d_in[21];
    const float *wd1 = (const float*)d_in[22], *bd1 = (const float*)d_in[23];
    const float *wd2 = (const float*)d_in[24], *bd2 = (const float*)d_in[25];
    const float *wpj = (const float*)d_in[26], *bpj = (const float*)d_in[27];
    const float *wr1 = (const float*)d_in[28], *br1 = (const float*)d_in[29];
    const float *wr2 = (const float*)d_in[30], *br2 = (const float*)d_in[31];

    float *dw, *v, *part, *sum, *bqkv, *bc;
    ush *dwTh, *dwTl, *wAh, *wAl, *qTh, *qTl, *vh, *Eh, *xTh, *xTl, *wch, *wcl;
    cudaGetSymbolAddress((void**)&dw, g_dw);
    cudaGetSymbolAddress((void**)&dwTh, g_dwTh); cudaGetSymbolAddress((void**)&dwTl, g_dwTl);
    cudaGetSymbolAddress((void**)&wAh, g_wAh);   cudaGetSymbolAddress((void**)&wAl, g_wAl);
    cudaGetSymbolAddress((void**)&bqkv, g_bqkv);
    cudaGetSymbolAddress((void**)&qTh, g_qkvTh); cudaGetSymbolAddress((void**)&qTl, g_qkvTl);
    cudaGetSymbolAddress((void**)&v, g_v);
    cudaGetSymbolAddress((void**)&vh, g_vh);
    cudaGetSymbolAddress((void**)&Eh, g_Eh);
    cudaGetSymbolAddress((void**)&part, g_part); cudaGetSymbolAddress((void**)&sum, g_sum);
    cudaGetSymbolAddress((void**)&xTh, g_xTh);   cudaGetSymbolAddress((void**)&xTl, g_xTl);
    cudaGetSymbolAddress((void**)&wch, g_wch);   cudaGetSymbolAddress((void**)&wcl, g_wcl);
    cudaGetSymbolAddress((void**)&bc, g_bcat);

    cudaFuncSetAttribute(mma_k<0,1,80>, cudaFuncAttributeMaxDynamicSharedMemorySize, SMEMSZ);
    cudaFuncSetAttribute(mma_k<0,0,2>,  cudaFuncAttributeMaxDynamicSharedMemorySize, SMEMSZ);
    cudaFuncSetAttribute(mma_k<0,0,32>, cudaFuncAttributeMaxDynamicSharedMemorySize, SMEMSZ);
    cudaFuncSetAttribute(mma_k<1,1,8>,  cudaFuncAttributeMaxDynamicSharedMemorySize, SMEMSZ);

    const long long TT = (long long)HW * Cc;            // 524288
    const long long TT384 = (long long)HW * 384;        // 1572864
    const long long SS = (long long)HW * HW;
    const long long XS = (long long)HW * 512;

    pack_wqkv<<<384, 256>>>(wq1, wk1, wv1, wq2, wk2, wv2,
                            bq1, bk1, bv1, bq2, bk2, bv2, wAh, wAl, bqkv);
    packw<<<512, 256>>>(wpj, bpj, wr1, br1, wr2, br2, wch, wcl, bc);
    bn_dw_kernel<<<1024, 256>>>(F_i, F_w, bn1g, bn2g, bn1b, bn2b, bn1m, bn2m,
                                bn1v, bn2v, wd1, wd2, bd1, bd2, dw);
    tsplit_k<<<dim3(128, 4, 8), 256>>>(dw, dwTh, dwTl, 128, TT, TT);
    tsplit_k<<<dim3(128, 4, 4), 256>>>(F_i, xTh + 256, xTl + 256, 512, TT, XS);
    tsplit_k<<<dim3(128, 4, 4), 256>>>(F_w, xTh + 384, xTl + 384, 512, TT, XS);

    // QKV merged: M=384 (Q|K|V), N=4096, K=128, z = branch*4+batch
    // 2-pass (wh*xh + wh*xl), Q/K store hi plane only (lo is dead: S is 1-pass)
    mma_k<0,1,80><<<dim3(32, 3, 8), 256, SMEMSZ>>>(
        wAh, wAl, dwTh, dwTl, v, qTh, qTl, bqkv, 0,
        128, 128, 384, 128, 49152, TT, TT384,
        2, 0, 255, 0, TT, HW, 384);

    // S merged: z = attn*4+batch; A=Q hi (own branch), B=K hi (other branch)  (1-pass)
    mma_k<0,0,2><<<dim3(32, 32, 8), 256, SMEMSZ>>>(
        qTh, qTh, qTh + 128, qTh + 128, 0, Eh, 0, 0, part,
        384, 384, HW, 128, TT384, TT384, SS,
        0, 4, 255, 0, 0, 0, 0);

    rcpsum<<<128, 256>>>(part, sum);
    vscale<<<4096, 256>>>((const float4*)v, (const float4*)sum, vh);

    // AV merged (flipped): D[m][c] = sum_n Eh[m][n]*Vh[c][n]; M=4096, N=128, K=4096  (1-pass)
    mma_k<0,0,32><<<dim3(1, 32, 8), 256, SMEMSZ>>>(
        Eh, Eh, vh, vh, 0, xTh, xTl, 0, 0,
        HW, HW, 512, HW, SS, TT, XS,
        0, 4, 3, 128, 0, 0, 0);

    // out = wcat @ xT^T + bcat : M=256, N=4096, K=512  (3-pass)
    mma_k<1,1,8><<<dim3(32, 2, 4), 256, SMEMSZ>>>(
        wch, wcl, xTh, xTl, (float*)d_out, 0, 0, bc, 0,
        512, 512, HW, 512, 0, XS, (long long)OUTC * HW,
        0, 0, 255, 0, 0, 0, 0);
}

// round 9
// speedup vs baseline: 5.4486x; 1.2787x over previous
#include <cuda_runtime.h>
#include <cstdint>
#include <math.h>

typedef unsigned short ush;
#define HW 4096
#define Cc 128
#define Bn 4
#define OUTC 256
#define EPSf 1e-5f
#define PL 10240

// ---------------- scratch ----------------
__device__ float g_dw [2*Bn*Cc*HW];
__device__ ush   g_dwTh[2*Bn*Cc*HW], g_dwTl[2*Bn*Cc*HW];
__device__ ush   g_wAh[2*384*128],   g_wAl[2*384*128];
__device__ float g_bqkv[2*384];
__device__ ush   g_qkvTh[2ll*Bn*HW*384], g_qkvTl[2ll*Bn*HW*384];  // [br][B][pix][Q|K|V]
__device__ float g_v [2*Bn*Cc*HW];
__device__ ush   g_vh[2*Bn*Cc*HW];
__device__ ush   g_Eh[134217728];                 // [attn][B][4096][4096] bf16
__device__ float g_part[64*8*HW];
__device__ float g_sum[8*HW];
__device__ ush   g_xTh[Bn*HW*512], g_xTl[Bn*HW*512];
__device__ ush   g_wch[OUTC*512], g_wcl[OUTC*512];
__device__ float g_bcat[OUTC];

__device__ __forceinline__ uint32_t smem_u32(const void* p) {
    uint32_t a;
    asm("{ .reg .u64 t; cvta.to.shared.u64 t, %1; cvt.u32.u64 %0, t; }" : "=r"(a) : "l"(p));
    return a;
}
__device__ __forceinline__ uint32_t bfh(float x) {
    uint32_t u = __float_as_uint(x);
    return (u + 0x7FFFu + ((u >> 16) & 1)) & 0xFFFF0000u;
}
__device__ __forceinline__ void ldmx4(uint32_t* r, uint32_t a) {
    asm volatile("ldmatrix.sync.aligned.m8n8.x4.shared.b16 {%0,%1,%2,%3}, [%4];"
        : "=r"(r[0]), "=r"(r[1]), "=r"(r[2]), "=r"(r[3]) : "r"(a));
}
__device__ __forceinline__ void mma16816(float* d, const uint32_t* a, const uint32_t* b) {
    asm volatile("mma.sync.aligned.m16n8k16.row.col.f32.bf16.bf16.f32 "
        "{%0,%1,%2,%3}, {%4,%5,%6,%7}, {%8,%9}, {%0,%1,%2,%3};"
        : "+f"(d[0]), "+f"(d[1]), "+f"(d[2]), "+f"(d[3])
        : "r"(a[0]), "r"(a[1]), "r"(a[2]), "r"(a[3]), "r"(b[0]), "r"(b[1]));
}
#define CP16(d, s) asm volatile("cp.async.cg.shared.global [%0], [%1], 16;" :: "r"(d), "l"(s))
#define CPCOMMIT() asm volatile("cp.async.commit_group;" ::: "memory")
template <int N>
__device__ __forceinline__ void cp_wait() {
    asm volatile("cp.async.wait_group %0;" :: "n"(N) : "memory");
}

// ===== cp.async pipelined split-bf16 warp-MMA GEMM: D[m][n] = sum_k A[m][k]*B[n][k] =====
// AL: al*bh pass; BL: ah*bl pass; NST: pipeline stages; MB: min blocks/SM hint
// FLG: 2=exp+colsum+bf16hi trans store(E) | 16=QKV mixed | 32=row split store(AV)
//      | 8=fp32 row store | 64=skip lo-plane store in QKV Q/K epilogue
template <int AL, int BL, int NST, int MB, int FLG>
__global__ void __launch_bounds__(256, MB) mma_k(
    const ush* __restrict__ Ah, const ush* __restrict__ Al,
    const ush* __restrict__ Bh, const ush* __restrict__ Bl,
    float* __restrict__ Cf, ush* __restrict__ Ch, ush* __restrict__ Cl,
    const float* __restrict__ bias, float* __restrict__ part,
    int lda, int ldb, int ldc, int K,
    long long bsA, long long bsB, long long bsC,
    int zshA, int zxB, int zmC, int cshift,
    long long bsC2, int ldc2, int bstride)
{
    constexpr int BHO  = (1 + AL) * PL;          // B-hi plane offset in stage
    constexpr int STGB = (2 + AL + BL) * PL;     // stage bytes
    extern __shared__ char sm[];
    float* smf = (float*)sm;
    uint32_t su = smem_u32(sm);
    int tid = threadIdx.x, lane = tid & 31, w = tid >> 5;
    int wm = w & 3, wn = w >> 2;
    int m0 = blockIdx.y * 128, n0 = blockIdx.x * 128;
    long long z = blockIdx.z;

    const ush* pAh = Ah + (z >> zshA) * bsA;
    const ush* pAl = Al + (z >> zshA) * bsA;
    long long zB = z ^ zxB;
    const ush* pBh = Bh + zB * bsB;
    const ush* pBl = Bl + zB * bsB;
    long long zC = z & zmC;
    int colofs = (int)(z >> 2) * cshift;

    float acc[2][8][4];
#pragma unroll
    for (int a = 0; a < 2; a++)
#pragma unroll
        for (int b = 0; b < 8; b++)
#pragma unroll
            for (int c = 0; c < 4; c++) acc[a][b][c] = 0.f;

    int nch = K >> 5;

    auto cpstage = [&](int ch) {
        uint32_t dst = su + (ch % NST) * STGB;
        int k0 = ch << 5;
#pragma unroll
        for (int i = 0; i < 2; i++) {
            int idx = tid + (i << 8);
            int r = idx >> 2, c8 = (idx & 3) << 3;
            uint32_t doff = r * 80 + (c8 << 1);
            CP16(dst + doff,       pAh + (long long)(m0 + r) * lda + k0 + c8);
            if (AL)
                CP16(dst + PL + doff,  pAl + (long long)(m0 + r) * lda + k0 + c8);
            CP16(dst + BHO + doff, pBh + (long long)(n0 + r) * ldb + k0 + c8);
            if (BL)
                CP16(dst + BHO + PL + doff, pBl + (long long)(n0 + r) * ldb + k0 + c8);
        }
    };
    auto consume = [&](int ch) {
        uint32_t sst = su + (ch % NST) * STGB;
#pragma unroll
        for (int kk = 0; kk < 32; kk += 16) {
            uint32_t ah[2][4], al[2][4], bh[4][4], bl[4][4];
            int rA = (lane & 7) + ((lane >> 3) & 1) * 8;
            int kA = kk + (lane >> 4) * 8;
#pragma unroll
            for (int mt = 0; mt < 2; mt++) {
                uint32_t ad = sst + (wm * 32 + mt * 16 + rA) * 80 + kA * 2;
                ldmx4(ah[mt], ad);
                if (AL) ldmx4(al[mt], ad + PL);
            }
            int rB = (lane & 7) + (lane >> 4) * 8;
            int kB = kk + ((lane >> 3) & 1) * 8;
#pragma unroll
            for (int nt = 0; nt < 4; nt++) {
                uint32_t bd = sst + BHO + (wn * 64 + nt * 16 + rB) * 80 + kB * 2;
                ldmx4(bh[nt], bd);
                if (BL) ldmx4(bl[nt], bd + PL);
            }
#pragma unroll
            for (int mt = 0; mt < 2; mt++)
#pragma unroll
                for (int nt = 0; nt < 8; nt++) {
                    const uint32_t* ph = &bh[nt >> 1][(nt & 1) * 2];
                    const uint32_t* pl = &bl[nt >> 1][(nt & 1) * 2];
                    mma16816(acc[mt][nt], ah[mt], ph);
                    if (BL) mma16816(acc[mt][nt], ah[mt], pl);
                    if (AL) mma16816(acc[mt][nt], al[mt], ph);
                }
        }
    };

#pragma unroll
    for (int s = 0; s < NST - 1; s++) { cpstage(s); CPCOMMIT(); }
    cp_wait<NST - 2>();
    __syncthreads();
    for (int ch = 0; ch < nch; ch++) {
        consume(ch);
        __syncthreads();
        if (ch + NST - 1 < nch) cpstage(ch + NST - 1);
        CPCOMMIT();
        if (ch + 1 < nch) { cp_wait<NST - 2>(); __syncthreads(); }
    }

    // acc -> smem fp32 tile (stride 130)
    __syncthreads();
#pragma unroll
    for (int mt = 0; mt < 2; mt++)
#pragma unroll
        for (int nt = 0; nt < 8; nt++) {
            int r = wm * 32 + mt * 16 + (lane >> 2);
            int c = wn * 64 + nt * 8 + 2 * (lane & 3);
            *(float2*)&smf[r * 130 + c]       = make_float2(acc[mt][nt][0], acc[mt][nt][1]);
            *(float2*)&smf[(r + 8) * 130 + c] = make_float2(acc[mt][nt][2], acc[mt][nt][3]);
        }
    __syncthreads();

    if (FLG & 2) {               // S: exp + colsum + bf16-hi trans store
        int r = tid & 127, hf = tid >> 7;
        float lsum = 0.f;
        ush* co = Ch + zC * bsC;
        int j0 = hf * 64;
#pragma unroll 4
        for (int j = j0; j < j0 + 64; j++) {
            float e = __expf(fminf(smf[r * 130 + j], 60.f));
            lsum += e;
            co[(long long)(n0 + j) * ldc + m0 + r] = (ush)(bfh(e) >> 16);
        }
        part[((long long)blockIdx.x * 2 + hf) * (8 * HW) + z * HW + m0 + r] = lsum;
    } else if (FLG & 32) {       // AV: row split store
        ush* ch2 = Ch + zC * bsC;
        ush* cl2 = Cl + zC * bsC;
#pragma unroll 4
        for (int i = tid; i < 16384; i += 256) {
            int r = i >> 7, c = i & 127;
            float v = smf[r * 130 + c];
            long long o = (long long)(m0 + r) * ldc + colofs + n0 + c;
            uint32_t hb = bfh(v);
            ch2[o] = (ush)(hb >> 16);
            cl2[o] = (ush)(bfh(v - __int_as_float(hb)) >> 16);
        }
    } else if (FLG & 16) {       // QKV mixed
        if (blockIdx.y == 2) {   // V rows: fp32 row store
            float* cf = Cf + z * bsC2;
#pragma unroll 4
            for (int i = tid; i < 16384; i += 256) {
                int r = i >> 7, c = i & 127;
                cf[(long long)r * ldc2 + n0 + c] =
                    smf[r * 130 + c] + bias[(z >> zshA) * bstride + m0 + r];
            }
        } else {                 // Q/K: trans store + bias (hi, optional lo)
            int r = tid & 127, hf = tid >> 7;
            float bb = bias[(z >> zshA) * bstride + m0 + r];
            ush* ch2 = Ch + zC * bsC;
            ush* cl2 = Cl + zC * bsC;
            int j0 = hf * 64;
#pragma unroll 4
            for (int j = j0; j < j0 + 64; j++) {
                float v = smf[r * 130 + j] + bb;
                long long o = (long long)(n0 + j) * ldc + m0 + r;
                uint32_t hb = bfh(v);
                ch2[o] = (ush)(hb >> 16);
                if (!(FLG & 64))
                    cl2[o] = (ush)(bfh(v - __int_as_float(hb)) >> 16);
            }
        }
    } else {                     // fp32 row store + bias
        float* cf = Cf + zC * bsC;
#pragma unroll 4
        for (int i = tid; i < 16384; i += 256) {
            int r = i >> 7, c = i & 127;
            cf[(long long)(m0 + r) * ldc + n0 + c] =
                smf[r * 130 + c] + bias[(z >> zshA) * bstride + m0 + r];
        }
    }
}

// ---- BN(eval) + depthwise 3x3 SAME, both branches in one launch ----
__global__ void __launch_bounds__(256) bn_dw_kernel(
    const float* __restrict__ x0, const float* __restrict__ x1,
    const float* __restrict__ g0, const float* __restrict__ g1,
    const float* __restrict__ b0, const float* __restrict__ b1,
    const float* __restrict__ m0p, const float* __restrict__ m1p,
    const float* __restrict__ v0, const float* __restrict__ v1,
    const float* __restrict__ w0p, const float* __restrict__ w1p,
    const float* __restrict__ d0, const float* __restrict__ d1,
    float* __restrict__ y)
{
    __shared__ float tile[66 * 66];
    int bc = blockIdx.x, sel = bc >> 9, lc = bc & 511, c = bc & 127;
    const float* xp = (sel ? x1 : x0) + (size_t)lc * HW;
    const float* g = sel ? g1 : g0; const float* b = sel ? b1 : b0;
    const float* m = sel ? m1p : m0p; const float* v = sel ? v1 : v0;
    const float* wdw = sel ? w1p : w0p; const float* bdw = sel ? d1 : d0;
    float sc = g[c] * rsqrtf(v[c] + EPSf), sh = b[c] - m[c] * sc;
    for (int i = threadIdx.x; i < 66 * 66; i += 256) {
        int r = i / 66 - 1, cl = i % 66 - 1;
        tile[i] = (r >= 0 && r < 64 && cl >= 0 && cl < 64) ? xp[r * 64 + cl] * sc + sh : 0.f;
    }
    __syncthreads();
    float w0 = wdw[c*9], w1 = wdw[c*9+1], w2 = wdw[c*9+2], w3 = wdw[c*9+3], w4 = wdw[c*9+4];
    float w5 = wdw[c*9+5], w6 = wdw[c*9+6], w7 = wdw[c*9+7], w8 = wdw[c*9+8], bb = bdw[c];
    float* yp = y + (size_t)bc * HW;
    for (int i = threadIdx.x; i < HW; i += 256) {
        const float* t = &tile[(i >> 6) * 66 + (i & 63)];
        yp[i] = bb + t[0]*w0 + t[1]*w1 + t[2]*w2 + t[66]*w3 + t[67]*w4 + t[68]*w5
                   + t[132]*w6 + t[133]*w7 + t[134]*w8;
    }
}

// ---- transpose [128][HW] -> split bf16 [HW][ldd] ----
__global__ void __launch_bounds__(256) tsplit_k(
    const float* __restrict__ src, ush* __restrict__ dh, ush* __restrict__ dl,
    int ldd, long long bsS, long long bsD)
{
    __shared__ float t[32][33];
    src += blockIdx.z * bsS; dh += blockIdx.z * bsD; dl += blockIdx.z * bsD;
    int p0 = blockIdx.x * 32, c0 = blockIdx.y * 32;
    int x = threadIdx.x & 31, y = threadIdx.x >> 5;
#pragma unroll
    for (int i = 0; i < 32; i += 8) t[y + i][x] = src[(long long)(c0 + y + i) * HW + p0 + x];
    __syncthreads();
#pragma unroll
    for (int i = 0; i < 32; i += 8) {
        float v = t[x][y + i];
        long long o = (long long)(p0 + y + i) * ldd + c0 + x;
        uint32_t hb = bfh(v);
        dh[o] = (ush)(hb >> 16);
        dl[o] = (ush)(bfh(v - __int_as_float(hb)) >> 16);
    }
}

// ---- pack stacked QKV weights [2][384][128] split + bias [2][384] ----
__global__ void __launch_bounds__(256) pack_wqkv(
    const float* wq1, const float* wk1, const float* wv1,
    const float* wq2, const float* wk2, const float* wv2,
    const float* bq1, const float* bk1, const float* bv1,
    const float* bq2, const float* bk2, const float* bv2,
    ush* wAh, ush* wAl, float* bqkv)
{
    int i = blockIdx.x * 256 + threadIdx.x;   // 98304
    if (i >= 2 * 384 * 128) return;
    int br = i / 49152, rem = i % 49152, r = rem >> 7, c = rem & 127;
    const float* w; const float* bs;
    if (br == 0) { w = r < 128 ? wq1 : r < 256 ? wk1 : wv1; bs = r < 128 ? bq1 : r < 256 ? bk1 : bv1; }
    else         { w = r < 128 ? wq2 : r < 256 ? wk2 : wv2; bs = r < 128 ? bq2 : r < 256 ? bk2 : bv2; }
    float v = w[(r & 127) * 128 + c];
    uint32_t hb = bfh(v);
    wAh[i] = (ush)(hb >> 16);
    wAl[i] = (ush)(bfh(v - __int_as_float(hb)) >> 16);
    if (c == 0) bqkv[br * 384 + r] = bs[r & 127];
}

// ---- reduce 64 partial colsums -> reciprocal ----
__global__ void __launch_bounds__(256) rcpsum(const float* __restrict__ part, float* __restrict__ sums)
{
    int i = blockIdx.x * 256 + threadIdx.x;    // 32768
    float s = 0.f;
#pragma unroll
    for (int k = 0; k < 64; k++) s += part[(long long)k * 32768 + i];
    sums[i] = 1.f / s;
}

// ---- fold rs into V, bf16-hi only ----
__global__ void __launch_bounds__(256) vscale(
    const float4* __restrict__ v, const float4* __restrict__ rs4,
    ush* __restrict__ vh)
{
    int i = blockIdx.x * 256 + threadIdx.x;    // 1,048,576 float4
    int n4 = i & 1023, tb = i >> 17;
    float4 a = v[i], r = rs4[((tb ^ 4) << 10) + n4];
    a.x *= r.x; a.y *= r.y; a.z *= r.z; a.w *= r.w;
    uint32_t h0 = bfh(a.x), h1 = bfh(a.y), h2 = bfh(a.z), h3 = bfh(a.w);
    ((uint2*)vh)[i] = make_uint2((h0 >> 16) | h1, (h2 >> 16) | h3);
}

// ---- pack fused output weight (split bf16) + bias ----
__global__ void __launch_bounds__(256) packw(
    const float* __restrict__ wp, const float* __restrict__ bp,
    const float* __restrict__ w1, const float* __restrict__ b1,
    const float* __restrict__ w2, const float* __restrict__ b2,
    ush* __restrict__ wh, ush* __restrict__ wl, float* __restrict__ bc)
{
    int i = blockIdx.x * 256 + threadIdx.x;
    if (i >= OUTC * 512) return;
    int o = i >> 9, k = i & 511;
    float v = (k < 256) ? wp[o * 256 + k] : (k < 384) ? w1[o * 128 + k - 256] : w2[o * 128 + k - 384];
    uint32_t hb = bfh(v);
    wh[i] = (ush)(hb >> 16);
    wl[i] = (ush)(bfh(v - __int_as_float(hb)) >> 16);
    if (k == 0) bc[o] = bp[o] + b1[o] + b2[o];
}

extern "C" void kernel_launch(void* const* d_in, const int* in_sizes, int n_in,
                              void* d_out, int out_size)
{
    const float *F_i = (const float*)d_in[0], *F_w = (const float*)d_in[1];
    const float *bn1g = (const float*)d_in[2], *bn1b = (const float*)d_in[3];
    const float *bn1m = (const float*)d_in[4], *bn1v = (const float*)d_in[5];
    const float *bn2g = (const float*)d_in[6], *bn2b = (const float*)d_in[7];
    const float *bn2m = (const float*)d_in[8], *bn2v = (const float*)d_in[9];
    const float *wq1 = (const float*)d_in[10], *bq1 = (const float*)d_in[11];
    const float *wk1 = (const float*)d_in[12], *bk1 = (const float*)d_in[13];
    const float *wv1 = (const float*)d_in[14], *bv1 = (const float*)d_in[15];
    const float *wq2 = (const float*)d_in[16], *bq2 = (const float*)d_in[17];
    const float *wk2 = (const float*)d_in[18], *bk2 = (const float*)d_in[19];
    const float *wv2 = (const float*)d_in[20], *bv2 = (const float*)d_in[21];
    const float *wd1 = (const float*)d_in[22], *bd1 = (const float*)d_in[23];
    const float *wd2 = (const float*)d_in[24], *bd2 = (const float*)d_in[25];
    const float *wpj = (const float*)d_in[26], *bpj = (const float*)d_in[27];
    const float *wr1 = (const float*)d_in[28], *br1 = (const float*)d_in[29];
    const float *wr2 = (const float*)d_in[30], *br2 = (const float*)d_in[31];

    float *dw, *v, *part, *sum, *bqkv, *bc;
    ush *dwTh, *dwTl, *wAh, *wAl, *qTh, *qTl, *vh, *Eh, *xTh, *xTl, *wch, *wcl;
    cudaGetSymbolAddress((void**)&dw, g_dw);
    cudaGetSymbolAddress((void**)&dwTh, g_dwTh); cudaGetSymbolAddress((void**)&dwTl, g_dwTl);
    cudaGetSymbolAddress((void**)&wAh, g_wAh);   cudaGetSymbolAddress((void**)&wAl, g_wAl);
    cudaGetSymbolAddress((void**)&bqkv, g_bqkv);
    cudaGetSymbolAddress((void**)&qTh, g_qkvTh); cudaGetSymbolAddress((void**)&qTl, g_qkvTl);
    cudaGetSymbolAddress((void**)&v, g_v);
    cudaGetSymbolAddress((void**)&vh, g_vh);
    cudaGetSymbolAddress((void**)&Eh, g_Eh);
    cudaGetSymbolAddress((void**)&part, g_part); cudaGetSymbolAddress((void**)&sum, g_sum);
    cudaGetSymbolAddress((void**)&xTh, g_xTh);   cudaGetSymbolAddress((void**)&xTl, g_xTl);
    cudaGetSymbolAddress((void**)&wch, g_wch);   cudaGetSymbolAddress((void**)&wcl, g_wcl);
    cudaGetSymbolAddress((void**)&bc, g_bcat);

    // smem sizes: epilogue tile needs 128*130*4 = 66560 B minimum
    const int SM_QKV = 3 * 3 * PL;      // 92160  (3 planes, 3 stages) -> 2 CTA/SM
    const int SM_SAV = 4 * 2 * PL;      // 81920  (2 planes, 4 stages) -> 2 CTA/SM
    const int SM_FIN = 4 * 4 * PL;      // 163840 (4 planes, 4 stages) -> 1 CTA/SM

    cudaFuncSetAttribute(mma_k<0,1,3,2,80>, cudaFuncAttributeMaxDynamicSharedMemorySize, SM_QKV);
    cudaFuncSetAttribute(mma_k<0,0,4,2,2>,  cudaFuncAttributeMaxDynamicSharedMemorySize, SM_SAV);
    cudaFuncSetAttribute(mma_k<0,0,4,2,32>, cudaFuncAttributeMaxDynamicSharedMemorySize, SM_SAV);
    cudaFuncSetAttribute(mma_k<1,1,4,1,8>,  cudaFuncAttributeMaxDynamicSharedMemorySize, SM_FIN);

    const long long TT = (long long)HW * Cc;            // 524288
    const long long TT384 = (long long)HW * 384;        // 1572864
    const long long SS = (long long)HW * HW;
    const long long XS = (long long)HW * 512;

    pack_wqkv<<<384, 256>>>(wq1, wk1, wv1, wq2, wk2, wv2,
                            bq1, bk1, bv1, bq2, bk2, bv2, wAh, wAl, bqkv);
    packw<<<512, 256>>>(wpj, bpj, wr1, br1, wr2, br2, wch, wcl, bc);
    bn_dw_kernel<<<1024, 256>>>(F_i, F_w, bn1g, bn2g, bn1b, bn2b, bn1m, bn2m,
                                bn1v, bn2v, wd1, wd2, bd1, bd2, dw);
    tsplit_k<<<dim3(128, 4, 8), 256>>>(dw, dwTh, dwTl, 128, TT, TT);
    tsplit_k<<<dim3(128, 4, 4), 256>>>(F_i, xTh + 256, xTl + 256, 512, TT, XS);
    tsplit_k<<<dim3(128, 4, 4), 256>>>(F_w, xTh + 384, xTl + 384, 512, TT, XS);

    // QKV merged: M=384 (Q|K|V), N=4096, K=128, z = branch*4+batch
    // 2-pass (wh*xh + wh*xl), Q/K store hi plane only
    mma_k<0,1,3,2,80><<<dim3(32, 3, 8), 256, SM_QKV>>>(
        wAh, wAl, dwTh, dwTl, v, qTh, qTl, bqkv, 0,
        128, 128, 384, 128, 49152, TT, TT384,
        2, 0, 255, 0, TT, HW, 384);

    // S merged: z = attn*4+batch; A=Q hi (own branch), B=K hi (other branch)  (1-pass)
    mma_k<0,0,4,2,2><<<dim3(32, 32, 8), 256, SM_SAV>>>(
        qTh, qTh, qTh + 128, qTh + 128, 0, Eh, 0, 0, part,
        384, 384, HW, 128, TT384, TT384, SS,
        0, 4, 255, 0, 0, 0, 0);

    rcpsum<<<128, 256>>>(part, sum);
    vscale<<<4096, 256>>>((const float4*)v, (const float4*)sum, vh);

    // AV merged (flipped): D[m][c] = sum_n Eh[m][n]*Vh[c][n]; M=4096, N=128, K=4096  (1-pass)
    mma_k<0,0,4,2,32><<<dim3(1, 32, 8), 256, SM_SAV>>>(
        Eh, Eh, vh, vh, 0, xTh, xTl, 0, 0,
        HW, HW, 512, HW, SS, TT, XS,
        0, 4, 3, 128, 0, 0, 0);

    // out = wcat @ xT^T + bcat : M=256, N=4096, K=512  (3-pass)
    mma_k<1,1,4,1,8><<<dim3(32, 2, 4), 256, SM_FIN>>>(
        wch, wcl, xTh, xTl, (float*)d_out, 0, 0, bc, 0,
        512, 512, HW, 512, 0, XS, (long long)OUTC * HW,
        0, 0, 255, 0, 0, 0, 0);
}

// round 10
// speedup vs baseline: 5.7854x; 1.0618x over previous
#include <cuda_runtime.h>
#include <cstdint>
#include <math.h>

typedef unsigned short ush;
#define HW 4096
#define Cc 128
#define Bn 4
#define OUTC 256
#define EPSf 1e-5f
#define PL 10240

// ---------------- scratch ----------------
__device__ float g_dw [2*Bn*Cc*HW];
__device__ ush   g_dwTh[2*Bn*Cc*HW];
__device__ ush   g_wAh[2*384*128],   g_wAl[2*384*128];
__device__ float g_bqkv[2*384];
__device__ ush   g_qkvTh[2ll*Bn*HW*384], g_qkvTl[2ll*Bn*HW*384];  // [br][B][pix][Q|K|V]
__device__ float g_v [2*Bn*Cc*HW];
__device__ ush   g_vh[2*Bn*Cc*HW];
__device__ ush   g_Eh[134217728];                 // [attn][B][key][query] bf16
__device__ float g_part[64*8*HW];
__device__ float g_sum[8*HW];
__device__ ush   g_xTh[Bn*HW*512], g_xTl[Bn*HW*512];
__device__ ush   g_wch[OUTC*512], g_wcl[OUTC*512];
__device__ float g_bcat[OUTC];

__device__ __forceinline__ uint32_t smem_u32(const void* p) {
    uint32_t a;
    asm("{ .reg .u64 t; cvta.to.shared.u64 t, %1; cvt.u32.u64 %0, t; }" : "=r"(a) : "l"(p));
    return a;
}
__device__ __forceinline__ uint32_t bfh(float x) {
    uint32_t u = __float_as_uint(x);
    return (u + 0x7FFFu + ((u >> 16) & 1)) & 0xFFFF0000u;
}
__device__ __forceinline__ void ldmx4(uint32_t* r, uint32_t a) {
    asm volatile("ldmatrix.sync.aligned.m8n8.x4.shared.b16 {%0,%1,%2,%3}, [%4];"
        : "=r"(r[0]), "=r"(r[1]), "=r"(r[2]), "=r"(r[3]) : "r"(a));
}
__device__ __forceinline__ void mma16816(float* d, const uint32_t* a, const uint32_t* b) {
    asm volatile("mma.sync.aligned.m16n8k16.row.col.f32.bf16.bf16.f32 "
        "{%0,%1,%2,%3}, {%4,%5,%6,%7}, {%8,%9}, {%0,%1,%2,%3};"
        : "+f"(d[0]), "+f"(d[1]), "+f"(d[2]), "+f"(d[3])
        : "r"(a[0]), "r"(a[1]), "r"(a[2]), "r"(a[3]), "r"(b[0]), "r"(b[1]));
}
#define CP16(d, s) asm volatile("cp.async.cg.shared.global [%0], [%1], 16;" :: "r"(d), "l"(s))
#define CPCOMMIT() asm volatile("cp.async.commit_group;" ::: "memory")
template <int N>
__device__ __forceinline__ void cp_wait() {
    asm volatile("cp.async.wait_group %0;" :: "n"(N) : "memory");
}

// ===== cp.async pipelined split-bf16 warp-MMA GEMM: D[m][n] = sum_k A[m][k]*B[n][k] =====
// AL: al*bh pass; BL: ah*bl pass; NST: pipeline stages; MB: min blocks/SM
// FLG: 2=exp+colsum+bf16hi trans store(E) | 16=QKV mixed | 32=row split store(AV)
//      | 8=fp32 row store | 64=skip lo-plane store in QKV Q/K epilogue
template <int AL, int BL, int NST, int MB, int FLG>
__global__ void __launch_bounds__(256, MB) mma_k(
    const ush* __restrict__ Ah, const ush* __restrict__ Al,
    const ush* __restrict__ Bh, const ush* __restrict__ Bl,
    float* __restrict__ Cf, ush* __restrict__ Ch, ush* __restrict__ Cl,
    const float* __restrict__ bias, float* __restrict__ part,
    int lda, int ldb, int ldc, int K,
    long long bsA, long long bsB, long long bsC,
    int zshA, int zxB, int zmC, int cshift,
    long long bsC2, int ldc2, int bstride)
{
    constexpr int BHO  = (1 + AL) * PL;          // B-hi plane offset in stage
    constexpr int STGB = (2 + AL + BL) * PL;     // stage bytes
    extern __shared__ char sm[];
    float* smf = (float*)sm;
    uint32_t su = smem_u32(sm);
    int tid = threadIdx.x, lane = tid & 31, w = tid >> 5;
    int wm = w & 3, wn = w >> 2;
    int m0 = blockIdx.y * 128, n0 = blockIdx.x * 128;
    long long z = blockIdx.z;

    const ush* pAh = Ah + (z >> zshA) * bsA;
    const ush* pAl = Al + (z >> zshA) * bsA;
    long long zB = z ^ zxB;
    const ush* pBh = Bh + zB * bsB;
    const ush* pBl = Bl + zB * bsB;
    long long zC = z & zmC;
    int colofs = (int)(z >> 2) * cshift;

    float acc[2][8][4];
#pragma unroll
    for (int a = 0; a < 2; a++)
#pragma unroll
        for (int b = 0; b < 8; b++)
#pragma unroll
            for (int c = 0; c < 4; c++) acc[a][b][c] = 0.f;

    int nch = K >> 5;

    auto cpstage = [&](int ch) {
        uint32_t dst = su + (ch % NST) * STGB;
        int k0 = ch << 5;
#pragma unroll
        for (int i = 0; i < 2; i++) {
            int idx = tid + (i << 8);
            int r = idx >> 2, c8 = (idx & 3) << 3;
            uint32_t doff = r * 80 + (c8 << 1);
            CP16(dst + doff,       pAh + (long long)(m0 + r) * lda + k0 + c8);
            if (AL)
                CP16(dst + PL + doff,  pAl + (long long)(m0 + r) * lda + k0 + c8);
            CP16(dst + BHO + doff, pBh + (long long)(n0 + r) * ldb + k0 + c8);
            if (BL)
                CP16(dst + BHO + PL + doff, pBl + (long long)(n0 + r) * ldb + k0 + c8);
        }
    };
    auto consume = [&](int ch) {
        uint32_t sst = su + (ch % NST) * STGB;
#pragma unroll
        for (int kk = 0; kk < 32; kk += 16) {
            uint32_t ah[2][4], al[2][4], bh[4][4], bl[4][4];
            int rA = (lane & 7) + ((lane >> 3) & 1) * 8;
            int kA = kk + (lane >> 4) * 8;
#pragma unroll
            for (int mt = 0; mt < 2; mt++) {
                uint32_t ad = sst + (wm * 32 + mt * 16 + rA) * 80 + kA * 2;
                ldmx4(ah[mt], ad);
                if (AL) ldmx4(al[mt], ad + PL);
            }
            int rB = (lane & 7) + (lane >> 4) * 8;
            int kB = kk + ((lane >> 3) & 1) * 8;
#pragma unroll
            for (int nt = 0; nt < 4; nt++) {
                uint32_t bd = sst + BHO + (wn * 64 + nt * 16 + rB) * 80 + kB * 2;
                ldmx4(bh[nt], bd);
                if (BL) ldmx4(bl[nt], bd + PL);
            }
#pragma unroll
            for (int mt = 0; mt < 2; mt++)
#pragma unroll
                for (int nt = 0; nt < 8; nt++) {
                    const uint32_t* ph = &bh[nt >> 1][(nt & 1) * 2];
                    const uint32_t* pl = &bl[nt >> 1][(nt & 1) * 2];
                    mma16816(acc[mt][nt], ah[mt], ph);
                    if (BL) mma16816(acc[mt][nt], ah[mt], pl);
                    if (AL) mma16816(acc[mt][nt], al[mt], ph);
                }
        }
    };

    // single-barrier pipeline: cpstage(ch+NST-1) writes stage (ch-1)%NST,
    // already retired by the barrier at the top of this iteration.
#pragma unroll
    for (int s = 0; s < NST - 1; s++) { cpstage(s); CPCOMMIT(); }
    for (int ch = 0; ch < nch; ch++) {
        cp_wait<NST - 2>();
        __syncthreads();
        consume(ch);
        if (ch + NST - 1 < nch) cpstage(ch + NST - 1);
        CPCOMMIT();
    }

    // acc -> smem fp32 tile (stride 130)
    __syncthreads();
#pragma unroll
    for (int mt = 0; mt < 2; mt++)
#pragma unroll
        for (int nt = 0; nt < 8; nt++) {
            int r = wm * 32 + mt * 16 + (lane >> 2);
            int c = wn * 64 + nt * 8 + 2 * (lane & 3);
            *(float2*)&smf[r * 130 + c]       = make_float2(acc[mt][nt][0], acc[mt][nt][1]);
            *(float2*)&smf[(r + 8) * 130 + c] = make_float2(acc[mt][nt][2], acc[mt][nt][3]);
        }
    __syncthreads();

    if (FLG & 2) {               // S: exp + colsum + bf16-hi trans store
        int r = tid & 127, hf = tid >> 7;
        float lsum = 0.f;
        ush* co = Ch + zC * bsC;
        int j0 = hf * 64;
#pragma unroll 4
        for (int j = j0; j < j0 + 64; j++) {
            float e = __expf(fminf(smf[r * 130 + j], 60.f));
            lsum += e;
            co[(long long)(n0 + j) * ldc + m0 + r] = (ush)(bfh(e) >> 16);
        }
        part[((long long)blockIdx.x * 2 + hf) * (8 * HW) + z * HW + m0 + r] = lsum;
    } else if (FLG & 32) {       // AV: row split store
        ush* ch2 = Ch + zC * bsC;
        ush* cl2 = Cl + zC * bsC;
#pragma unroll 4
        for (int i = tid; i < 16384; i += 256) {
            int r = i >> 7, c = i & 127;
            float v = smf[r * 130 + c];
            long long o = (long long)(m0 + r) * ldc + colofs + n0 + c;
            uint32_t hb = bfh(v);
            ch2[o] = (ush)(hb >> 16);
            cl2[o] = (ush)(bfh(v - __int_as_float(hb)) >> 16);
        }
    } else if (FLG & 16) {       // QKV mixed
        if (blockIdx.y == 2) {   // V rows: fp32 row store
            float* cf = Cf + z * bsC2;
#pragma unroll 4
            for (int i = tid; i < 16384; i += 256) {
                int r = i >> 7, c = i & 127;
                cf[(long long)r * ldc2 + n0 + c] =
                    smf[r * 130 + c] + bias[(z >> zshA) * bstride + m0 + r];
            }
        } else {                 // Q/K: trans store + bias (hi, optional lo)
            int r = tid & 127, hf = tid >> 7;
            float bb = bias[(z >> zshA) * bstride + m0 + r];
            ush* ch2 = Ch + zC * bsC;
            ush* cl2 = Cl + zC * bsC;
            int j0 = hf * 64;
#pragma unroll 4
            for (int j = j0; j < j0 + 64; j++) {
                float v = smf[r * 130 + j] + bb;
                long long o = (long long)(n0 + j) * ldc + m0 + r;
                uint32_t hb = bfh(v);
                ch2[o] = (ush)(hb >> 16);
                if (!(FLG & 64))
                    cl2[o] = (ush)(bfh(v - __int_as_float(hb)) >> 16);
            }
        }
    } else {                     // fp32 row store + bias
        float* cf = Cf + zC * bsC;
#pragma unroll 4
        for (int i = tid; i < 16384; i += 256) {
            int r = i >> 7, c = i & 127;
            cf[(long long)(m0 + r) * ldc + n0 + c] =
                smf[r * 130 + c] + bias[(z >> zshA) * bstride + m0 + r];
        }
    }
}

// ---- BN(eval) + depthwise 3x3 SAME, both branches in one launch ----
__global__ void __launch_bounds__(256) bn_dw_kernel(
    const float* __restrict__ x0, const float* __restrict__ x1,
    const float* __restrict__ g0, const float* __restrict__ g1,
    const float* __restrict__ b0, const float* __restrict__ b1,
    const float* __restrict__ m0p, const float* __restrict__ m1p,
    const float* __restrict__ v0, const float* __restrict__ v1,
    const float* __restrict__ w0p, const float* __restrict__ w1p,
    const float* __restrict__ d0, const float* __restrict__ d1,
    float* __restrict__ y)
{
    __shared__ float tile[66 * 66];
    int bc = blockIdx.x, sel = bc >> 9, lc = bc & 511, c = bc & 127;
    const float* xp = (sel ? x1 : x0) + (size_t)lc * HW;
    const float* g = sel ? g1 : g0; const float* b = sel ? b1 : b0;
    const float* m = sel ? m1p : m0p; const float* v = sel ? v1 : v0;
    const float* wdw = sel ? w1p : w0p; const float* bdw = sel ? d1 : d0;
    float sc = g[c] * rsqrtf(v[c] + EPSf), sh = b[c] - m[c] * sc;
    for (int i = threadIdx.x; i < 66 * 66; i += 256) {
        int r = i / 66 - 1, cl = i % 66 - 1;
        tile[i] = (r >= 0 && r < 64 && cl >= 0 && cl < 64) ? xp[r * 64 + cl] * sc + sh : 0.f;
    }
    __syncthreads();
    float w0 = wdw[c*9], w1 = wdw[c*9+1], w2 = wdw[c*9+2], w3 = wdw[c*9+3], w4 = wdw[c*9+4];
    float w5 = wdw[c*9+5], w6 = wdw[c*9+6], w7 = wdw[c*9+7], w8 = wdw[c*9+8], bb = bdw[c];
    float* yp = y + (size_t)bc * HW;
    for (int i = threadIdx.x; i < HW; i += 256) {
        const float* t = &tile[(i >> 6) * 66 + (i & 63)];
        yp[i] = bb + t[0]*w0 + t[1]*w1 + t[2]*w2 + t[66]*w3 + t[67]*w4 + t[68]*w5
                   + t[132]*w6 + t[133]*w7 + t[134]*w8;
    }
}

// ---- transpose [128][HW] -> split bf16 [HW][ldd]; WL=0 skips lo plane ----
template <int WL>
__global__ void __launch_bounds__(256) tsplit_k(
    const float* __restrict__ src, ush* __restrict__ dh, ush* __restrict__ dl,
    int ldd, long long bsS, long long bsD)
{
    __shared__ float t[32][33];
    src += blockIdx.z * bsS; dh += blockIdx.z * bsD;
    if (WL) dl += blockIdx.z * bsD;
    int p0 = blockIdx.x * 32, c0 = blockIdx.y * 32;
    int x = threadIdx.x & 31, y = threadIdx.x >> 5;
#pragma unroll
    for (int i = 0; i < 32; i += 8) t[y + i][x] = src[(long long)(c0 + y + i) * HW + p0 + x];
    __syncthreads();
#pragma unroll
    for (int i = 0; i < 32; i += 8) {
        float v = t[x][y + i];
        long long o = (long long)(p0 + y + i) * ldd + c0 + x;
        uint32_t hb = bfh(v);
        dh[o] = (ush)(hb >> 16);
        if (WL) dl[o] = (ush)(bfh(v - __int_as_float(hb)) >> 16);
    }
}

// ---- pack stacked QKV weights [2][384][128] split + bias [2][384] ----
__global__ void __launch_bounds__(256) pack_wqkv(
    const float* wq1, const float* wk1, const float* wv1,
    const float* wq2, const float* wk2, const float* wv2,
    const float* bq1, const float* bk1, const float* bv1,
    const float* bq2, const float* bk2, const float* bv2,
    ush* wAh, ush* wAl, float* bqkv)
{
    int i = blockIdx.x * 256 + threadIdx.x;   // 98304
    if (i >= 2 * 384 * 128) return;
    int br = i / 49152, rem = i % 49152, r = rem >> 7, c = rem & 127;
    const float* w; const float* bs;
    if (br == 0) { w = r < 128 ? wq1 : r < 256 ? wk1 : wv1; bs = r < 128 ? bq1 : r < 256 ? bk1 : bv1; }
    else         { w = r < 128 ? wq2 : r < 256 ? wk2 : wv2; bs = r < 128 ? bq2 : r < 256 ? bk2 : bv2; }
    float v = w[(r & 127) * 128 + c];
    uint32_t hb = bfh(v);
    wAh[i] = (ush)(hb >> 16);
    wAl[i] = (ush)(bfh(v - __int_as_float(hb)) >> 16);
    if (c == 0) bqkv[br * 384 + r] = bs[r & 127];
}

// ---- reduce 64 partial colsums -> reciprocal ----
__global__ void __launch_bounds__(256) rcpsum(const float* __restrict__ part, float* __restrict__ sums)
{
    int i = blockIdx.x * 256 + threadIdx.x;    // 32768
    float s = 0.f;
#pragma unroll
    for (int k = 0; k < 64; k++) s += part[(long long)k * 32768 + i];
    sums[i] = 1.f / s;
}

// ---- fold rs into V, bf16-hi only ----
__global__ void __launch_bounds__(256) vscale(
    const float4* __restrict__ v, const float4* __restrict__ rs4,
    ush* __restrict__ vh)
{
    int i = blockIdx.x * 256 + threadIdx.x;    // 1,048,576 float4
    int n4 = i & 1023, tb = i >> 17;
    float4 a = v[i], r = rs4[((tb ^ 4) << 10) + n4];
    a.x *= r.x; a.y *= r.y; a.z *= r.z; a.w *= r.w;
    uint32_t h0 = bfh(a.x), h1 = bfh(a.y), h2 = bfh(a.z), h3 = bfh(a.w);
    ((uint2*)vh)[i] = make_uint2((h0 >> 16) | h1, (h2 >> 16) | h3);
}

// ---- pack fused output weight (split bf16) + bias ----
__global__ void __launch_bounds__(256) packw(
    const float* __restrict__ wp, const float* __restrict__ bp,
    const float* __restrict__ w1, const float* __restrict__ b1,
    const float* __restrict__ w2, const float* __restrict__ b2,
    ush* __restrict__ wh, ush* __restrict__ wl, float* __restrict__ bc)
{
    int i = blockIdx.x * 256 + threadIdx.x;
    if (i >= OUTC * 512) return;
    int o = i >> 9, k = i & 511;
    float v = (k < 256) ? wp[o * 256 + k] : (k < 384) ? w1[o * 128 + k - 256] : w2[o * 128 + k - 384];
    uint32_t hb = bfh(v);
    wh[i] = (ush)(hb >> 16);
    wl[i] = (ush)(bfh(v - __int_as_float(hb)) >> 16);
    if (k == 0) bc[o] = bp[o] + b1[o] + b2[o];
}

extern "C" void kernel_launch(void* const* d_in, const int* in_sizes, int n_in,
                              void* d_out, int out_size)
{
    const float *F_i = (const float*)d_in[0], *F_w = (const float*)d_in[1];
    const float *bn1g = (const float*)d_in[2], *bn1b = (const float*)d_in[3];
    const float *bn1m = (const float*)d_in[4], *bn1v = (const float*)d_in[5];
    const float *bn2g = (const float*)d_in[6], *bn2b = (const float*)d_in[7];
    const float *bn2m = (const float*)d_in[8], *bn2v = (const float*)d_in[9];
    const float *wq1 = (const float*)d_in[10], *bq1 = (const float*)d_in[11];
    const float *wk1 = (const float*)d_in[12], *bk1 = (const float*)d_in[13];
    const float *wv1 = (const float*)d_in[14], *bv1 = (const float*)d_in[15];
    const float *wq2 = (const float*)d_in[16], *bq2 = (const float*)d_in[17];
    const float *wk2 = (const float*)d_in[18], *bk2 = (const float*)d_in[19];
    const float *wv2 = (const float*)d_in[20], *bv2 = (const float*)d_in[21];
    const float *wd1 = (const float*)d_in[22], *bd1 = (const float*)d_in[23];
    const float *wd2 = (const float*)d_in[24], *bd2 = (const float*)d_in[25];
    const float *wpj = (const float*)d_in[26], *bpj = (const float*)d_in[27];
    const float *wr1 = (const float*)d_in[28], *br1 = (const float*)d_in[29];
    const float *wr2 = (const float*)d_in[30], *br2 = (const float*)d_in[31];

    float *dw, *v, *part, *sum, *bqkv, *bc;
    ush *dwTh, *wAh, *wAl, *qTh, *qTl, *vh, *Eh, *xTh, *xTl, *wch, *wcl;
    cudaGetSymbolAddress((void**)&dw, g_dw);
    cudaGetSymbolAddress((void**)&dwTh, g_dwTh);
    cudaGetSymbolAddress((void**)&wAh, g_wAh);   cudaGetSymbolAddress((void**)&wAl, g_wAl);
    cudaGetSymbolAddress((void**)&bqkv, g_bqkv);
    cudaGetSymbolAddress((void**)&qTh, g_qkvTh); cudaGetSymbolAddress((void**)&qTl, g_qkvTl);
    cudaGetSymbolAddress((void**)&v, g_v);
    cudaGetSymbolAddress((void**)&vh, g_vh);
    cudaGetSymbolAddress((void**)&Eh, g_Eh);
    cudaGetSymbolAddress((void**)&part, g_part); cudaGetSymbolAddress((void**)&sum, g_sum);
    cudaGetSymbolAddress((void**)&xTh, g_xTh);   cudaGetSymbolAddress((void**)&xTl, g_xTl);
    cudaGetSymbolAddress((void**)&wch, g_wch);   cudaGetSymbolAddress((void**)&wcl, g_wcl);
    cudaGetSymbolAddress((void**)&bc, g_bcat);

    const int SM_QKV = 4 * 2 * PL;      // 81920 (2 planes, 4 stages) -> 2 CTA/SM
    const int SM_SAV = 4 * 2 * PL;      // 81920 -> 2 CTA/SM
    const int SM_FIN = 4 * 4 * PL;      // 163840 -> 1 CTA/SM

    cudaFuncSetAttribute(mma_k<0,0,4,2,80>, cudaFuncAttributeMaxDynamicSharedMemorySize, SM_QKV);
    cudaFuncSetAttribute(mma_k<0,0,4,2,2>,  cudaFuncAttributeMaxDynamicSharedMemorySize, SM_SAV);
    cudaFuncSetAttribute(mma_k<0,0,4,2,32>, cudaFuncAttributeMaxDynamicSharedMemorySize, SM_SAV);
    cudaFuncSetAttribute(mma_k<1,1,4,1,8>,  cudaFuncAttributeMaxDynamicSharedMemorySize, SM_FIN);

    const long long TT = (long long)HW * Cc;            // 524288
    const long long TT384 = (long long)HW * 384;        // 1572864
    const long long SS = (long long)HW * HW;
    const long long XS = (long long)HW * 512;

    pack_wqkv<<<384, 256>>>(wq1, wk1, wv1, wq2, wk2, wv2,
                            bq1, bk1, bv1, bq2, bk2, bv2, wAh, wAl, bqkv);
    packw<<<512, 256>>>(wpj, bpj, wr1, br1, wr2, br2, wch, wcl, bc);
    bn_dw_kernel<<<1024, 256>>>(F_i, F_w, bn1g, bn2g, bn1b, bn2b, bn1m, bn2m,
                                bn1v, bn2v, wd1, wd2, bd1, bd2, dw);
    tsplit_k<0><<<dim3(128, 4, 8), 256>>>(dw, dwTh, nullptr, 128, TT, TT);
    tsplit_k<1><<<dim3(128, 4, 4), 256>>>(F_i, xTh + 256, xTl + 256, 512, TT, XS);
    tsplit_k<1><<<dim3(128, 4, 4), 256>>>(F_w, xTh + 384, xTl + 384, 512, TT, XS);

    // QKV merged: M=384 (Q|K|V), N=4096, K=128, z = branch*4+batch  (1-pass wh*xh)
    mma_k<0,0,4,2,80><<<dim3(32, 3, 8), 256, SM_QKV>>>(
        wAh, wAh, dwTh, dwTh, v, qTh, qTl, bqkv, 0,
        128, 128, 384, 128, 49152, TT, TT384,
        2, 0, 255, 0, TT, HW, 384);

    // S merged: z = attn*4+batch; A=Q hi (own branch), B=K hi (other branch)  (1-pass)
    mma_k<0,0,4,2,2><<<dim3(32, 32, 8), 256, SM_SAV>>>(
        qTh, qTh, qTh + 128, qTh + 128, 0, Eh, 0, 0, part,
        384, 384, HW, 128, TT384, TT384, SS,
        0, 4, 255, 0, 0, 0, 0);

    rcpsum<<<128, 256>>>(part, sum);
    vscale<<<4096, 256>>>((const float4*)v, (const float4*)sum, vh);

    // AV merged (flipped): D[m][c] = sum_n Eh[m][n]*Vh[c][n]; M=4096, N=128, K=4096  (1-pass)
    mma_k<0,0,4,2,32><<<dim3(1, 32, 8), 256, SM_SAV>>>(
        Eh, Eh, vh, vh, 0, xTh, xTl, 0, 0,
        HW, HW, 512, HW, SS, TT, XS,
        0, 4, 3, 128, 0, 0, 0);

    // out = wcat @ xT^T + bcat : M=256, N=4096, K=512  (3-pass)
    mma_k<1,1,4,1,8><<<dim3(32, 2, 4), 256, SM_FIN>>>(
        wch, wcl, xTh, xTl, (float*)d_out, 0, 0, bc, 0,
        512, 512, HW, 512, 0, XS, (long long)OUTC * HW,
        0, 0, 255, 0, 0, 0, 0);
}

// round 11
// speedup vs baseline: 6.0947x; 1.0535x over previous
#include <cuda_runtime.h>
#include <cuda_fp16.h>
#include <cstdint>
#include <math.h>

typedef unsigned short ush;
#define HW 4096
#define Cc 128
#define Bn 4
#define OUTC 256
#define EPSf 1e-5f
#define PL 10240

// ---------------- scratch ----------------
__device__ float g_dw [2*Bn*Cc*HW];
__device__ ush   g_dwTh[2*Bn*Cc*HW];
__device__ ush   g_wAh[2*384*128],   g_wAl[2*384*128];
__device__ float g_bqkv[2*384];
__device__ ush   g_qkvTh[2ll*Bn*HW*384], g_qkvTl[2ll*Bn*HW*384];  // [br][B][pix][Q|K|V]
__device__ float g_v [2*Bn*Cc*HW];
__device__ ush   g_vh[2*Bn*Cc*HW];
__device__ ush   g_Eh[134217728];                 // [attn][B][key][query] bf16
__device__ float g_part[64*8*HW];
__device__ float g_sum[8*HW];
__device__ ush   g_xTh[Bn*HW*512], g_xTl[Bn*HW*512];   // fp16 hi/lo planes
__device__ ush   g_wch[OUTC*512];                      // fp16 single plane
__device__ float g_bcat[OUTC];

__device__ __forceinline__ uint32_t smem_u32(const void* p) {
    uint32_t a;
    asm("{ .reg .u64 t; cvta.to.shared.u64 t, %1; cvt.u32.u64 %0, t; }" : "=r"(a) : "l"(p));
    return a;
}
__device__ __forceinline__ uint32_t bfh(float x) {
    uint32_t u = __float_as_uint(x);
    return (u + 0x7FFFu + ((u >> 16) & 1)) & 0xFFFF0000u;
}
__device__ __forceinline__ ush f16b(float x) {
    return __half_as_ushort(__float2half_rn(x));
}
__device__ __forceinline__ void ldmx4(uint32_t* r, uint32_t a) {
    asm volatile("ldmatrix.sync.aligned.m8n8.x4.shared.b16 {%0,%1,%2,%3}, [%4];"
        : "=r"(r[0]), "=r"(r[1]), "=r"(r[2]), "=r"(r[3]) : "r"(a));
}
__device__ __forceinline__ void mma_bf(float* d, const uint32_t* a, const uint32_t* b) {
    asm volatile("mma.sync.aligned.m16n8k16.row.col.f32.bf16.bf16.f32 "
        "{%0,%1,%2,%3}, {%4,%5,%6,%7}, {%8,%9}, {%0,%1,%2,%3};"
        : "+f"(d[0]), "+f"(d[1]), "+f"(d[2]), "+f"(d[3])
        : "r"(a[0]), "r"(a[1]), "r"(a[2]), "r"(a[3]), "r"(b[0]), "r"(b[1]));
}
__device__ __forceinline__ void mma_hf(float* d, const uint32_t* a, const uint32_t* b) {
    asm volatile("mma.sync.aligned.m16n8k16.row.col.f32.f16.f16.f32 "
        "{%0,%1,%2,%3}, {%4,%5,%6,%7}, {%8,%9}, {%0,%1,%2,%3};"
        : "+f"(d[0]), "+f"(d[1]), "+f"(d[2]), "+f"(d[3])
        : "r"(a[0]), "r"(a[1]), "r"(a[2]), "r"(a[3]), "r"(b[0]), "r"(b[1]));
}
#define CP16(d, s) asm volatile("cp.async.cg.shared.global [%0], [%1], 16;" :: "r"(d), "l"(s))
#define CPCOMMIT() asm volatile("cp.async.commit_group;" ::: "memory")
template <int N>
__device__ __forceinline__ void cp_wait() {
    asm volatile("cp.async.wait_group %0;" :: "n"(N) : "memory");
}

// ===== cp.async pipelined warp-MMA GEMM: D[m][n] = sum_k A[m][k]*B[n][k] =====
// AL: al*bh pass; BL: ah*bl pass; NST: stages; MB: min blocks/SM; H16: fp16 mma
// FLG: 2=exp+colsum+bf16hi trans store(E) | 16=QKV mixed | 32=row fp16-split store(AV)
//      | 8=fp32 row store | 64=skip lo-plane store in QKV Q/K epilogue
template <int AL, int BL, int NST, int MB, int FLG, int H16>
__global__ void __launch_bounds__(256, MB) mma_k(
    const ush* __restrict__ Ah, const ush* __restrict__ Al,
    const ush* __restrict__ Bh, const ush* __restrict__ Bl,
    float* __restrict__ Cf, ush* __restrict__ Ch, ush* __restrict__ Cl,
    const float* __restrict__ bias, float* __restrict__ part,
    int lda, int ldb, int ldc, int K,
    long long bsA, long long bsB, long long bsC,
    int zshA, int zxB, int zmC, int cshift,
    long long bsC2, int ldc2, int bstride)
{
    constexpr int BHO  = (1 + AL) * PL;
    constexpr int STGB = (2 + AL + BL) * PL;
    extern __shared__ char sm[];
    float* smf = (float*)sm;
    uint32_t su = smem_u32(sm);
    int tid = threadIdx.x, lane = tid & 31, w = tid >> 5;
    int wm = w & 3, wn = w >> 2;
    int m0 = blockIdx.y * 128, n0 = blockIdx.x * 128;
    long long z = blockIdx.z;

    const ush* pAh = Ah + (z >> zshA) * bsA;
    const ush* pAl = Al + (z >> zshA) * bsA;
    long long zB = z ^ zxB;
    const ush* pBh = Bh + zB * bsB;
    const ush* pBl = Bl + zB * bsB;
    long long zC = z & zmC;
    int colofs = (int)(z >> 2) * cshift;

    float acc[2][8][4];
#pragma unroll
    for (int a = 0; a < 2; a++)
#pragma unroll
        for (int b = 0; b < 8; b++)
#pragma unroll
            for (int c = 0; c < 4; c++) acc[a][b][c] = 0.f;

    int nch = K >> 5;

    auto cpstage = [&](int ch) {
        uint32_t dst = su + (ch % NST) * STGB;
        int k0 = ch << 5;
#pragma unroll
        for (int i = 0; i < 2; i++) {
            int idx = tid + (i << 8);
            int r = idx >> 2, c8 = (idx & 3) << 3;
            uint32_t doff = r * 80 + (c8 << 1);
            CP16(dst + doff,       pAh + (long long)(m0 + r) * lda + k0 + c8);
            if (AL)
                CP16(dst + PL + doff,  pAl + (long long)(m0 + r) * lda + k0 + c8);
            CP16(dst + BHO + doff, pBh + (long long)(n0 + r) * ldb + k0 + c8);
            if (BL)
                CP16(dst + BHO + PL + doff, pBl + (long long)(n0 + r) * ldb + k0 + c8);
        }
    };
    auto consume = [&](int ch) {
        uint32_t sst = su + (ch % NST) * STGB;
#pragma unroll
        for (int kk = 0; kk < 32; kk += 16) {
            uint32_t ah[2][4], al[2][4], bh[4][4], bl[4][4];
            int rA = (lane & 7) + ((lane >> 3) & 1) * 8;
            int kA = kk + (lane >> 4) * 8;
#pragma unroll
            for (int mt = 0; mt < 2; mt++) {
                uint32_t ad = sst + (wm * 32 + mt * 16 + rA) * 80 + kA * 2;
                ldmx4(ah[mt], ad);
                if (AL) ldmx4(al[mt], ad + PL);
            }
            int rB = (lane & 7) + (lane >> 4) * 8;
            int kB = kk + ((lane >> 3) & 1) * 8;
#pragma unroll
            for (int nt = 0; nt < 4; nt++) {
                uint32_t bd = sst + BHO + (wn * 64 + nt * 16 + rB) * 80 + kB * 2;
                ldmx4(bh[nt], bd);
                if (BL) ldmx4(bl[nt], bd + PL);
            }
#pragma unroll
            for (int mt = 0; mt < 2; mt++)
#pragma unroll
                for (int nt = 0; nt < 8; nt++) {
                    const uint32_t* ph = &bh[nt >> 1][(nt & 1) * 2];
                    const uint32_t* pl = &bl[nt >> 1][(nt & 1) * 2];
                    if (H16) {
                        mma_hf(acc[mt][nt], ah[mt], ph);
                        if (BL) mma_hf(acc[mt][nt], ah[mt], pl);
                        if (AL) mma_hf(acc[mt][nt], al[mt], ph);
                    } else {
                        mma_bf(acc[mt][nt], ah[mt], ph);
                        if (BL) mma_bf(acc[mt][nt], ah[mt], pl);
                        if (AL) mma_bf(acc[mt][nt], al[mt], ph);
                    }
                }
        }
    };

    // single-barrier pipeline
#pragma unroll
    for (int s = 0; s < NST - 1; s++) { cpstage(s); CPCOMMIT(); }
    for (int ch = 0; ch < nch; ch++) {
        cp_wait<NST - 2>();
        __syncthreads();
        consume(ch);
        if (ch + NST - 1 < nch) cpstage(ch + NST - 1);
        CPCOMMIT();
    }

    // acc -> smem fp32 tile (stride 130)
    __syncthreads();
#pragma unroll
    for (int mt = 0; mt < 2; mt++)
#pragma unroll
        for (int nt = 0; nt < 8; nt++) {
            int r = wm * 32 + mt * 16 + (lane >> 2);
            int c = wn * 64 + nt * 8 + 2 * (lane & 3);
            *(float2*)&smf[r * 130 + c]       = make_float2(acc[mt][nt][0], acc[mt][nt][1]);
            *(float2*)&smf[(r + 8) * 130 + c] = make_float2(acc[mt][nt][2], acc[mt][nt][3]);
        }
    __syncthreads();

    if (FLG & 2) {               // S: exp + colsum + bf16-hi trans store
        int r = tid & 127, hf = tid >> 7;
        float lsum = 0.f;
        ush* co = Ch + zC * bsC;
        int j0 = hf * 64;
#pragma unroll 4
        for (int j = j0; j < j0 + 64; j++) {
            float e = __expf(fminf(smf[r * 130 + j], 60.f));
            lsum += e;
            co[(long long)(n0 + j) * ldc + m0 + r] = (ush)(bfh(e) >> 16);
        }
        part[((long long)blockIdx.x * 2 + hf) * (8 * HW) + z * HW + m0 + r] = lsum;
    } else if (FLG & 32) {       // AV: row fp16-split store
        ush* ch2 = Ch + zC * bsC;
        ush* cl2 = Cl + zC * bsC;
#pragma unroll 4
        for (int i = tid; i < 16384; i += 256) {
            int r = i >> 7, c = i & 127;
            float v = smf[r * 130 + c];
            long long o = (long long)(m0 + r) * ldc + colofs + n0 + c;
            ush hb = f16b(v);
            ch2[o] = hb;
            cl2[o] = f16b(v - __half2float(__ushort_as_half(hb)));
        }
    } else if (FLG & 16) {       // QKV mixed
        if (blockIdx.y == 2) {   // V rows: fp32 row store
            float* cf = Cf + z * bsC2;
#pragma unroll 4
            for (int i = tid; i < 16384; i += 256) {
                int r = i >> 7, c = i & 127;
                cf[(long long)r * ldc2 + n0 + c] =
                    smf[r * 130 + c] + bias[(z >> zshA) * bstride + m0 + r];
            }
        } else {                 // Q/K: trans bf16-hi store + bias
            int r = tid & 127, hf = tid >> 7;
            float bb = bias[(z >> zshA) * bstride + m0 + r];
            ush* ch2 = Ch + zC * bsC;
            ush* cl2 = Cl + zC * bsC;
            int j0 = hf * 64;
#pragma unroll 4
            for (int j = j0; j < j0 + 64; j++) {
                float v = smf[r * 130 + j] + bb;
                long long o = (long long)(n0 + j) * ldc + m0 + r;
                uint32_t hb = bfh(v);
                ch2[o] = (ush)(hb >> 16);
                if (!(FLG & 64))
                    cl2[o] = (ush)(bfh(v - __int_as_float(hb)) >> 16);
            }
        }
    } else {                     // fp32 row store + bias (final)
        float* cf = Cf + zC * bsC;
#pragma unroll 4
        for (int i = tid; i < 16384; i += 256) {
            int r = i >> 7, c = i & 127;
            cf[(long long)(m0 + r) * ldc + n0 + c] =
                smf[r * 130 + c] + bias[(z >> zshA) * bstride + m0 + r];
        }
    }
}

// ---- BN(eval) + depthwise 3x3 SAME, both branches in one launch ----
__global__ void __launch_bounds__(256) bn_dw_kernel(
    const float* __restrict__ x0, const float* __restrict__ x1,
    const float* __restrict__ g0, const float* __restrict__ g1,
    const float* __restrict__ b0, const float* __restrict__ b1,
    const float* __restrict__ m0p, const float* __restrict__ m1p,
    const float* __restrict__ v0, const float* __restrict__ v1,
    const float* __restrict__ w0p, const float* __restrict__ w1p,
    const float* __restrict__ d0, const float* __restrict__ d1,
    float* __restrict__ y)
{
    __shared__ float tile[66 * 66];
    int bc = blockIdx.x, sel = bc >> 9, lc = bc & 511, c = bc & 127;
    const float* xp = (sel ? x1 : x0) + (size_t)lc * HW;
    const float* g = sel ? g1 : g0; const float* b = sel ? b1 : b0;
    const float* m = sel ? m1p : m0p; const float* v = sel ? v1 : v0;
    const float* wdw = sel ? w1p : w0p; const float* bdw = sel ? d1 : d0;
    float sc = g[c] * rsqrtf(v[c] + EPSf), sh = b[c] - m[c] * sc;
    for (int i = threadIdx.x; i < 66 * 66; i += 256) {
        int r = i / 66 - 1, cl = i % 66 - 1;
        tile[i] = (r >= 0 && r < 64 && cl >= 0 && cl < 64) ? xp[r * 64 + cl] * sc + sh : 0.f;
    }
    __syncthreads();
    float w0 = wdw[c*9], w1 = wdw[c*9+1], w2 = wdw[c*9+2], w3 = wdw[c*9+3], w4 = wdw[c*9+4];
    float w5 = wdw[c*9+5], w6 = wdw[c*9+6], w7 = wdw[c*9+7], w8 = wdw[c*9+8], bb = bdw[c];
    float* yp = y + (size_t)bc * HW;
    for (int i = threadIdx.x; i < HW; i += 256) {
        const float* t = &tile[(i >> 6) * 66 + (i & 63)];
        yp[i] = bb + t[0]*w0 + t[1]*w1 + t[2]*w2 + t[66]*w3 + t[67]*w4 + t[68]*w5
                   + t[132]*w6 + t[133]*w7 + t[134]*w8;
    }
}

// ---- transpose [128][HW] -> bf16-hi [HW][128] (dw) ----
__global__ void __launch_bounds__(256) tsplit_k(
    const float* __restrict__ src, ush* __restrict__ dh, long long bs)
{
    __shared__ float t[32][33];
    src += blockIdx.z * bs; dh += blockIdx.z * bs;
    int p0 = blockIdx.x * 32, c0 = blockIdx.y * 32;
    int x = threadIdx.x & 31, y = threadIdx.x >> 5;
#pragma unroll
    for (int i = 0; i < 32; i += 8) t[y + i][x] = src[(long long)(c0 + y + i) * HW + p0 + x];
    __syncthreads();
#pragma unroll
    for (int i = 0; i < 32; i += 8) {
        long long o = (long long)(p0 + y + i) * 128 + c0 + x;
        dh[o] = (ush)(bfh(t[x][y + i]) >> 16);
    }
}

// ---- merged residual transpose: F_i/F_w -> fp16 hi/lo planes of xT ----
__global__ void __launch_bounds__(256) tres_k(
    const float* __restrict__ Fi, const float* __restrict__ Fw,
    ush* __restrict__ xh, ush* __restrict__ xl)
{
    __shared__ float t[32][33];
    long long z = blockIdx.z;          // 0..7 : branch = z>>2, batch = z&3
    int br = (int)(z >> 2), b = (int)(z & 3);
    const float* src = (br ? Fw : Fi) + (long long)b * Cc * HW;
    int p0 = blockIdx.x * 32, c0 = blockIdx.y * 32;
    int x = threadIdx.x & 31, y = threadIdx.x >> 5;
#pragma unroll
    for (int i = 0; i < 32; i += 8) t[y + i][x] = src[(long long)(c0 + y + i) * HW + p0 + x];
    __syncthreads();
#pragma unroll
    for (int i = 0; i < 32; i += 8) {
        float v = t[x][y + i];
        long long o = ((long long)b * HW + p0 + y + i) * 512 + 256 + br * 128 + c0 + x;
        ush hb = f16b(v);
        xh[o] = hb;
        xl[o] = f16b(v - __half2float(__ushort_as_half(hb)));
    }
}

// ---- pack stacked QKV weights [2][384][128] split bf16 + bias [2][384] ----
__global__ void __launch_bounds__(256) pack_wqkv(
    const float* wq1, const float* wk1, const float* wv1,
    const float* wq2, const float* wk2, const float* wv2,
    const float* bq1, const float* bk1, const float* bv1,
    const float* bq2, const float* bk2, const float* bv2,
    ush* wAh, ush* wAl, float* bqkv)
{
    int i = blockIdx.x * 256 + threadIdx.x;   // 98304
    if (i >= 2 * 384 * 128) return;
    int br = i / 49152, rem = i % 49152, r = rem >> 7, c = rem & 127;
    const float* w; const float* bs;
    if (br == 0) { w = r < 128 ? wq1 : r < 256 ? wk1 : wv1; bs = r < 128 ? bq1 : r < 256 ? bk1 : bv1; }
    else         { w = r < 128 ? wq2 : r < 256 ? wk2 : wv2; bs = r < 128 ? bq2 : r < 256 ? bk2 : bv2; }
    float v = w[(r & 127) * 128 + c];
    uint32_t hb = bfh(v);
    wAh[i] = (ush)(hb >> 16);
    wAl[i] = (ush)(bfh(v - __int_as_float(hb)) >> 16);
    if (c == 0) bqkv[br * 384 + r] = bs[r & 127];
}

// ---- reduce 64 partial colsums -> reciprocal ----
__global__ void __launch_bounds__(256) rcpsum(const float* __restrict__ part, float* __restrict__ sums)
{
    int i = blockIdx.x * 256 + threadIdx.x;    // 32768
    float s = 0.f;
#pragma unroll
    for (int k = 0; k < 64; k++) s += part[(long long)k * 32768 + i];
    sums[i] = 1.f / s;
}

// ---- fold rs into V, bf16-hi only ----
__global__ void __launch_bounds__(256) vscale(
    const float4* __restrict__ v, const float4* __restrict__ rs4,
    ush* __restrict__ vh)
{
    int i = blockIdx.x * 256 + threadIdx.x;    // 1,048,576 float4
    int n4 = i & 1023, tb = i >> 17;
    float4 a = v[i], r = rs4[((tb ^ 4) << 10) + n4];
    a.x *= r.x; a.y *= r.y; a.z *= r.z; a.w *= r.w;
    uint32_t h0 = bfh(a.x), h1 = bfh(a.y), h2 = bfh(a.z), h3 = bfh(a.w);
    ((uint2*)vh)[i] = make_uint2((h0 >> 16) | h1, (h2 >> 16) | h3);
}

// ---- pack fused output weight (fp16 single plane) + bias ----
__global__ void __launch_bounds__(256) packw(
    const float* __restrict__ wp, const float* __restrict__ bp,
    const float* __restrict__ w1, const float* __restrict__ b1,
    const float* __restrict__ w2, const float* __restrict__ b2,
    ush* __restrict__ wh, float* __restrict__ bc)
{
    int i = blockIdx.x * 256 + threadIdx.x;
    if (i >= OUTC * 512) return;
    int o = i >> 9, k = i & 511;
    float v = (k < 256) ? wp[o * 256 + k] : (k < 384) ? w1[o * 128 + k - 256] : w2[o * 128 + k - 384];
    wh[i] = f16b(v);
    if (k == 0) bc[o] = bp[o] + b1[o] + b2[o];
}

extern "C" void kernel_launch(void* const* d_in, const int* in_sizes, int n_in,
                              void* d_out, int out_size)
{
    const float *F_i = (const float*)d_in[0], *F_w = (const float*)d_in[1];
    const float *bn1g = (const float*)d_in[2], *bn1b = (const float*)d_in[3];
    const float *bn1m = (const float*)d_in[4], *bn1v = (const float*)d_in[5];
    const float *bn2g = (const float*)d_in[6], *bn2b = (const float*)d_in[7];
    const float *bn2m = (const float*)d_in[8], *bn2v = (const float*)d_in[9];
    const float *wq1 = (const float*)d_in[10], *bq1 = (const float*)d_in[11];
    const float *wk1 = (const float*)d_in[12], *bk1 = (const float*)d_in[13];
    const float *wv1 = (const float*)d_in[14], *bv1 = (const float*)d_in[15];
    const float *wq2 = (const float*)d_in[16], *bq2 = (const float*)d_in[17];
    const float *wk2 = (const float*)d_in[18], *bk2 = (const float*)d_in[19];
    const float *wv2 = (const float*)d_in[20], *bv2 = (const float*)d_in[21];
    const float *wd1 = (const float*)d_in[22], *bd1 = (const float*)d_in[23];
    const float *wd2 = (const float*)d_in[24], *bd2 = (const float*)d_in[25];
    const float *wpj = (const float*)d_in[26], *bpj = (const float*)d_in[27];
    const float *wr1 = (const float*)d_in[28], *br1 = (const float*)d_in[29];
    const float *wr2 = (const float*)d_in[30], *br2 = (const float*)d_in[31];

    float *dw, *v, *part, *sum, *bqkv, *bc;
    ush *dwTh, *wAh, *wAl, *qTh, *qTl, *vh, *Eh, *xTh, *xTl, *wch;
    cudaGetSymbolAddress((void**)&dw, g_dw);
    cudaGetSymbolAddress((void**)&dwTh, g_dwTh);
    cudaGetSymbolAddress((void**)&wAh, g_wAh);   cudaGetSymbolAddress((void**)&wAl, g_wAl);
    cudaGetSymbolAddress((void**)&bqkv, g_bqkv);
    cudaGetSymbolAddress((void**)&qTh, g_qkvTh); cudaGetSymbolAddress((void**)&qTl, g_qkvTl);
    cudaGetSymbolAddress((void**)&v, g_v);
    cudaGetSymbolAddress((void**)&vh, g_vh);
    cudaGetSymbolAddress((void**)&Eh, g_Eh);
    cudaGetSymbolAddress((void**)&part, g_part); cudaGetSymbolAddress((void**)&sum, g_sum);
    cudaGetSymbolAddress((void**)&xTh, g_xTh);   cudaGetSymbolAddress((void**)&xTl, g_xTl);
    cudaGetSymbolAddress((void**)&wch, g_wch);
    cudaGetSymbolAddress((void**)&bc, g_bcat);

    const int SM_QKV = 4 * 2 * PL;      // 81920 -> 2 CTA/SM
    const int SM_SAV = 4 * 2 * PL;      // 81920 -> 2 CTA/SM
    const int SM_FIN = 3 * 3 * PL;      // 92160 -> 2 CTA/SM (fp16, 3 planes, 3 stages)

    cudaFuncSetAttribute(mma_k<0,0,4,2,80,0>, cudaFuncAttributeMaxDynamicSharedMemorySize, SM_QKV);
    cudaFuncSetAttribute(mma_k<0,0,4,2,2,0>,  cudaFuncAttributeMaxDynamicSharedMemorySize, SM_SAV);
    cudaFuncSetAttribute(mma_k<0,0,4,2,32,0>, cudaFuncAttributeMaxDynamicSharedMemorySize, SM_SAV);
    cudaFuncSetAttribute(mma_k<0,1,3,2,8,1>,  cudaFuncAttributeMaxDynamicSharedMemorySize, SM_FIN);

    const long long TT = (long long)HW * Cc;            // 524288
    const long long TT384 = (long long)HW * 384;        // 1572864
    const long long SS = (long long)HW * HW;
    const long long XS = (long long)HW * 512;

    pack_wqkv<<<384, 256>>>(wq1, wk1, wv1, wq2, wk2, wv2,
                            bq1, bk1, bv1, bq2, bk2, bv2, wAh, wAl, bqkv);
    packw<<<512, 256>>>(wpj, bpj, wr1, br1, wr2, br2, wch, bc);
    bn_dw_kernel<<<1024, 256>>>(F_i, F_w, bn1g, bn2g, bn1b, bn2b, bn1m, bn2m,
                                bn1v, bn2v, wd1, wd2, bd1, bd2, dw);
    tsplit_k<<<dim3(128, 4, 8), 256>>>(dw, dwTh, TT);
    tres_k<<<dim3(128, 4, 8), 256>>>(F_i, F_w, xTh, xTl);

    // QKV merged: M=384 (Q|K|V), N=4096, K=128, z = branch*4+batch  (1-pass wh*xh)
    mma_k<0,0,4,2,80,0><<<dim3(32, 3, 8), 256, SM_QKV>>>(
        wAh, wAh, dwTh, dwTh, v, qTh, qTl, bqkv, 0,
        128, 128, 384, 128, 49152, TT, TT384,
        2, 0, 255, 0, TT, HW, 384);

    // S merged: z = attn*4+batch; A=Q hi (own branch), B=K hi (other branch)  (1-pass)
    mma_k<0,0,4,2,2,0><<<dim3(32, 32, 8), 256, SM_SAV>>>(
        qTh, qTh, qTh + 128, qTh + 128, 0, Eh, 0, 0, part,
        384, 384, HW, 128, TT384, TT384, SS,
        0, 4, 255, 0, 0, 0, 0);

    rcpsum<<<128, 256>>>(part, sum);
    vscale<<<4096, 256>>>((const float4*)v, (const float4*)sum, vh);

    // AV merged (flipped): D[m][c] = sum_n Eh[m][n]*Vh[c][n]; fp16-split store -> xT
    mma_k<0,0,4,2,32,0><<<dim3(1, 32, 8), 256, SM_SAV>>>(
        Eh, Eh, vh, vh, 0, xTh, xTl, 0, 0,
        HW, HW, 512, HW, SS, TT, XS,
        0, 4, 3, 128, 0, 0, 0);

    // out = wcat(fp16) @ xT^T(fp16 hi+lo) + bcat : M=256, N=4096, K=512  (2-pass fp16)
    mma_k<0,1,3,2,8,1><<<dim3(32, 2, 4), 256, SM_FIN>>>(
        wch, wch, xTh, xTl, (float*)d_out, 0, 0, bc, 0,
        512, 512, HW, 512, 0, XS, (long long)OUTC * HW,
        0, 0, 255, 0, 0, 0, 0);
}

// round 13
// speedup vs baseline: 6.3063x; 1.0347x over previous
#include <cuda_runtime.h>
#include <cuda_fp16.h>
#include <cstdint>
#include <math.h>

typedef unsigned short ush;
#define HW 4096
#define Cc 128
#define Bn 4
#define OUTC 256
#define EPSf 1e-5f
#define PL 10240

// ---------------- scratch ----------------
__device__ ush   g_dwraw[2*Bn*Cc*HW];             // bn+dw output, bf16-hi [br][b][c][pix]
__device__ ush   g_dwTh[2*Bn*Cc*HW];              // transposed [br][b][pix][c]
__device__ ush   g_wAh[2*384*128],   g_wAl[2*384*128];
__device__ float g_bqkv[2*384];
__device__ ush   g_qkvTh[2ll*Bn*HW*384], g_qkvTl[2ll*Bn*HW*384];  // [br][B][pix][Q|K|V]
__device__ ush   g_vraw[2*Bn*Cc*HW];              // V bf16-hi, unscaled
__device__ ush   g_vh[2*Bn*Cc*HW];                // V*rs bf16-hi
__device__ ush   g_Eh[134217728];                 // [attn][B][key][query] bf16
__device__ float g_part[64*8*HW];
__device__ float g_sum[8*HW];
__device__ ush   g_xTh[Bn*HW*512];                // fp16 plane
__device__ ush   g_wch[OUTC*512];                 // fp16 plane
__device__ float g_bcat[OUTC];

__device__ __forceinline__ uint32_t smem_u32(const void* p) {
    uint32_t a;
    asm("{ .reg .u64 t; cvta.to.shared.u64 t, %1; cvt.u32.u64 %0, t; }" : "=r"(a) : "l"(p));
    return a;
}
__device__ __forceinline__ uint32_t bfh(float x) {
    uint32_t u = __float_as_uint(x);
    return (u + 0x7FFFu + ((u >> 16) & 1)) & 0xFFFF0000u;
}
__device__ __forceinline__ ush f16b(float x) {
    return __half_as_ushort(__float2half_rn(x));
}
__device__ __forceinline__ void ldmx4(uint32_t* r, uint32_t a) {
    asm volatile("ldmatrix.sync.aligned.m8n8.x4.shared.b16 {%0,%1,%2,%3}, [%4];"
        : "=r"(r[0]), "=r"(r[1]), "=r"(r[2]), "=r"(r[3]) : "r"(a));
}
__device__ __forceinline__ void mma_bf(float* d, const uint32_t* a, const uint32_t* b) {
    asm volatile("mma.sync.aligned.m16n8k16.row.col.f32.bf16.bf16.f32 "
        "{%0,%1,%2,%3}, {%4,%5,%6,%7}, {%8,%9}, {%0,%1,%2,%3};"
        : "+f"(d[0]), "+f"(d[1]), "+f"(d[2]), "+f"(d[3])
        : "r"(a[0]), "r"(a[1]), "r"(a[2]), "r"(a[3]), "r"(b[0]), "r"(b[1]));
}
__device__ __forceinline__ void mma_hf(float* d, const uint32_t* a, const uint32_t* b) {
    asm volatile("mma.sync.aligned.m16n8k16.row.col.f32.f16.f16.f32 "
        "{%0,%1,%2,%3}, {%4,%5,%6,%7}, {%8,%9}, {%0,%1,%2,%3};"
        : "+f"(d[0]), "+f"(d[1]), "+f"(d[2]), "+f"(d[3])
        : "r"(a[0]), "r"(a[1]), "r"(a[2]), "r"(a[3]), "r"(b[0]), "r"(b[1]));
}
#define CP16(d, s) asm volatile("cp.async.cg.shared.global [%0], [%1], 16;" :: "r"(d), "l"(s))
#define CPCOMMIT() asm volatile("cp.async.commit_group;" ::: "memory")
template <int N>
__device__ __forceinline__ void cp_wait() {
    asm volatile("cp.async.wait_group %0;" :: "n"(N) : "memory");
}

// ===== cp.async pipelined warp-MMA GEMM: D[m][n] = sum_k A[m][k]*B[n][k] =====
// AL: al*bh pass; BL: ah*bl pass; NST: stages; MB: min blocks/SM; H16: fp16 mma
// FLG: 2=exp2+colsum+bf16hi trans store(E) | 16=QKV mixed | 32=row fp16 store(AV)
//      | 8=fp32 row store | 64=skip lo-plane store
template <int AL, int BL, int NST, int MB, int FLG, int H16>
__global__ void __launch_bounds__(256, MB) mma_k(
    const ush* __restrict__ Ah, const ush* __restrict__ Al,
    const ush* __restrict__ Bh, const ush* __restrict__ Bl,
    float* __restrict__ Cf, ush* __restrict__ Ch, ush* __restrict__ Cl,
    const float* __restrict__ bias, float* __restrict__ part,
    int lda, int ldb, int ldc, int K,
    long long bsA, long long bsB, long long bsC,
    int zshA, int zxB, int zmC, int cshift,
    long long bsC2, int ldc2, int bstride)
{
    constexpr int BHO  = (1 + AL) * PL;
    constexpr int STGB = (2 + AL + BL) * PL;
    extern __shared__ char sm[];
    float* smf = (float*)sm;
    uint32_t su = smem_u32(sm);
    int tid = threadIdx.x, lane = tid & 31, w = tid >> 5;
    int wm = w & 3, wn = w >> 2;
    int m0 = blockIdx.y * 128, n0 = blockIdx.x * 128;
    long long z = blockIdx.z;

    const ush* pAh = Ah + (z >> zshA) * bsA;
    const ush* pAl = Al + (z >> zshA) * bsA;
    long long zB = z ^ zxB;
    const ush* pBh = Bh + zB * bsB;
    const ush* pBl = Bl + zB * bsB;
    long long zC = z & zmC;
    int colofs = (int)(z >> 2) * cshift;

    float acc[2][8][4];
#pragma unroll
    for (int a = 0; a < 2; a++)
#pragma unroll
        for (int b = 0; b < 8; b++)
#pragma unroll
            for (int c = 0; c < 4; c++) acc[a][b][c] = 0.f;

    int nch = K >> 5;

    auto cpstage = [&](int ch) {
        uint32_t dst = su + (ch % NST) * STGB;
        int k0 = ch << 5;
#pragma unroll
        for (int i = 0; i < 2; i++) {
            int idx = tid + (i << 8);
            int r = idx >> 2, c8 = (idx & 3) << 3;
            uint32_t doff = r * 80 + (c8 << 1);
            CP16(dst + doff,       pAh + (long long)(m0 + r) * lda + k0 + c8);
            if (AL)
                CP16(dst + PL + doff,  pAl + (long long)(m0 + r) * lda + k0 + c8);
            CP16(dst + BHO + doff, pBh + (long long)(n0 + r) * ldb + k0 + c8);
            if (BL)
                CP16(dst + BHO + PL + doff, pBl + (long long)(n0 + r) * ldb + k0 + c8);
        }
    };
    auto consume = [&](int ch) {
        uint32_t sst = su + (ch % NST) * STGB;
#pragma unroll
        for (int kk = 0; kk < 32; kk += 16) {
            uint32_t ah[2][4], al[2][4], bh[4][4], bl[4][4];
            int rA = (lane & 7) + ((lane >> 3) & 1) * 8;
            int kA = kk + (lane >> 4) * 8;
#pragma unroll
            for (int mt = 0; mt < 2; mt++) {
                uint32_t ad = sst + (wm * 32 + mt * 16 + rA) * 80 + kA * 2;
                ldmx4(ah[mt], ad);
                if (AL) ldmx4(al[mt], ad + PL);
            }
            int rB = (lane & 7) + (lane >> 4) * 8;
            int kB = kk + ((lane >> 3) & 1) * 8;
#pragma unroll
            for (int nt = 0; nt < 4; nt++) {
                uint32_t bd = sst + BHO + (wn * 64 + nt * 16 + rB) * 80 + kB * 2;
                ldmx4(bh[nt], bd);
                if (BL) ldmx4(bl[nt], bd + PL);
            }
#pragma unroll
            for (int mt = 0; mt < 2; mt++)
#pragma unroll
                for (int nt = 0; nt < 8; nt++) {
                    const uint32_t* ph = &bh[nt >> 1][(nt & 1) * 2];
                    const uint32_t* pl = &bl[nt >> 1][(nt & 1) * 2];
                    if (H16) {
                        mma_hf(acc[mt][nt], ah[mt], ph);
                        if (BL) mma_hf(acc[mt][nt], ah[mt], pl);
                        if (AL) mma_hf(acc[mt][nt], al[mt], ph);
                    } else {
                        mma_bf(acc[mt][nt], ah[mt], ph);
                        if (BL) mma_bf(acc[mt][nt], ah[mt], pl);
                        if (AL) mma_bf(acc[mt][nt], al[mt], ph);
                    }
                }
        }
    };

    // single-barrier pipeline
#pragma unroll
    for (int s = 0; s < NST - 1; s++) { cpstage(s); CPCOMMIT(); }
    for (int ch = 0; ch < nch; ch++) {
        cp_wait<NST - 2>();
        __syncthreads();
        consume(ch);
        if (ch + NST - 1 < nch) cpstage(ch + NST - 1);
        CPCOMMIT();
    }

    // acc -> smem fp32 tile (stride 130)
    __syncthreads();
#pragma unroll
    for (int mt = 0; mt < 2; mt++)
#pragma unroll
        for (int nt = 0; nt < 8; nt++) {
            int r = wm * 32 + mt * 16 + (lane >> 2);
            int c = wn * 64 + nt * 8 + 2 * (lane & 3);
            *(float2*)&smf[r * 130 + c]       = make_float2(acc[mt][nt][0], acc[mt][nt][1]);
            *(float2*)&smf[(r + 8) * 130 + c] = make_float2(acc[mt][nt][2], acc[mt][nt][3]);
        }
    __syncthreads();

    if (FLG & 2) {               // S: exp2 + colsum + bf16-hi trans store (K pre-scaled by log2e)
        int r = tid & 127, hf = tid >> 7;
        float lsum = 0.f;
        ush* co = Ch + zC * bsC;
        int j0 = hf * 64;
#pragma unroll 4
        for (int j = j0; j < j0 + 64; j++) {
            float e = exp2f(fminf(smf[r * 130 + j], 86.0f));
            lsum += e;
            co[(long long)(n0 + j) * ldc + m0 + r] = (ush)(bfh(e) >> 16);
        }
        part[((long long)blockIdx.x * 2 + hf) * (8 * HW) + z * HW + m0 + r] = lsum;
    } else if (FLG & 32) {       // AV: row fp16 store (hi only when FLG&64)
        ush* ch2 = Ch + zC * bsC;
        ush* cl2 = Cl + zC * bsC;
#pragma unroll 4
        for (int i = tid; i < 16384; i += 256) {
            int r = i >> 7, c = i & 127;
            float v = smf[r * 130 + c];
            long long o = (long long)(m0 + r) * ldc + colofs + n0 + c;
            ush hb = f16b(v);
            ch2[o] = hb;
            if (!(FLG & 64))
                cl2[o] = f16b(v - __half2float(__ushort_as_half(hb)));
        }
    } else if (FLG & 16) {       // QKV mixed
        if (blockIdx.y == 2) {   // V rows: bf16-hi row store
            ush* cv = (ush*)Cf + z * bsC2;
#pragma unroll 4
            for (int i = tid; i < 16384; i += 256) {
                int r = i >> 7, c = i & 127;
                float v = smf[r * 130 + c] + bias[(z >> zshA) * bstride + m0 + r];
                cv[(long long)r * ldc2 + n0 + c] = (ush)(bfh(v) >> 16);
            }
        } else {                 // Q/K: trans bf16-hi store + bias
            int r = tid & 127, hf = tid >> 7;
            float bb = bias[(z >> zshA) * bstride + m0 + r];
            ush* ch2 = Ch + zC * bsC;
            ush* cl2 = Cl + zC * bsC;
            int j0 = hf * 64;
#pragma unroll 4
            for (int j = j0; j < j0 + 64; j++) {
                float v = smf[r * 130 + j] + bb;
                long long o = (long long)(n0 + j) * ldc + m0 + r;
                uint32_t hb = bfh(v);
                ch2[o] = (ush)(hb >> 16);
                if (!(FLG & 64))
                    cl2[o] = (ush)(bfh(v - __int_as_float(hb)) >> 16);
            }
        }
    } else {                     // fp32 row store + bias (final)
        float* cf = Cf + zC * bsC;
#pragma unroll 4
        for (int i = tid; i < 16384; i += 256) {
            int r = i >> 7, c = i & 127;
            cf[(long long)(m0 + r) * ldc + n0 + c] =
                smf[r * 130 + c] + bias[(z >> zshA) * bstride + m0 + r];
        }
    }
}

// ---- BN(eval) + depthwise 3x3 SAME, both branches; bf16-hi output ----
__global__ void __launch_bounds__(256) bn_dw_kernel(
    const float* __restrict__ x0, const float* __restrict__ x1,
    const float* __restrict__ g0, const float* __restrict__ g1,
    const float* __restrict__ b0, const float* __restrict__ b1,
    const float* __restrict__ m0p, const float* __restrict__ m1p,
    const float* __restrict__ v0, const float* __restrict__ v1,
    const float* __restrict__ w0p, const float* __restrict__ w1p,
    const float* __restrict__ d0, const float* __restrict__ d1,
    ush* __restrict__ y)
{
    __shared__ float tile[66 * 66];
    int bc = blockIdx.x, sel = bc >> 9, lc = bc & 511, c = bc & 127;
    const float* xp = (sel ? x1 : x0) + (size_t)lc * HW;
    const float* g = sel ? g1 : g0; const float* b = sel ? b1 : b0;
    const float* m = sel ? m1p : m0p; const float* v = sel ? v1 : v0;
    const float* wdw = sel ? w1p : w0p; const float* bdw = sel ? d1 : d0;
    float sc = g[c] * rsqrtf(v[c] + EPSf), sh = b[c] - m[c] * sc;
    for (int i = threadIdx.x; i < 66 * 66; i += 256) {
        int r = i / 66 - 1, cl = i % 66 - 1;
        tile[i] = (r >= 0 && r < 64 && cl >= 0 && cl < 64) ? xp[r * 64 + cl] * sc + sh : 0.f;
    }
    __syncthreads();
    float w0 = wdw[c*9], w1 = wdw[c*9+1], w2 = wdw[c*9+2], w3 = wdw[c*9+3], w4 = wdw[c*9+4];
    float w5 = wdw[c*9+5], w6 = wdw[c*9+6], w7 = wdw[c*9+7], w8 = wdw[c*9+8], bb = bdw[c];
    ush* yp = y + (size_t)bc * HW;
    for (int i = threadIdx.x; i < HW; i += 256) {
        const float* t = &tile[(i >> 6) * 66 + (i & 63)];
        float s = bb + t[0]*w0 + t[1]*w1 + t[2]*w2 + t[66]*w3 + t[67]*w4 + t[68]*w5
                     + t[132]*w6 + t[133]*w7 + t[134]*w8;
        yp[i] = (ush)(bfh(s) >> 16);
    }
}

// ---- transpose ush [128][HW] -> [HW][128] ----
__global__ void __launch_bounds__(256) tsplit_k(
    const ush* __restrict__ src, ush* __restrict__ dh, long long bs)
{
    __shared__ ush t[32][34];
    src += blockIdx.z * bs; dh += blockIdx.z * bs;
    int p0 = blockIdx.x * 32, c0 = blockIdx.y * 32;
    int x = threadIdx.x & 31, y = threadIdx.x >> 5;
#pragma unroll
    for (int i = 0; i < 32; i += 8) t[y + i][x] = src[(long long)(c0 + y + i) * HW + p0 + x];
    __syncthreads();
#pragma unroll
    for (int i = 0; i < 32; i += 8)
        dh[(long long)(p0 + y + i) * 128 + c0 + x] = t[x][y + i];
}

// ---- merged residual transpose: F_i/F_w -> fp16 plane of xT ----
__global__ void __launch_bounds__(256) tres_k(
    const float* __restrict__ Fi, const float* __restrict__ Fw,
    ush* __restrict__ xh)
{
    __shared__ float t[32][33];
    long long z = blockIdx.z;
    int br = (int)(z >> 2), b = (int)(z & 3);
    const float* src = (br ? Fw : Fi) + (long long)b * Cc * HW;
    int p0 = blockIdx.x * 32, c0 = blockIdx.y * 32;
    int x = threadIdx.x & 31, y = threadIdx.x >> 5;
#pragma unroll
    for (int i = 0; i < 32; i += 8) t[y + i][x] = src[(long long)(c0 + y + i) * HW + p0 + x];
    __syncthreads();
#pragma unroll
    for (int i = 0; i < 32; i += 8) {
        long long o = ((long long)b * HW + p0 + y + i) * 512 + 256 + br * 128 + c0 + x;
        xh[o] = f16b(t[x][y + i]);
    }
}

// ---- pack stacked QKV weights; K-block pre-scaled by log2(e) ----
__global__ void __launch_bounds__(256) pack_wqkv(
    const float* wq1, const float* wk1, const float* wv1,
    const float* wq2, const float* wk2, const float* wv2,
    const float* bq1, const float* bk1, const float* bv1,
    const float* bq2, const float* bk2, const float* bv2,
    ush* wAh, ush* wAl, float* bqkv)
{
    int i = blockIdx.x * 256 + threadIdx.x;   // 98304
    if (i >= 2 * 384 * 128) return;
    int br = i / 49152, rem = i % 49152, r = rem >> 7, c = rem & 127;
    const float* w; const float* bs;
    if (br == 0) { w = r < 128 ? wq1 : r < 256 ? wk1 : wv1; bs = r < 128 ? bq1 : r < 256 ? bk1 : bv1; }
    else         { w = r < 128 ? wq2 : r < 256 ? wk2 : wv2; bs = r < 128 ? bq2 : r < 256 ? bk2 : bv2; }
    float scl = (r >= 128 && r < 256) ? 1.44269504088896f : 1.f;
    float v = w[(r & 127) * 128 + c] * scl;
    uint32_t hb = bfh(v);
    wAh[i] = (ush)(hb >> 16);
    wAl[i] = (ush)(bfh(v - __int_as_float(hb)) >> 16);
    if (c == 0) bqkv[br * 384 + r] = bs[r & 127] * scl;
}

// ---- reduce 64 partial colsums -> reciprocal ----
__global__ void __launch_bounds__(256) rcpsum(const float* __restrict__ part, float* __restrict__ sums)
{
    int i = blockIdx.x * 256 + threadIdx.x;    // 32768
    float s = 0.f;
#pragma unroll
    for (int k = 0; k < 64; k++) s += part[(long long)k * 32768 + i];
    sums[i] = 1.f / s;
}

// ---- fold rs into V (bf16 in, bf16 out); 524288 uint4 total ----
__global__ void __launch_bounds__(256) vscale(
    const uint4* __restrict__ vraw, const float4* __restrict__ rs4,
    uint4* __restrict__ vh)
{
    int i = blockIdx.x * 256 + threadIdx.x;    // 524,288 x uint4 (8 ush each)
    int n8 = i & 511, tb = i >> 16;            // tb = tensor*4+batch; 65536 uint4 per tb
    uint4 a = vraw[i];
    float4 r0 = rs4[(((tb ^ 4) << 10)) + n8 * 2];
    float4 r1 = rs4[(((tb ^ 4) << 10)) + n8 * 2 + 1];
    uint4 o;
    {
        float f0 = __int_as_float((a.x & 0xFFFFu) << 16) * r0.x;
        float f1 = __int_as_float(a.x & 0xFFFF0000u) * r0.y;
        o.x = (bfh(f0) >> 16) | bfh(f1);
        float f2 = __int_as_float((a.y & 0xFFFFu) << 16) * r0.z;
        float f3 = __int_as_float(a.y & 0xFFFF0000u) * r0.w;
        o.y = (bfh(f2) >> 16) | bfh(f3);
        float f4 = __int_as_float((a.z & 0xFFFFu) << 16) * r1.x;
        float f5 = __int_as_float(a.z & 0xFFFF0000u) * r1.y;
        o.z = (bfh(f4) >> 16) | bfh(f5);
        float f6 = __int_as_float((a.w & 0xFFFFu) << 16) * r1.z;
        float f7 = __int_as_float(a.w & 0xFFFF0000u) * r1.w;
        o.w = (bfh(f6) >> 16) | bfh(f7);
    }
    vh[i] = o;
}

// ---- pack fused output weight (fp16 single plane) + bias ----
__global__ void __launch_bounds__(256) packw(
    const float* __restrict__ wp, const float* __restrict__ bp,
    const float* __restrict__ w1, const float* __restrict__ b1,
    const float* __restrict__ w2, const float* __restrict__ b2,
    ush* __restrict__ wh, float* __restrict__ bc)
{
    int i = blockIdx.x * 256 + threadIdx.x;
    if (i >= OUTC * 512) return;
    int o = i >> 9, k = i & 511;
    float v = (k < 256) ? wp[o * 256 + k] : (k < 384) ? w1[o * 128 + k - 256] : w2[o * 128 + k - 384];
    wh[i] = f16b(v);
    if (k == 0) bc[o] = bp[o] + b1[o] + b2[o];
}

extern "C" void kernel_launch(void* const* d_in, const int* in_sizes, int n_in,
                              void* d_out, int out_size)
{
    const float *F_i = (const float*)d_in[0], *F_w = (const float*)d_in[1];
    const float *bn1g = (const float*)d_in[2], *bn1b = (const float*)d_in[3];
    const float *bn1m = (const float*)d_in[4], *bn1v = (const float*)d_in[5];
    const float *bn2g = (const float*)d_in[6], *bn2b = (const float*)d_in[7];
    const float *bn2m = (const float*)d_in[8], *bn2v = (const float*)d_in[9];
    const float *wq1 = (const float*)d_in[10], *bq1 = (const float*)d_in[11];
    const float *wk1 = (const float*)d_in[12], *bk1 = (const float*)d_in[13];
    const float *wv1 = (const float*)d_in[14], *bv1 = (const float*)d_in[15];
    const float *wq2 = (const float*)d_in[16], *bq2 = (const float*)d_in[17];
    const float *wk2 = (const float*)d_in[18], *bk2 = (const float*)d_in[19];
    const float *wv2 = (const float*)d_in[20], *bv2 = (const float*)d_in[21];
    const float *wd1 = (const float*)d_in[22], *bd1 = (const float*)d_in[23];
    const float *wd2 = (const float*)d_in[24], *bd2 = (const float*)d_in[25];
    const float *wpj = (const float*)d_in[26], *bpj = (const float*)d_in[27];
    const float *wr1 = (const float*)d_in[28], *br1 = (const float*)d_in[29];
    const float *wr2 = (const float*)d_in[30], *br2 = (const float*)d_in[31];

    float *part, *sum, *bqkv, *bc;
    ush *dwraw, *dwTh, *wAh, *wAl, *qTh, *qTl, *vraw, *vh, *Eh, *xTh, *wch;
    cudaGetSymbolAddress((void**)&dwraw, g_dwraw);
    cudaGetSymbolAddress((void**)&dwTh, g_dwTh);
    cudaGetSymbolAddress((void**)&wAh, g_wAh);   cudaGetSymbolAddress((void**)&wAl, g_wAl);
    cudaGetSymbolAddress((void**)&bqkv, g_bqkv);
    cudaGetSymbolAddress((void**)&qTh, g_qkvTh); cudaGetSymbolAddress((void**)&qTl, g_qkvTl);
    cudaGetSymbolAddress((void**)&vraw, g_vraw);
    cudaGetSymbolAddress((void**)&vh, g_vh);
    cudaGetSymbolAddress((void**)&Eh, g_Eh);
    cudaGetSymbolAddress((void**)&part, g_part); cudaGetSymbolAddress((void**)&sum, g_sum);
    cudaGetSymbolAddress((void**)&xTh, g_xTh);
    cudaGetSymbolAddress((void**)&wch, g_wch);
    cudaGetSymbolAddress((void**)&bc, g_bcat);

    const int SM_QKV = 4 * 2 * PL;      // 81920 -> 2 CTA/SM
    const int SM_SAV = 4 * 2 * PL;      // 81920 -> 2 CTA/SM
    const int SM_FIN = 66560;           // epilogue tile bound; 3 stages x 2 planes = 61440 fits

    cudaFuncSetAttribute(mma_k<0,0,4,2,80,0>, cudaFuncAttributeMaxDynamicSharedMemorySize, SM_QKV);
    cudaFuncSetAttribute(mma_k<0,0,4,2,2,0>,  cudaFuncAttributeMaxDynamicSharedMemorySize, SM_SAV);
    cudaFuncSetAttribute(mma_k<0,0,4,2,96,0>, cudaFuncAttributeMaxDynamicSharedMemorySize, SM_SAV);
    cudaFuncSetAttribute(mma_k<0,0,3,2,8,1>,  cudaFuncAttributeMaxDynamicSharedMemorySize, SM_FIN);

    const long long TT = (long long)HW * Cc;            // 524288
    const long long TT384 = (long long)HW * 384;        // 1572864
    const long long SS = (long long)HW * HW;
    const long long XS = (long long)HW * 512;

    pack_wqkv<<<384, 256>>>(wq1, wk1, wv1, wq2, wk2, wv2,
                            bq1, bk1, bv1, bq2, bk2, bv2, wAh, wAl, bqkv);
    packw<<<512, 256>>>(wpj, bpj, wr1, br1, wr2, br2, wch, bc);
    bn_dw_kernel<<<1024, 256>>>(F_i, F_w, bn1g, bn2g, bn1b, bn2b, bn1m, bn2m,
                                bn1v, bn2v, wd1, wd2, bd1, bd2, dwraw);
    tsplit_k<<<dim3(128, 4, 8), 256>>>(dwraw, dwTh, TT);
    tres_k<<<dim3(128, 4, 8), 256>>>(F_i, F_w, xTh);

    // QKV merged: M=384 (Q|K|V), N=4096, K=128, z = branch*4+batch  (1-pass)
    mma_k<0,0,4,2,80,0><<<dim3(32, 3, 8), 256, SM_QKV>>>(
        wAh, wAh, dwTh, dwTh, (float*)vraw, qTh, qTl, bqkv, 0,
        128, 128, 384, 128, 49152, TT, TT384,
        2, 0, 255, 0, TT, HW, 384);

    // S merged: z = attn*4+batch; A=Q hi (own), B=K hi (other, log2e-scaled)  (1-pass)
    mma_k<0,0,4,2,2,0><<<dim3(32, 32, 8), 256, SM_SAV>>>(
        qTh, qTh, qTh + 128, qTh + 128, 0, Eh, 0, 0, part,
        384, 384, HW, 128, TT384, TT384, SS,
        0, 4, 255, 0, 0, 0, 0);

    rcpsum<<<128, 256>>>(part, sum);
    vscale<<<2048, 256>>>((const uint4*)vraw, (const float4*)sum, (uint4*)vh);

    // AV merged (flipped): D[m][c] = sum_n Eh[m][n]*Vh[c][n]; fp16-hi store -> xT
    mma_k<0,0,4,2,96,0><<<dim3(1, 32, 8), 256, SM_SAV>>>(
        Eh, Eh, vh, vh, 0, xTh, xTh, 0, 0,
        HW, HW, 512, HW, SS, TT, XS,
        0, 4, 3, 128, 0, 0, 0);

    // out = wcat(fp16) @ xT^T(fp16) + bcat : M=256, N=4096, K=512  (1-pass fp16)
    mma_k<0,0,3,2,8,1><<<dim3(32, 2, 4), 256, SM_FIN>>>(
        wch, wch, xTh, xTh, (float*)d_out, 0, 0, bc, 0,
        512, 512, HW, 512, 0, XS, (long long)OUTC * HW,
        0, 0, 255, 0, 0, 0, 0);
}

// round 14
// speedup vs baseline: 6.4045x; 1.0156x over previous
#include <cuda_runtime.h>
#include <cuda_fp16.h>
#include <cstdint>
#include <math.h>

typedef unsigned short ush;
#define HW 4096
#define Cc 128
#define Bn 4
#define OUTC 256
#define EPSf 1e-5f
#define PL 10240

// ---------------- scratch ----------------
__device__ ush   g_dwraw[2*Bn*Cc*HW];             // bn+dw output, bf16-hi [br][b][c][pix]
__device__ ush   g_dwTh[2*Bn*Cc*HW];              // transposed [br][b][pix][c]
__device__ ush   g_wAh[2*384*128],   g_wAl[2*384*128];
__device__ float g_bqkv[2*384];
__device__ ush   g_qkvTh[2ll*Bn*HW*384], g_qkvTl[2ll*Bn*HW*384];  // [br][B][pix][Q|K|V]
__device__ ush   g_vraw[2*Bn*Cc*HW];              // V bf16-hi, unscaled
__device__ ush   g_vh[2*Bn*Cc*HW];                // V*rs bf16-hi
__device__ ush   g_Eh[134217728];                 // [attn][B][key][query] bf16
__device__ float g_part[64*8*HW];
__device__ float g_sum[8*HW];
__device__ ush   g_xTh[Bn*HW*512];                // fp16 plane
__device__ ush   g_wch[OUTC*512];                 // fp16 plane
__device__ float g_bcat[OUTC];

__device__ __forceinline__ uint32_t smem_u32(const void* p) {
    uint32_t a;
    asm("{ .reg .u64 t; cvta.to.shared.u64 t, %1; cvt.u32.u64 %0, t; }" : "=r"(a) : "l"(p));
    return a;
}
__device__ __forceinline__ uint32_t bfh(float x) {
    uint32_t u = __float_as_uint(x);
    return (u + 0x7FFFu + ((u >> 16) & 1)) & 0xFFFF0000u;
}
__device__ __forceinline__ ush f16b(float x) {
    return __half_as_ushort(__float2half_rn(x));
}
__device__ __forceinline__ void ldmx4(uint32_t* r, uint32_t a) {
    asm volatile("ldmatrix.sync.aligned.m8n8.x4.shared.b16 {%0,%1,%2,%3}, [%4];"
        : "=r"(r[0]), "=r"(r[1]), "=r"(r[2]), "=r"(r[3]) : "r"(a));
}
__device__ __forceinline__ void mma_bf(float* d, const uint32_t* a, const uint32_t* b) {
    asm volatile("mma.sync.aligned.m16n8k16.row.col.f32.bf16.bf16.f32 "
        "{%0,%1,%2,%3}, {%4,%5,%6,%7}, {%8,%9}, {%0,%1,%2,%3};"
        : "+f"(d[0]), "+f"(d[1]), "+f"(d[2]), "+f"(d[3])
        : "r"(a[0]), "r"(a[1]), "r"(a[2]), "r"(a[3]), "r"(b[0]), "r"(b[1]));
}
__device__ __forceinline__ void mma_hf(float* d, const uint32_t* a, const uint32_t* b) {
    asm volatile("mma.sync.aligned.m16n8k16.row.col.f32.f16.f16.f32 "
        "{%0,%1,%2,%3}, {%4,%5,%6,%7}, {%8,%9}, {%0,%1,%2,%3};"
        : "+f"(d[0]), "+f"(d[1]), "+f"(d[2]), "+f"(d[3])
        : "r"(a[0]), "r"(a[1]), "r"(a[2]), "r"(a[3]), "r"(b[0]), "r"(b[1]));
}
#define CP16(d, s) asm volatile("cp.async.cg.shared.global [%0], [%1], 16;" :: "r"(d), "l"(s))
#define CPCOMMIT() asm volatile("cp.async.commit_group;" ::: "memory")
template <int N>
__device__ __forceinline__ void cp_wait() {
    asm volatile("cp.async.wait_group %0;" :: "n"(N) : "memory");
}

// ===== cp.async pipelined warp-MMA GEMM: D[m][n] = sum_k A[m][k]*B[n][k] =====
// AL: al*bh pass; BL: ah*bl pass; NST: stages; MB: min blocks/SM; H16: fp16 mma
// FLG: 2=exp2+colsum+bf16hi trans store(E) | 16=QKV mixed | 32=row fp16 store(AV)
//      | 8=fp32 row store | 64=skip lo-plane store
template <int AL, int BL, int NST, int MB, int FLG, int H16>
__global__ void __launch_bounds__(256, MB) mma_k(
    const ush* __restrict__ Ah, const ush* __restrict__ Al,
    const ush* __restrict__ Bh, const ush* __restrict__ Bl,
    float* __restrict__ Cf, ush* __restrict__ Ch, ush* __restrict__ Cl,
    const float* __restrict__ bias, float* __restrict__ part,
    int lda, int ldb, int ldc, int K,
    long long bsA, long long bsB, long long bsC,
    int zshA, int zxB, int zmC, int cshift,
    long long bsC2, int ldc2, int bstride)
{
    constexpr int BHO  = (1 + AL) * PL;
    constexpr int STGB = (2 + AL + BL) * PL;
    extern __shared__ char sm[];
    float* smf = (float*)sm;
    uint32_t su = smem_u32(sm);
    int tid = threadIdx.x, lane = tid & 31, w = tid >> 5;
    int wm = w & 3, wn = w >> 2;
    int m0 = blockIdx.y * 128, n0 = blockIdx.x * 128;
    long long z = blockIdx.z;

    const ush* pAh = Ah + (z >> zshA) * bsA;
    const ush* pAl = Al + (z >> zshA) * bsA;
    long long zB = z ^ zxB;
    const ush* pBh = Bh + zB * bsB;
    const ush* pBl = Bl + zB * bsB;
    long long zC = z & zmC;
    int colofs = (int)(z >> 2) * cshift;

    float acc[2][8][4];
#pragma unroll
    for (int a = 0; a < 2; a++)
#pragma unroll
        for (int b = 0; b < 8; b++)
#pragma unroll
            for (int c = 0; c < 4; c++) acc[a][b][c] = 0.f;

    int nch = K >> 5;

    auto cpstage = [&](int ch) {
        uint32_t dst = su + (ch % NST) * STGB;
        int k0 = ch << 5;
#pragma unroll
        for (int i = 0; i < 2; i++) {
            int idx = tid + (i << 8);
            int r = idx >> 2, c8 = (idx & 3) << 3;
            uint32_t doff = r * 80 + (c8 << 1);
            CP16(dst + doff,       pAh + (long long)(m0 + r) * lda + k0 + c8);
            if (AL)
                CP16(dst + PL + doff,  pAl + (long long)(m0 + r) * lda + k0 + c8);
            CP16(dst + BHO + doff, pBh + (long long)(n0 + r) * ldb + k0 + c8);
            if (BL)
                CP16(dst + BHO + PL + doff, pBl + (long long)(n0 + r) * ldb + k0 + c8);
        }
    };
    auto consume = [&](int ch) {
        uint32_t sst = su + (ch % NST) * STGB;
#pragma unroll
        for (int kk = 0; kk < 32; kk += 16) {
            uint32_t ah[2][4], al[2][4], bh[4][4], bl[4][4];
            int rA = (lane & 7) + ((lane >> 3) & 1) * 8;
            int kA = kk + (lane >> 4) * 8;
#pragma unroll
            for (int mt = 0; mt < 2; mt++) {
                uint32_t ad = sst + (wm * 32 + mt * 16 + rA) * 80 + kA * 2;
                ldmx4(ah[mt], ad);
                if (AL) ldmx4(al[mt], ad + PL);
            }
            int rB = (lane & 7) + (lane >> 4) * 8;
            int kB = kk + ((lane >> 3) & 1) * 8;
#pragma unroll
            for (int nt = 0; nt < 4; nt++) {
                uint32_t bd = sst + BHO + (wn * 64 + nt * 16 + rB) * 80 + kB * 2;
                ldmx4(bh[nt], bd);
                if (BL) ldmx4(bl[nt], bd + PL);
            }
#pragma unroll
            for (int mt = 0; mt < 2; mt++)
#pragma unroll
                for (int nt = 0; nt < 8; nt++) {
                    const uint32_t* ph = &bh[nt >> 1][(nt & 1) * 2];
                    const uint32_t* pl = &bl[nt >> 1][(nt & 1) * 2];
                    if (H16) {
                        mma_hf(acc[mt][nt], ah[mt], ph);
                        if (BL) mma_hf(acc[mt][nt], ah[mt], pl);
                        if (AL) mma_hf(acc[mt][nt], al[mt], ph);
                    } else {
                        mma_bf(acc[mt][nt], ah[mt], ph);
                        if (BL) mma_bf(acc[mt][nt], ah[mt], pl);
                        if (AL) mma_bf(acc[mt][nt], al[mt], ph);
                    }
                }
        }
    };

    // single-barrier pipeline
#pragma unroll
    for (int s = 0; s < NST - 1; s++) { cpstage(s); CPCOMMIT(); }
    for (int ch = 0; ch < nch; ch++) {
        cp_wait<NST - 2>();
        __syncthreads();
        consume(ch);
        if (ch + NST - 1 < nch) cpstage(ch + NST - 1);
        CPCOMMIT();
    }

    // acc -> smem fp32 tile (stride 130)
    __syncthreads();
#pragma unroll
    for (int mt = 0; mt < 2; mt++)
#pragma unroll
        for (int nt = 0; nt < 8; nt++) {
            int r = wm * 32 + mt * 16 + (lane >> 2);
            int c = wn * 64 + nt * 8 + 2 * (lane & 3);
            *(float2*)&smf[r * 130 + c]       = make_float2(acc[mt][nt][0], acc[mt][nt][1]);
            *(float2*)&smf[(r + 8) * 130 + c] = make_float2(acc[mt][nt][2], acc[mt][nt][3]);
        }
    __syncthreads();

    if (FLG & 2) {               // S: exp2 + colsum + bf16-hi trans store (K pre-scaled by log2e)
        int r = tid & 127, hf = tid >> 7;
        float lsum = 0.f;
        ush* co = Ch + zC * bsC;
        int j0 = hf * 64;
#pragma unroll 4
        for (int j = j0; j < j0 + 64; j++) {
            float e = exp2f(fminf(smf[r * 130 + j], 86.0f));
            lsum += e;
            co[(long long)(n0 + j) * ldc + m0 + r] = (ush)(bfh(e) >> 16);
        }
        part[((long long)blockIdx.x * 2 + hf) * (8 * HW) + z * HW + m0 + r] = lsum;
    } else if (FLG & 32) {       // AV: row fp16 store (hi only when FLG&64)
        ush* ch2 = Ch + zC * bsC;
        ush* cl2 = Cl + zC * bsC;
#pragma unroll 4
        for (int i = tid; i < 16384; i += 256) {
            int r = i >> 7, c = i & 127;
            float v = smf[r * 130 + c];
            long long o = (long long)(m0 + r) * ldc + colofs + n0 + c;
            ush hb = f16b(v);
            ch2[o] = hb;
            if (!(FLG & 64))
                cl2[o] = f16b(v - __half2float(__ushort_as_half(hb)));
        }
    } else if (FLG & 16) {       // QKV mixed
        if (blockIdx.y == 2) {   // V rows: bf16-hi row store
            ush* cv = (ush*)Cf + z * bsC2;
#pragma unroll 4
            for (int i = tid; i < 16384; i += 256) {
                int r = i >> 7, c = i & 127;
                float v = smf[r * 130 + c] + bias[(z >> zshA) * bstride + m0 + r];
                cv[(long long)r * ldc2 + n0 + c] = (ush)(bfh(v) >> 16);
            }
        } else {                 // Q/K: trans bf16-hi store + bias
            int r = tid & 127, hf = tid >> 7;
            float bb = bias[(z >> zshA) * bstride + m0 + r];
            ush* ch2 = Ch + zC * bsC;
            ush* cl2 = Cl + zC * bsC;
            int j0 = hf * 64;
#pragma unroll 4
            for (int j = j0; j < j0 + 64; j++) {
                float v = smf[r * 130 + j] + bb;
                long long o = (long long)(n0 + j) * ldc + m0 + r;
                uint32_t hb = bfh(v);
                ch2[o] = (ush)(hb >> 16);
                if (!(FLG & 64))
                    cl2[o] = (ush)(bfh(v - __int_as_float(hb)) >> 16);
            }
        }
    } else {                     // fp32 row store + bias (final)
        float* cf = Cf + zC * bsC;
#pragma unroll 4
        for (int i = tid; i < 16384; i += 256) {
            int r = i >> 7, c = i & 127;
            cf[(long long)(m0 + r) * ldc + n0 + c] =
                smf[r * 130 + c] + bias[(z >> zshA) * bstride + m0 + r];
        }
    }
}

// ===== merged prep kernel: bn_dw (2048) | tres (4096) | pack_wqkv (384) | packw (512) =====
__global__ void __launch_bounds__(256) prep_k(
    const float* __restrict__ F_i, const float* __restrict__ F_w,
    const float* __restrict__ g0, const float* __restrict__ g1,
    const float* __restrict__ b0, const float* __restrict__ b1,
    const float* __restrict__ m0p, const float* __restrict__ m1p,
    const float* __restrict__ v0, const float* __restrict__ v1,
    const float* __restrict__ w0p, const float* __restrict__ w1p,
    const float* __restrict__ d0, const float* __restrict__ d1,
    ush* __restrict__ dwraw, ush* __restrict__ xh,
    const float* __restrict__ wq1, const float* __restrict__ wk1, const float* __restrict__ wv1,
    const float* __restrict__ wq2, const float* __restrict__ wk2, const float* __restrict__ wv2,
    const float* __restrict__ bq1, const float* __restrict__ bk1, const float* __restrict__ bv1,
    const float* __restrict__ bq2, const float* __restrict__ bk2, const float* __restrict__ bv2,
    ush* __restrict__ wAh, ush* __restrict__ wAl, float* __restrict__ bqkv,
    const float* __restrict__ wp, const float* __restrict__ bp,
    const float* __restrict__ w1r, const float* __restrict__ b1r,
    const float* __restrict__ w2r, const float* __restrict__ b2r,
    ush* __restrict__ wh, float* __restrict__ bc)
{
    __shared__ float buf[34 * 66];     // bn: 34x66 halo tile; tres reuses as 32x33
    int bid = blockIdx.x, tid = threadIdx.x;

    if (bid < 2048) {
        // ---- bn + depthwise 3x3, half-channel (32 rows) per block ----
        int bc2 = bid >> 1, half = bid & 1;
        int sel = bc2 >> 9, lc = bc2 & 511, c = bc2 & 127;
        int r0 = half * 32;
        const float* xp = (sel ? F_w : F_i) + (size_t)lc * HW;
        const float* g = sel ? g1 : g0; const float* b = sel ? b1 : b0;
        const float* m = sel ? m1p : m0p; const float* v = sel ? v1 : v0;
        const float* wdw = sel ? w1p : w0p; const float* bdw = sel ? d1 : d0;
        float sc = g[c] * rsqrtf(v[c] + EPSf), sh = b[c] - m[c] * sc;
        for (int i = tid; i < 34 * 66; i += 256) {
            int r = i / 66 - 1 + r0, cl = i % 66 - 1;
            buf[i] = (r >= 0 && r < 64 && cl >= 0 && cl < 64) ? xp[r * 64 + cl] * sc + sh : 0.f;
        }
        __syncthreads();
        float w0 = wdw[c*9], w1 = wdw[c*9+1], w2 = wdw[c*9+2], w3 = wdw[c*9+3], w4 = wdw[c*9+4];
        float w5 = wdw[c*9+5], w6 = wdw[c*9+6], w7 = wdw[c*9+7], w8 = wdw[c*9+8], bb = bdw[c];
        ush* yp = dwraw + (size_t)bc2 * HW + r0 * 64;
        for (int i = tid; i < 2048; i += 256) {
            const float* t = &buf[(i >> 6) * 66 + (i & 63)];
            float s = bb + t[0]*w0 + t[1]*w1 + t[2]*w2 + t[66]*w3 + t[67]*w4 + t[68]*w5
                         + t[132]*w6 + t[133]*w7 + t[134]*w8;
            yp[i] = (ush)(bfh(s) >> 16);
        }
    } else if (bid < 6144) {
        // ---- residual transpose -> fp16 plane of xT ----
        int idx = bid - 2048;
        int px = idx & 127, cy = (idx >> 7) & 3, z = idx >> 9;
        int br = z >> 2, bb = z & 3;
        const float* src = (br ? F_w : F_i) + (long long)bb * Cc * HW;
        float (*t)[33] = (float(*)[33])buf;
        int p0 = px * 32, c0 = cy * 32;
        int x = tid & 31, y = tid >> 5;
#pragma unroll
        for (int i = 0; i < 32; i += 8) t[y + i][x] = src[(long long)(c0 + y + i) * HW + p0 + x];
        __syncthreads();
#pragma unroll
        for (int i = 0; i < 32; i += 8) {
            long long o = ((long long)bb * HW + p0 + y + i) * 512 + 256 + br * 128 + c0 + x;
            xh[o] = f16b(t[x][y + i]);
        }
    } else if (bid < 6528) {
        // ---- pack stacked QKV weights; K-block pre-scaled by log2(e) ----
        int i = (bid - 6144) * 256 + tid;
        int br = i / 49152, rem = i % 49152, r = rem >> 7, c = rem & 127;
        const float* w; const float* bs;
        if (br == 0) { w = r < 128 ? wq1 : r < 256 ? wk1 : wv1; bs = r < 128 ? bq1 : r < 256 ? bk1 : bv1; }
        else         { w = r < 128 ? wq2 : r < 256 ? wk2 : wv2; bs = r < 128 ? bq2 : r < 256 ? bk2 : bv2; }
        float scl = (r >= 128 && r < 256) ? 1.44269504088896f : 1.f;
        float v = w[(r & 127) * 128 + c] * scl;
        uint32_t hb = bfh(v);
        wAh[i] = (ush)(hb >> 16);
        wAl[i] = (ush)(bfh(v - __int_as_float(hb)) >> 16);
        if (c == 0) bqkv[br * 384 + r] = bs[r & 127] * scl;
    } else {
        // ---- pack fused output weight (fp16) + bias ----
        int i = (bid - 6528) * 256 + tid;
        if (i < OUTC * 512) {
            int o = i >> 9, k = i & 511;
            float v = (k < 256) ? wp[o * 256 + k] : (k < 384) ? w1r[o * 128 + k - 256] : w2r[o * 128 + k - 384];
            wh[i] = f16b(v);
            if (k == 0) bc[o] = bp[o] + b1r[o] + b2r[o];
        }
    }
}

// ---- transpose ush [128][HW] -> [HW][128] ----
__global__ void __launch_bounds__(256) tsplit_k(
    const ush* __restrict__ src, ush* __restrict__ dh, long long bs)
{
    __shared__ ush t[32][34];
    src += blockIdx.z * bs; dh += blockIdx.z * bs;
    int p0 = blockIdx.x * 32, c0 = blockIdx.y * 32;
    int x = threadIdx.x & 31, y = threadIdx.x >> 5;
#pragma unroll
    for (int i = 0; i < 32; i += 8) t[y + i][x] = src[(long long)(c0 + y + i) * HW + p0 + x];
    __syncthreads();
#pragma unroll
    for (int i = 0; i < 32; i += 8)
        dh[(long long)(p0 + y + i) * 128 + c0 + x] = t[x][y + i];
}

// ---- reduce 64 partial colsums -> reciprocal ----
__global__ void __launch_bounds__(256) rcpsum(const float* __restrict__ part, float* __restrict__ sums)
{
    int i = blockIdx.x * 256 + threadIdx.x;    // 32768
    float s = 0.f;
#pragma unroll
    for (int k = 0; k < 64; k++) s += part[(long long)k * 32768 + i];
    sums[i] = 1.f / s;
}

// ---- fold rs into V (bf16 in, bf16 out); 524288 uint4 total ----
__global__ void __launch_bounds__(256) vscale(
    const uint4* __restrict__ vraw, const float4* __restrict__ rs4,
    uint4* __restrict__ vh)
{
    int i = blockIdx.x * 256 + threadIdx.x;    // 524,288 x uint4 (8 ush each)
    int n8 = i & 511, tb = i >> 16;
    uint4 a = vraw[i];
    float4 r0 = rs4[(((tb ^ 4) << 10)) + n8 * 2];
    float4 r1 = rs4[(((tb ^ 4) << 10)) + n8 * 2 + 1];
    uint4 o;
    {
        float f0 = __int_as_float((a.x & 0xFFFFu) << 16) * r0.x;
        float f1 = __int_as_float(a.x & 0xFFFF0000u) * r0.y;
        o.x = (bfh(f0) >> 16) | bfh(f1);
        float f2 = __int_as_float((a.y & 0xFFFFu) << 16) * r0.z;
        float f3 = __int_as_float(a.y & 0xFFFF0000u) * r0.w;
        o.y = (bfh(f2) >> 16) | bfh(f3);
        float f4 = __int_as_float((a.z & 0xFFFFu) << 16) * r1.x;
        float f5 = __int_as_float(a.z & 0xFFFF0000u) * r1.y;
        o.z = (bfh(f4) >> 16) | bfh(f5);
        float f6 = __int_as_float((a.w & 0xFFFFu) << 16) * r1.z;
        float f7 = __int_as_float(a.w & 0xFFFF0000u) * r1.w;
        o.w = (bfh(f6) >> 16) | bfh(f7);
    }
    vh[i] = o;
}

extern "C" void kernel_launch(void* const* d_in, const int* in_sizes, int n_in,
                              void* d_out, int out_size)
{
    const float *F_i = (const float*)d_in[0], *F_w = (const float*)d_in[1];
    const float *bn1g = (const float*)d_in[2], *bn1b = (const float*)d_in[3];
    const float *bn1m = (const float*)d_in[4], *bn1v = (const float*)d_in[5];
    const float *bn2g = (const float*)d_in[6], *bn2b = (const float*)d_in[7];
    const float *bn2m = (const float*)d_in[8], *bn2v = (const float*)d_in[9];
    const float *wq1 = (const float*)d_in[10], *bq1 = (const float*)d_in[11];
    const float *wk1 = (const float*)d_in[12], *bk1 = (const float*)d_in[13];
    const float *wv1 = (const float*)d_in[14], *bv1 = (const float*)d_in[15];
    const float *wq2 = (const float*)d_in[16], *bq2 = (const float*)d_in[17];
    const float *wk2 = (const float*)d_in[18], *bk2 = (const float*)d_in[19];
    const float *wv2 = (const float*)d_in[20], *bv2 = (const float*)d_in[21];
    const float *wd1 = (const float*)d_in[22], *bd1 = (const float*)d_in[23];
    const float *wd2 = (const float*)d_in[24], *bd2 = (const float*)d_in[25];
    const float *wpj = (const float*)d_in[26], *bpj = (const float*)d_in[27];
    const float *wr1 = (const float*)d_in[28], *br1 = (const float*)d_in[29];
    const float *wr2 = (const float*)d_in[30], *br2 = (const float*)d_in[31];

    float *part, *sum, *bqkv, *bc;
    ush *dwraw, *dwTh, *wAh, *wAl, *qTh, *qTl, *vraw, *vh, *Eh, *xTh, *wch;
    cudaGetSymbolAddress((void**)&dwraw, g_dwraw);
    cudaGetSymbolAddress((void**)&dwTh, g_dwTh);
    cudaGetSymbolAddress((void**)&wAh, g_wAh);   cudaGetSymbolAddress((void**)&wAl, g_wAl);
    cudaGetSymbolAddress((void**)&bqkv, g_bqkv);
    cudaGetSymbolAddress((void**)&qTh, g_qkvTh); cudaGetSymbolAddress((void**)&qTl, g_qkvTl);
    cudaGetSymbolAddress((void**)&vraw, g_vraw);
    cudaGetSymbolAddress((void**)&vh, g_vh);
    cudaGetSymbolAddress((void**)&Eh, g_Eh);
    cudaGetSymbolAddress((void**)&part, g_part); cudaGetSymbolAddress((void**)&sum, g_sum);
    cudaGetSymbolAddress((void**)&xTh, g_xTh);
    cudaGetSymbolAddress((void**)&wch, g_wch);
    cudaGetSymbolAddress((void**)&bc, g_bcat);

    const int SM_QKV = 4 * 2 * PL;      // 81920 -> 2 CTA/SM
    const int SM_SAV = 4 * 2 * PL;      // 81920 -> 2 CTA/SM
    const int SM_FIN = 66560;           // epilogue tile bound; 3 stages x 2 planes fits

    cudaFuncSetAttribute(mma_k<0,0,4,2,80,0>, cudaFuncAttributeMaxDynamicSharedMemorySize, SM_QKV);
    cudaFuncSetAttribute(mma_k<0,0,4,2,2,0>,  cudaFuncAttributeMaxDynamicSharedMemorySize, SM_SAV);
    cudaFuncSetAttribute(mma_k<0,0,4,2,96,0>, cudaFuncAttributeMaxDynamicSharedMemorySize, SM_SAV);
    cudaFuncSetAttribute(mma_k<0,0,3,2,8,1>,  cudaFuncAttributeMaxDynamicSharedMemorySize, SM_FIN);

    const long long TT = (long long)HW * Cc;            // 524288
    const long long TT384 = (long long)HW * 384;        // 1572864
    const long long SS = (long long)HW * HW;
    const long long XS = (long long)HW * 512;

    // merged prep: bn_dw(2048) + tres(4096) + pack_wqkv(384) + packw(512)
    prep_k<<<7040, 256>>>(
        F_i, F_w, bn1g, bn2g, bn1b, bn2b, bn1m, bn2m, bn1v, bn2v,
        wd1, wd2, bd1, bd2, dwraw, xTh,
        wq1, wk1, wv1, wq2, wk2, wv2, bq1, bk1, bv1, bq2, bk2, bv2,
        wAh, wAl, bqkv,
        wpj, bpj, wr1, br1, wr2, br2, wch, bc);

    tsplit_k<<<dim3(128, 4, 8), 256>>>(dwraw, dwTh, TT);

    // QKV merged: M=384 (Q|K|V), N=4096, K=128, z = branch*4+batch  (1-pass)
    mma_k<0,0,4,2,80,0><<<dim3(32, 3, 8), 256, SM_QKV>>>(
        wAh, wAh, dwTh, dwTh, (float*)vraw, qTh, qTl, bqkv, 0,
        128, 128, 384, 128, 49152, TT, TT384,
        2, 0, 255, 0, TT, HW, 384);

    // S merged: z = attn*4+batch; A=Q hi (own), B=K hi (other, log2e-scaled)  (1-pass)
    mma_k<0,0,4,2,2,0><<<dim3(32, 32, 8), 256, SM_SAV>>>(
        qTh, qTh, qTh + 128, qTh + 128, 0, Eh, 0, 0, part,
        384, 384, HW, 128, TT384, TT384, SS,
        0, 4, 255, 0, 0, 0, 0);

    rcpsum<<<128, 256>>>(part, sum);
    vscale<<<2048, 256>>>((const uint4*)vraw, (const float4*)sum, (uint4*)vh);

    // AV merged (flipped): D[m][c] = sum_n Eh[m][n]*Vh[c][n]; fp16-hi store -> xT
    mma_k<0,0,4,2,96,0><<<dim3(1, 32, 8), 256, SM_SAV>>>(
        Eh, Eh, vh, vh, 0, xTh, xTh, 0, 0,
        HW, HW, 512, HW, SS, TT, XS,
        0, 4, 3, 128, 0, 0, 0);

    // out = wcat(fp16) @ xT^T(fp16) + bcat : M=256, N=4096, K=512  (1-pass fp16)
    mma_k<0,0,3,2,8,1><<<dim3(32, 2, 4), 256, SM_FIN>>>(
        wch, wch, xTh, xTh, (float*)d_out, 0, 0, bc, 0,
        512, 512, HW, 512, 0, XS, (long long)OUTC * HW,
        0, 0, 255, 0, 0, 0, 0);
}

// round 15
// speedup vs baseline: 6.6200x; 1.0337x over previous
#include <cuda_runtime.h>
#include <cuda_fp16.h>
#include <cstdint>
#include <math.h>

typedef unsigned short ush;
#define HW 4096
#define Cc 128
#define Bn 4
#define OUTC 256
#define EPSf 1e-5f
#define PL 10240

// ---------------- scratch ----------------
__device__ ush   g_dwraw[2*Bn*Cc*HW];
__device__ ush   g_dwTh[2*Bn*Cc*HW];
__device__ ush   g_wAh[2*384*128],   g_wAl[2*384*128];
__device__ float g_bqkv[2*384];
__device__ ush   g_qkvTh[2ll*Bn*HW*384], g_qkvTl[2ll*Bn*HW*384];
__device__ ush   g_vraw[2*Bn*Cc*HW];
__device__ ush   g_vh[2*Bn*Cc*HW];
__device__ ush   g_Eh[134217728];                 // [attn][B][key][query] bf16
__device__ float g_part[128*8*HW];
__device__ float g_sum[8*HW];
__device__ ush   g_xTh[Bn*HW*512];                // fp16 plane
__device__ ush   g_wch[OUTC*512];                 // fp16 plane
__device__ float g_bcat[OUTC];

__device__ __forceinline__ uint32_t smem_u32(const void* p) {
    uint32_t a;
    asm("{ .reg .u64 t; cvta.to.shared.u64 t, %1; cvt.u32.u64 %0, t; }" : "=r"(a) : "l"(p));
    return a;
}
__device__ __forceinline__ uint32_t bfh(float x) {
    uint32_t u = __float_as_uint(x);
    return (u + 0x7FFFu + ((u >> 16) & 1)) & 0xFFFF0000u;
}
__device__ __forceinline__ ush f16b(float x) {
    return __half_as_ushort(__float2half_rn(x));
}
__device__ __forceinline__ void ldmx4(uint32_t* r, uint32_t a) {
    asm volatile("ldmatrix.sync.aligned.m8n8.x4.shared.b16 {%0,%1,%2,%3}, [%4];"
        : "=r"(r[0]), "=r"(r[1]), "=r"(r[2]), "=r"(r[3]) : "r"(a));
}
__device__ __forceinline__ void mma_bf(float* d, const uint32_t* a, const uint32_t* b) {
    asm volatile("mma.sync.aligned.m16n8k16.row.col.f32.bf16.bf16.f32 "
        "{%0,%1,%2,%3}, {%4,%5,%6,%7}, {%8,%9}, {%0,%1,%2,%3};"
        : "+f"(d[0]), "+f"(d[1]), "+f"(d[2]), "+f"(d[3])
        : "r"(a[0]), "r"(a[1]), "r"(a[2]), "r"(a[3]), "r"(b[0]), "r"(b[1]));
}
__device__ __forceinline__ void mma_hf(float* d, const uint32_t* a, const uint32_t* b) {
    asm volatile("mma.sync.aligned.m16n8k16.row.col.f32.f16.f16.f32 "
        "{%0,%1,%2,%3}, {%4,%5,%6,%7}, {%8,%9}, {%0,%1,%2,%3};"
        : "+f"(d[0]), "+f"(d[1]), "+f"(d[2]), "+f"(d[3])
        : "r"(a[0]), "r"(a[1]), "r"(a[2]), "r"(a[3]), "r"(b[0]), "r"(b[1]));
}
#define CP16(d, s) asm volatile("cp.async.cg.shared.global [%0], [%1], 16;" :: "r"(d), "l"(s))
#define CPCOMMIT() asm volatile("cp.async.commit_group;" ::: "memory")
template <int N>
__device__ __forceinline__ void cp_wait() {
    asm volatile("cp.async.wait_group %0;" :: "n"(N) : "memory");
}

// ===== cp.async pipelined warp-MMA GEMM: D[m][n] = sum_k A[m][k]*B[n][k] =====
// AL/BL: extra passes; NST: stages; MB: min blocks/SM; H16: fp16 mma; FK: K==NST*32 barrier-free
// FLG: 2=exp2+colsum+bf16hi trans store(E) | 16=QKV mixed | 32=row fp16 store(AV)
//      | 8=fp32 row store | 64=skip lo-plane store
template <int AL, int BL, int NST, int MB, int FLG, int H16, int FK>
__global__ void __launch_bounds__(256, MB) mma_k(
    const ush* __restrict__ Ah, const ush* __restrict__ Al,
    const ush* __restrict__ Bh, const ush* __restrict__ Bl,
    float* __restrict__ Cf, ush* __restrict__ Ch, ush* __restrict__ Cl,
    const float* __restrict__ bias, float* __restrict__ part,
    int lda, int ldb, int ldc, int K,
    long long bsA, long long bsB, long long bsC,
    int zshA, int zxB, int zmC, int cshift,
    long long bsC2, int ldc2, int bstride)
{
    constexpr int BHO  = (1 + AL) * PL;
    constexpr int STGB = (2 + AL + BL) * PL;
    extern __shared__ char sm[];
    float* smf = (float*)sm;
    uint32_t su = smem_u32(sm);
    int tid = threadIdx.x, lane = tid & 31, w = tid >> 5;
    int wm = w & 3, wn = w >> 2;
    int m0 = blockIdx.y * 128, n0 = blockIdx.x * 128;
    long long z = blockIdx.z;

    const ush* pAh = Ah + (z >> zshA) * bsA;
    const ush* pAl = Al + (z >> zshA) * bsA;
    long long zB = z ^ zxB;
    const ush* pBh = Bh + zB * bsB;
    const ush* pBl = Bl + zB * bsB;
    long long zC = z & zmC;
    int colofs = (int)(z >> 2) * cshift;

    float acc[2][8][4];
#pragma unroll
    for (int a = 0; a < 2; a++)
#pragma unroll
        for (int b = 0; b < 8; b++)
#pragma unroll
            for (int c = 0; c < 4; c++) acc[a][b][c] = 0.f;

    int nch = K >> 5;

    auto cpstage = [&](int ch) {
        uint32_t dst = su + (ch % NST) * STGB;
        int k0 = ch << 5;
#pragma unroll
        for (int i = 0; i < 2; i++) {
            int idx = tid + (i << 8);
            int r = idx >> 2, c8 = (idx & 3) << 3;
            uint32_t doff = r * 80 + (c8 << 1);
            CP16(dst + doff,       pAh + (long long)(m0 + r) * lda + k0 + c8);
            if (AL)
                CP16(dst + PL + doff,  pAl + (long long)(m0 + r) * lda + k0 + c8);
            CP16(dst + BHO + doff, pBh + (long long)(n0 + r) * ldb + k0 + c8);
            if (BL)
                CP16(dst + BHO + PL + doff, pBl + (long long)(n0 + r) * ldb + k0 + c8);
        }
    };
    auto consume = [&](int ch) {
        uint32_t sst = su + (ch % NST) * STGB;
#pragma unroll
        for (int kk = 0; kk < 32; kk += 16) {
            uint32_t ah[2][4], al[2][4], bh[4][4], bl[4][4];
            int rA = (lane & 7) + ((lane >> 3) & 1) * 8;
            int kA = kk + (lane >> 4) * 8;
#pragma unroll
            for (int mt = 0; mt < 2; mt++) {
                uint32_t ad = sst + (wm * 32 + mt * 16 + rA) * 80 + kA * 2;
                ldmx4(ah[mt], ad);
                if (AL) ldmx4(al[mt], ad + PL);
            }
            int rB = (lane & 7) + (lane >> 4) * 8;
            int kB = kk + ((lane >> 3) & 1) * 8;
#pragma unroll
            for (int nt = 0; nt < 4; nt++) {
                uint32_t bd = sst + BHO + (wn * 64 + nt * 16 + rB) * 80 + kB * 2;
                ldmx4(bh[nt], bd);
                if (BL) ldmx4(bl[nt], bd + PL);
            }
#pragma unroll
            for (int mt = 0; mt < 2; mt++)
#pragma unroll
                for (int nt = 0; nt < 8; nt++) {
                    const uint32_t* ph = &bh[nt >> 1][(nt & 1) * 2];
                    const uint32_t* pl = &bl[nt >> 1][(nt & 1) * 2];
                    if (H16) {
                        mma_hf(acc[mt][nt], ah[mt], ph);
                        if (BL) mma_hf(acc[mt][nt], ah[mt], pl);
                        if (AL) mma_hf(acc[mt][nt], al[mt], ph);
                    } else {
                        mma_bf(acc[mt][nt], ah[mt], ph);
                        if (BL) mma_bf(acc[mt][nt], ah[mt], pl);
                        if (AL) mma_bf(acc[mt][nt], al[mt], ph);
                    }
                }
        }
    };

    if (FK) {
        // whole K fits in the NST stages: one wait, one barrier, barrier-free consume
#pragma unroll
        for (int s = 0; s < NST; s++) { cpstage(s); CPCOMMIT(); }
        cp_wait<0>();
        __syncthreads();
#pragma unroll
        for (int ch = 0; ch < NST; ch++) consume(ch);
    } else {
#pragma unroll
        for (int s = 0; s < NST - 1; s++) { cpstage(s); CPCOMMIT(); }
        for (int ch = 0; ch < nch; ch++) {
            cp_wait<NST - 2>();
            __syncthreads();
            consume(ch);
            if (ch + NST - 1 < nch) cpstage(ch + NST - 1);
            CPCOMMIT();
        }
    }

    // acc -> smem fp32 tile (stride 130)
    __syncthreads();
#pragma unroll
    for (int mt = 0; mt < 2; mt++)
#pragma unroll
        for (int nt = 0; nt < 8; nt++) {
            int r = wm * 32 + mt * 16 + (lane >> 2);
            int c = wn * 64 + nt * 8 + 2 * (lane & 3);
            *(float2*)&smf[r * 130 + c]       = make_float2(acc[mt][nt][0], acc[mt][nt][1]);
            *(float2*)&smf[(r + 8) * 130 + c] = make_float2(acc[mt][nt][2], acc[mt][nt][3]);
        }
    __syncthreads();

    if (FLG & 2) {               // S: exp2 + colsum + packed bf16 trans store (2 rows/thread)
        int r2 = (tid & 63) * 2, hf = tid >> 6;     // hf in 0..3, 32 cols each
        float ls0 = 0.f, ls1 = 0.f;
        ush* co = Ch + zC * bsC;
        int j0 = hf * 32;
#pragma unroll 4
        for (int j = j0; j < j0 + 32; j++) {
            float e0 = exp2f(fminf(smf[r2 * 130 + j], 86.0f));
            float e1 = exp2f(fminf(smf[(r2 + 1) * 130 + j], 86.0f));
            ls0 += e0; ls1 += e1;
            *(uint32_t*)(co + (long long)(n0 + j) * ldc + m0 + r2) =
                (bfh(e0) >> 16) | bfh(e1);
        }
        long long pb = ((long long)blockIdx.x * 4 + hf) * (8 * HW) + z * HW + m0;
        part[pb + r2]     = ls0;
        part[pb + r2 + 1] = ls1;
    } else if (FLG & 32) {       // AV: row fp16 store (hi only when FLG&64)
        ush* ch2 = Ch + zC * bsC;
        ush* cl2 = Cl + zC * bsC;
#pragma unroll 4
        for (int i = tid; i < 16384; i += 256) {
            int r = i >> 7, c = i & 127;
            float v = smf[r * 130 + c];
            long long o = (long long)(m0 + r) * ldc + colofs + n0 + c;
            ush hb = f16b(v);
            ch2[o] = hb;
            if (!(FLG & 64))
                cl2[o] = f16b(v - __half2float(__ushort_as_half(hb)));
        }
    } else if (FLG & 16) {       // QKV mixed
        if (blockIdx.y == 2) {   // V rows: bf16-hi row store
            ush* cv = (ush*)Cf + z * bsC2;
#pragma unroll 4
            for (int i = tid; i < 16384; i += 256) {
                int r = i >> 7, c = i & 127;
                float v = smf[r * 130 + c] + bias[(z >> zshA) * bstride + m0 + r];
                cv[(long long)r * ldc2 + n0 + c] = (ush)(bfh(v) >> 16);
            }
        } else {                 // Q/K: trans bf16-hi store + bias
            int r = tid & 127, hf = tid >> 7;
            float bb = bias[(z >> zshA) * bstride + m0 + r];
            ush* ch2 = Ch + zC * bsC;
            ush* cl2 = Cl + zC * bsC;
            int j0 = hf * 64;
#pragma unroll 4
            for (int j = j0; j < j0 + 64; j++) {
                float v = smf[r * 130 + j] + bb;
                long long o = (long long)(n0 + j) * ldc + m0 + r;
                uint32_t hb = bfh(v);
                ch2[o] = (ush)(hb >> 16);
                if (!(FLG & 64))
                    cl2[o] = (ush)(bfh(v - __int_as_float(hb)) >> 16);
            }
        }
    } else {                     // fp32 row store + bias (final)
        float* cf = Cf + zC * bsC;
#pragma unroll 4
        for (int i = tid; i < 16384; i += 256) {
            int r = i >> 7, c = i & 127;
            cf[(long long)(m0 + r) * ldc + n0 + c] =
                smf[r * 130 + c] + bias[(z >> zshA) * bstride + m0 + r];
        }
    }
}

// ===== merged prep kernel: bn_dw (2048) | tres (4096) | pack_wqkv (384) | packw (512) =====
__global__ void __launch_bounds__(256) prep_k(
    const float* __restrict__ F_i, const float* __restrict__ F_w,
    const float* __restrict__ g0, const float* __restrict__ g1,
    const float* __restrict__ b0, const float* __restrict__ b1,
    const float* __restrict__ m0p, const float* __restrict__ m1p,
    const float* __restrict__ v0, const float* __restrict__ v1,
    const float* __restrict__ w0p, const float* __restrict__ w1p,
    const float* __restrict__ d0, const float* __restrict__ d1,
    ush* __restrict__ dwraw, ush* __restrict__ xh,
    const float* __restrict__ wq1, const float* __restrict__ wk1, const float* __restrict__ wv1,
    const float* __restrict__ wq2, const float* __restrict__ wk2, const float* __restrict__ wv2,
    const float* __restrict__ bq1, const float* __restrict__ bk1, const float* __restrict__ bv1,
    const float* __restrict__ bq2, const float* __restrict__ bk2, const float* __restrict__ bv2,
    ush* __restrict__ wAh, ush* __restrict__ wAl, float* __restrict__ bqkv,
    const float* __restrict__ wp, const float* __restrict__ bp,
    const float* __restrict__ w1r, const float* __restrict__ b1r,
    const float* __restrict__ w2r, const float* __restrict__ b2r,
    ush* __restrict__ wh, float* __restrict__ bc)
{
    __shared__ float buf[34 * 66];
    int bid = blockIdx.x, tid = threadIdx.x;

    if (bid < 2048) {
        int bc2 = bid >> 1, half = bid & 1;
        int sel = bc2 >> 9, lc = bc2 & 511, c = bc2 & 127;
        int r0 = half * 32;
        const float* xp = (sel ? F_w : F_i) + (size_t)lc * HW;
        const float* g = sel ? g1 : g0; const float* b = sel ? b1 : b0;
        const float* m = sel ? m1p : m0p; const float* v = sel ? v1 : v0;
        const float* wdw = sel ? w1p : w0p; const float* bdw = sel ? d1 : d0;
        float sc = g[c] * rsqrtf(v[c] + EPSf), sh = b[c] - m[c] * sc;
        for (int i = tid; i < 34 * 66; i += 256) {
            int r = i / 66 - 1 + r0, cl = i % 66 - 1;
            buf[i] = (r >= 0 && r < 64 && cl >= 0 && cl < 64) ? xp[r * 64 + cl] * sc + sh : 0.f;
        }
        __syncthreads();
        float w0 = wdw[c*9], w1 = wdw[c*9+1], w2 = wdw[c*9+2], w3 = wdw[c*9+3], w4 = wdw[c*9+4];
        float w5 = wdw[c*9+5], w6 = wdw[c*9+6], w7 = wdw[c*9+7], w8 = wdw[c*9+8], bb = bdw[c];
        ush* yp = dwraw + (size_t)bc2 * HW + r0 * 64;
        for (int i = tid; i < 2048; i += 256) {
            const float* t = &buf[(i >> 6) * 66 + (i & 63)];
            float s = bb + t[0]*w0 + t[1]*w1 + t[2]*w2 + t[66]*w3 + t[67]*w4 + t[68]*w5
                         + t[132]*w6 + t[133]*w7 + t[134]*w8;
            yp[i] = (ush)(bfh(s) >> 16);
        }
    } else if (bid < 6144) {
        int idx = bid - 2048;
        int px = idx & 127, cy = (idx >> 7) & 3, z = idx >> 9;
        int br = z >> 2, bb = z & 3;
        const float* src = (br ? F_w : F_i) + (long long)bb * Cc * HW;
        float (*t)[33] = (float(*)[33])buf;
        int p0 = px * 32, c0 = cy * 32;
        int x = tid & 31, y = tid >> 5;
#pragma unroll
        for (int i = 0; i < 32; i += 8) t[y + i][x] = src[(long long)(c0 + y + i) * HW + p0 + x];
        __syncthreads();
#pragma unroll
        for (int i = 0; i < 32; i += 8) {
            long long o = ((long long)bb * HW + p0 + y + i) * 512 + 256 + br * 128 + c0 + x;
            xh[o] = f16b(t[x][y + i]);
        }
    } else if (bid < 6528) {
        int i = (bid - 6144) * 256 + tid;
        int br = i / 49152, rem = i % 49152, r = rem >> 7, c = rem & 127;
        const float* w; const float* bs;
        if (br == 0) { w = r < 128 ? wq1 : r < 256 ? wk1 : wv1; bs = r < 128 ? bq1 : r < 256 ? bk1 : bv1; }
        else         { w = r < 128 ? wq2 : r < 256 ? wk2 : wv2; bs = r < 128 ? bq2 : r < 256 ? bk2 : bv2; }
        float scl = (r >= 128 && r < 256) ? 1.44269504088896f : 1.f;
        float v = w[(r & 127) * 128 + c] * scl;
        uint32_t hb = bfh(v);
        wAh[i] = (ush)(hb >> 16);
        wAl[i] = (ush)(bfh(v - __int_as_float(hb)) >> 16);
        if (c == 0) bqkv[br * 384 + r] = bs[r & 127] * scl;
    } else {
        int i = (bid - 6528) * 256 + tid;
        if (i < OUTC * 512) {
            int o = i >> 9, k = i & 511;
            float v = (k < 256) ? wp[o * 256 + k] : (k < 384) ? w1r[o * 128 + k - 256] : w2r[o * 128 + k - 384];
            wh[i] = f16b(v);
            if (k == 0) bc[o] = bp[o] + b1r[o] + b2r[o];
        }
    }
}

// ---- transpose ush [128][HW] -> [HW][128] ----
__global__ void __launch_bounds__(256) tsplit_k(
    const ush* __restrict__ src, ush* __restrict__ dh, long long bs)
{
    __shared__ ush t[32][34];
    src += blockIdx.z * bs; dh += blockIdx.z * bs;
    int p0 = blockIdx.x * 32, c0 = blockIdx.y * 32;
    int x = threadIdx.x & 31, y = threadIdx.x >> 5;
#pragma unroll
    for (int i = 0; i < 32; i += 8) t[y + i][x] = src[(long long)(c0 + y + i) * HW + p0 + x];
    __syncthreads();
#pragma unroll
    for (int i = 0; i < 32; i += 8)
        dh[(long long)(p0 + y + i) * 128 + c0 + x] = t[x][y + i];
}

// ---- reduce 128 partial colsums -> reciprocal ----
__global__ void __launch_bounds__(256) rcpsum(const float* __restrict__ part, float* __restrict__ sums)
{
    int i = blockIdx.x * 256 + threadIdx.x;    // 32768
    float s = 0.f;
#pragma unroll
    for (int k = 0; k < 128; k++) s += part[(long long)k * 32768 + i];
    sums[i] = 1.f / s;
}

// ---- fold rs into V (bf16 in, bf16 out); 524288 uint4 total ----
__global__ void __launch_bounds__(256) vscale(
    const uint4* __restrict__ vraw, const float4* __restrict__ rs4,
    uint4* __restrict__ vh)
{
    int i = blockIdx.x * 256 + threadIdx.x;
    int n8 = i & 511, tb = i >> 16;
    uint4 a = vraw[i];
    float4 r0 = rs4[(((tb ^ 4) << 10)) + n8 * 2];
    float4 r1 = rs4[(((tb ^ 4) << 10)) + n8 * 2 + 1];
    uint4 o;
    {
        float f0 = __int_as_float((a.x & 0xFFFFu) << 16) * r0.x;
        float f1 = __int_as_float(a.x & 0xFFFF0000u) * r0.y;
        o.x = (bfh(f0) >> 16) | bfh(f1);
        float f2 = __int_as_float((a.y & 0xFFFFu) << 16) * r0.z;
        float f3 = __int_as_float(a.y & 0xFFFF0000u) * r0.w;
        o.y = (bfh(f2) >> 16) | bfh(f3);
        float f4 = __int_as_float((a.z & 0xFFFFu) << 16) * r1.x;
        float f5 = __int_as_float(a.z & 0xFFFF0000u) * r1.y;
        o.z = (bfh(f4) >> 16) | bfh(f5);
        float f6 = __int_as_float((a.w & 0xFFFFu) << 16) * r1.z;
        float f7 = __int_as_float(a.w & 0xFFFF0000u) * r1.w;
        o.w = (bfh(f6) >> 16) | bfh(f7);
    }
    vh[i] = o;
}

extern "C" void kernel_launch(void* const* d_in, const int* in_sizes, int n_in,
                              void* d_out, int out_size)
{
    const float *F_i = (const float*)d_in[0], *F_w = (const float*)d_in[1];
    const float *bn1g = (const float*)d_in[2], *bn1b = (const float*)d_in[3];
    const float *bn1m = (const float*)d_in[4], *bn1v = (const float*)d_in[5];
    const float *bn2g = (const float*)d_in[6], *bn2b = (const float*)d_in[7];
    const float *bn2m = (const float*)d_in[8], *bn2v = (const float*)d_in[9];
    const float *wq1 = (const float*)d_in[10], *bq1 = (const float*)d_in[11];
    const float *wk1 = (const float*)d_in[12], *bk1 = (const float*)d_in[13];
    const float *wv1 = (const float*)d_in[14], *bv1 = (const float*)d_in[15];
    const float *wq2 = (const float*)d_in[16], *bq2 = (const float*)d_in[17];
    const float *wk2 = (const float*)d_in[18], *bk2 = (const float*)d_in[19];
    const float *wv2 = (const float*)d_in[20], *bv2 = (const float*)d_in[21];
    const float *wd1 = (const float*)d_in[22], *bd1 = (const float*)d_in[23];
    const float *wd2 = (const float*)d_in[24], *bd2 = (const float*)d_in[25];
    const float *wpj = (const float*)d_in[26], *bpj = (const float*)d_in[27];
    const float *wr1 = (const float*)d_in[28], *br1 = (const float*)d_in[29];
    const float *wr2 = (const float*)d_in[30], *br2 = (const float*)d_in[31];

    float *part, *sum, *bqkv, *bc;
    ush *dwraw, *dwTh, *wAh, *wAl, *qTh, *qTl, *vraw, *vh, *Eh, *xTh, *wch;
    cudaGetSymbolAddress((void**)&dwraw, g_dwraw);
    cudaGetSymbolAddress((void**)&dwTh, g_dwTh);
    cudaGetSymbolAddress((void**)&wAh, g_wAh);   cudaGetSymbolAddress((void**)&wAl, g_wAl);
    cudaGetSymbolAddress((void**)&bqkv, g_bqkv);
    cudaGetSymbolAddress((void**)&qTh, g_qkvTh); cudaGetSymbolAddress((void**)&qTl, g_qkvTl);
    cudaGetSymbolAddress((void**)&vraw, g_vraw);
    cudaGetSymbolAddress((void**)&vh, g_vh);
    cudaGetSymbolAddress((void**)&Eh, g_Eh);
    cudaGetSymbolAddress((void**)&part, g_part); cudaGetSymbolAddress((void**)&sum, g_sum);
    cudaGetSymbolAddress((void**)&xTh, g_xTh);
    cudaGetSymbolAddress((void**)&wch, g_wch);
    cudaGetSymbolAddress((void**)&bc, g_bcat);

    const int SM_QKV = 4 * 2 * PL;
    const int SM_SAV = 4 * 2 * PL;
    const int SM_FIN = 66560;

    cudaFuncSetAttribute(mma_k<0,0,4,2,80,0,1>, cudaFuncAttributeMaxDynamicSharedMemorySize, SM_QKV);
    cudaFuncSetAttribute(mma_k<0,0,4,2,2,0,1>,  cudaFuncAttributeMaxDynamicSharedMemorySize, SM_SAV);
    cudaFuncSetAttribute(mma_k<0,0,4,2,96,0,0>, cudaFuncAttributeMaxDynamicSharedMemorySize, SM_SAV);
    cudaFuncSetAttribute(mma_k<0,0,3,2,8,1,0>,  cudaFuncAttributeMaxDynamicSharedMemorySize, SM_FIN);

    const long long TT = (long long)HW * Cc;
    const long long TT384 = (long long)HW * 384;
    const long long SS = (long long)HW * HW;
    const long long XS = (long long)HW * 512;

    prep_k<<<7040, 256>>>(
        F_i, F_w, bn1g, bn2g, bn1b, bn2b, bn1m, bn2m, bn1v, bn2v,
        wd1, wd2, bd1, bd2, dwraw, xTh,
        wq1, wk1, wv1, wq2, wk2, wv2, bq1, bk1, bv1, bq2, bk2, bv2,
        wAh, wAl, bqkv,
        wpj, bpj, wr1, br1, wr2, br2, wch, bc);

    tsplit_k<<<dim3(128, 4, 8), 256>>>(dwraw, dwTh, TT);

    // QKV merged: M=384, N=4096, K=128, z = branch*4+batch  (1-pass, FULLK)
    mma_k<0,0,4,2,80,0,1><<<dim3(32, 3, 8), 256, SM_QKV>>>(
        wAh, wAh, dwTh, dwTh, (float*)vraw, qTh, qTl, bqkv, 0,
        128, 128, 384, 128, 49152, TT, TT384,
        2, 0, 255, 0, TT, HW, 384);

    // S merged: z = attn*4+batch  (1-pass, FULLK, vectorized epilogue)
    mma_k<0,0,4,2,2,0,1><<<dim3(32, 32, 8), 256, SM_SAV>>>(
        qTh, qTh, qTh + 128, qTh + 128, 0, Eh, 0, 0, part,
        384, 384, HW, 128, TT384, TT384, SS,
        0, 4, 255, 0, 0, 0, 0);

    rcpsum<<<128, 256>>>(part, sum);
    vscale<<<2048, 256>>>((const uint4*)vraw, (const float4*)sum, (uint4*)vh);

    // AV merged (flipped): D[m][c] = sum_n Eh[m][n]*Vh[c][n]; fp16-hi store -> xT
    mma_k<0,0,4,2,96,0,0><<<dim3(1, 32, 8), 256, SM_SAV>>>(
        Eh, Eh, vh, vh, 0, xTh, xTh, 0, 0,
        HW, HW, 512, HW, SS, TT, XS,
        0, 4, 3, 128, 0, 0, 0);

    // out = wcat(fp16) @ xT^T(fp16) + bcat : M=256, N=4096, K=512  (1-pass fp16)
    mma_k<0,0,3,2,8,1,0><<<dim3(32, 2, 4), 256, SM_FIN>>>(
        wch, wch, xTh, xTh, (float*)d_out, 0, 0, bc, 0,
        512, 512, HW, 512, 0, XS, (long long)OUTC * HW,
        0, 0, 255, 0, 0, 0, 0);
}

// round 16
// speedup vs baseline: 6.9168x; 1.0448x over previous
#include <cuda_runtime.h>
#include <cuda_fp16.h>
#include <cstdint>
#include <math.h>

typedef unsigned short ush;
#define HW 4096
#define Cc 128
#define Bn 4
#define OUTC 256
#define EPSf 1e-5f
#define PL 10240

// ---------------- scratch ----------------
__device__ ush   g_dwraw[2*Bn*Cc*HW];
__device__ ush   g_dwTh[2*Bn*Cc*HW];
__device__ ush   g_wAh[2*384*128],   g_wAl[2*384*128];
__device__ float g_bqkv[2*384];
__device__ ush   g_qkvTh[2ll*Bn*HW*384], g_qkvTl[2ll*Bn*HW*384];
__device__ ush   g_vraw[2*Bn*Cc*HW];
__device__ ush   g_vh[2*Bn*Cc*HW];
__device__ ush   g_Eh[134217728];                 // [attn][B][key][query] bf16
__device__ float g_part[128*8*HW];
__device__ float g_sum[8*HW];
__device__ ush   g_xTh[Bn*HW*512];                // fp16 plane
__device__ ush   g_wch[OUTC*512];                 // fp16 plane
__device__ float g_bcat[OUTC];

__device__ __forceinline__ uint32_t smem_u32(const void* p) {
    uint32_t a;
    asm("{ .reg .u64 t; cvta.to.shared.u64 t, %1; cvt.u32.u64 %0, t; }" : "=r"(a) : "l"(p));
    return a;
}
__device__ __forceinline__ uint32_t bfh(float x) {
    uint32_t u = __float_as_uint(x);
    return (u + 0x7FFFu + ((u >> 16) & 1)) & 0xFFFF0000u;
}
__device__ __forceinline__ ush f16b(float x) {
    return __half_as_ushort(__float2half_rn(x));
}
// pack 2 floats -> bf16x2 (lo = first arg), single cvt instruction (RNE)
__device__ __forceinline__ uint32_t bf2pack(float lo, float hi) {
    uint32_t r;
    asm("cvt.rn.bf16x2.f32 %0, %1, %2;" : "=r"(r) : "f"(hi), "f"(lo));
    return r;
}
__device__ __forceinline__ float ex2f(float x) {
    float y;
    asm("ex2.approx.ftz.f32 %0, %1;" : "=f"(y) : "f"(x));
    return y;
}
__device__ __forceinline__ void ldmx4(uint32_t* r, uint32_t a) {
    asm volatile("ldmatrix.sync.aligned.m8n8.x4.shared.b16 {%0,%1,%2,%3}, [%4];"
        : "=r"(r[0]), "=r"(r[1]), "=r"(r[2]), "=r"(r[3]) : "r"(a));
}
__device__ __forceinline__ void mma_bf(float* d, const uint32_t* a, const uint32_t* b) {
    asm volatile("mma.sync.aligned.m16n8k16.row.col.f32.bf16.bf16.f32 "
        "{%0,%1,%2,%3}, {%4,%5,%6,%7}, {%8,%9}, {%0,%1,%2,%3};"
        : "+f"(d[0]), "+f"(d[1]), "+f"(d[2]), "+f"(d[3])
        : "r"(a[0]), "r"(a[1]), "r"(a[2]), "r"(a[3]), "r"(b[0]), "r"(b[1]));
}
__device__ __forceinline__ void mma_hf(float* d, const uint32_t* a, const uint32_t* b) {
    asm volatile("mma.sync.aligned.m16n8k16.row.col.f32.f16.f16.f32 "
        "{%0,%1,%2,%3}, {%4,%5,%6,%7}, {%8,%9}, {%0,%1,%2,%3};"
        : "+f"(d[0]), "+f"(d[1]), "+f"(d[2]), "+f"(d[3])
        : "r"(a[0]), "r"(a[1]), "r"(a[2]), "r"(a[3]), "r"(b[0]), "r"(b[1]));
}
#define CP16(d, s) asm volatile("cp.async.cg.shared.global [%0], [%1], 16;" :: "r"(d), "l"(s))
#define CPCOMMIT() asm volatile("cp.async.commit_group;" ::: "memory")
template <int N>
__device__ __forceinline__ void cp_wait() {
    asm volatile("cp.async.wait_group %0;" :: "n"(N) : "memory");
}

// ===== cp.async pipelined warp-MMA GEMM: D[m][n] = sum_k A[m][k]*B[n][k] =====
// AL/BL: extra passes; NST: stages; MB: min blocks/SM; H16: fp16 mma; FK: K==NST*32 barrier-free
// FLG: 2=exp2+colsum+bf16hi trans store(E) | 16=QKV mixed | 32=row fp16 store(AV)
//      | 8=fp32 row store | 64=skip lo-plane store
template <int AL, int BL, int NST, int MB, int FLG, int H16, int FK>
__global__ void __launch_bounds__(256, MB) mma_k(
    const ush* __restrict__ Ah, const ush* __restrict__ Al,
    const ush* __restrict__ Bh, const ush* __restrict__ Bl,
    float* __restrict__ Cf, ush* __restrict__ Ch, ush* __restrict__ Cl,
    const float* __restrict__ bias, float* __restrict__ part,
    int lda, int ldb, int ldc, int K,
    long long bsA, long long bsB, long long bsC,
    int zshA, int zxB, int zmC, int cshift,
    long long bsC2, int ldc2, int bstride)
{
    constexpr int BHO  = (1 + AL) * PL;
    constexpr int STGB = (2 + AL + BL) * PL;
    extern __shared__ char sm[];
    float* smf = (float*)sm;
    uint32_t su = smem_u32(sm);
    int tid = threadIdx.x, lane = tid & 31, w = tid >> 5;
    int wm = w & 3, wn = w >> 2;
    int m0 = blockIdx.y * 128, n0 = blockIdx.x * 128;
    long long z = blockIdx.z;

    const ush* pAh = Ah + (z >> zshA) * bsA;
    const ush* pAl = Al + (z >> zshA) * bsA;
    long long zB = z ^ zxB;
    const ush* pBh = Bh + zB * bsB;
    const ush* pBl = Bl + zB * bsB;
    long long zC = z & zmC;
    int colofs = (int)(z >> 2) * cshift;

    float acc[2][8][4];
#pragma unroll
    for (int a = 0; a < 2; a++)
#pragma unroll
        for (int b = 0; b < 8; b++)
#pragma unroll
            for (int c = 0; c < 4; c++) acc[a][b][c] = 0.f;

    int nch = K >> 5;

    auto cpstage = [&](int ch) {
        uint32_t dst = su + (ch % NST) * STGB;
        int k0 = ch << 5;
#pragma unroll
        for (int i = 0; i < 2; i++) {
            int idx = tid + (i << 8);
            int r = idx >> 2, c8 = (idx & 3) << 3;
            uint32_t doff = r * 80 + (c8 << 1);
            CP16(dst + doff,       pAh + (long long)(m0 + r) * lda + k0 + c8);
            if (AL)
                CP16(dst + PL + doff,  pAl + (long long)(m0 + r) * lda + k0 + c8);
            CP16(dst + BHO + doff, pBh + (long long)(n0 + r) * ldb + k0 + c8);
            if (BL)
                CP16(dst + BHO + PL + doff, pBl + (long long)(n0 + r) * ldb + k0 + c8);
        }
    };
    auto consume = [&](int ch) {
        uint32_t sst = su + (ch % NST) * STGB;
#pragma unroll
        for (int kk = 0; kk < 32; kk += 16) {
            uint32_t ah[2][4], al[2][4], bh[4][4], bl[4][4];
            int rA = (lane & 7) + ((lane >> 3) & 1) * 8;
            int kA = kk + (lane >> 4) * 8;
#pragma unroll
            for (int mt = 0; mt < 2; mt++) {
                uint32_t ad = sst + (wm * 32 + mt * 16 + rA) * 80 + kA * 2;
                ldmx4(ah[mt], ad);
                if (AL) ldmx4(al[mt], ad + PL);
            }
            int rB = (lane & 7) + (lane >> 4) * 8;
            int kB = kk + ((lane >> 3) & 1) * 8;
#pragma unroll
            for (int nt = 0; nt < 4; nt++) {
                uint32_t bd = sst + BHO + (wn * 64 + nt * 16 + rB) * 80 + kB * 2;
                ldmx4(bh[nt], bd);
                if (BL) ldmx4(bl[nt], bd + PL);
            }
#pragma unroll
            for (int mt = 0; mt < 2; mt++)
#pragma unroll
                for (int nt = 0; nt < 8; nt++) {
                    const uint32_t* ph = &bh[nt >> 1][(nt & 1) * 2];
                    const uint32_t* pl = &bl[nt >> 1][(nt & 1) * 2];
                    if (H16) {
                        mma_hf(acc[mt][nt], ah[mt], ph);
                        if (BL) mma_hf(acc[mt][nt], ah[mt], pl);
                        if (AL) mma_hf(acc[mt][nt], al[mt], ph);
                    } else {
                        mma_bf(acc[mt][nt], ah[mt], ph);
                        if (BL) mma_bf(acc[mt][nt], ah[mt], pl);
                        if (AL) mma_bf(acc[mt][nt], al[mt], ph);
                    }
                }
        }
    };

    if (FK) {
#pragma unroll
        for (int s = 0; s < NST; s++) { cpstage(s); CPCOMMIT(); }
        cp_wait<0>();
        __syncthreads();
#pragma unroll
        for (int ch = 0; ch < NST; ch++) consume(ch);
    } else {
#pragma unroll
        for (int s = 0; s < NST - 1; s++) { cpstage(s); CPCOMMIT(); }
        for (int ch = 0; ch < nch; ch++) {
            cp_wait<NST - 2>();
            __syncthreads();
            consume(ch);
            if (ch + NST - 1 < nch) cpstage(ch + NST - 1);
            CPCOMMIT();
        }
    }

    // acc -> smem fp32 tile (stride 130)
    __syncthreads();
#pragma unroll
    for (int mt = 0; mt < 2; mt++)
#pragma unroll
        for (int nt = 0; nt < 8; nt++) {
            int r = wm * 32 + mt * 16 + (lane >> 2);
            int c = wn * 64 + nt * 8 + 2 * (lane & 3);
            *(float2*)&smf[r * 130 + c]       = make_float2(acc[mt][nt][0], acc[mt][nt][1]);
            *(float2*)&smf[(r + 8) * 130 + c] = make_float2(acc[mt][nt][2], acc[mt][nt][3]);
        }
    __syncthreads();

    if (FLG & 2) {               // S: exp2 + colsum + packed bf16x2 trans store
        int r2 = (tid & 63) * 2, hf = tid >> 6;
        float ls0 = 0.f, ls1 = 0.f;
        ush* co = Ch + zC * bsC;
        int j0 = hf * 32;
#pragma unroll 4
        for (int j = j0; j < j0 + 32; j++) {
            float e0 = ex2f(fminf(smf[r2 * 130 + j], 86.0f));
            float e1 = ex2f(fminf(smf[(r2 + 1) * 130 + j], 86.0f));
            ls0 += e0; ls1 += e1;
            *(uint32_t*)(co + (long long)(n0 + j) * ldc + m0 + r2) = bf2pack(e0, e1);
        }
        long long pb = ((long long)blockIdx.x * 4 + hf) * (8 * HW) + z * HW + m0;
        part[pb + r2]     = ls0;
        part[pb + r2 + 1] = ls1;
    } else if (FLG & 32) {       // AV: row fp16x2 packed store
        ush* ch2 = Ch + zC * bsC;
#pragma unroll 4
        for (int i2 = tid; i2 < 8192; i2 += 256) {
            int r = i2 >> 6, c = (i2 & 63) * 2;
            __half2 h = __floats2half2_rn(smf[r * 130 + c], smf[r * 130 + c + 1]);
            *(__half2*)(ch2 + (long long)(m0 + r) * ldc + colofs + n0 + c) = h;
        }
    } else if (FLG & 16) {       // QKV mixed
        if (blockIdx.y == 2) {   // V rows: bf16x2 packed row store
            ush* cv = (ush*)Cf + z * bsC2;
            const float* bp2 = bias + (z >> zshA) * bstride + m0;
#pragma unroll 4
            for (int i2 = tid; i2 < 8192; i2 += 256) {
                int r = i2 >> 6, c = (i2 & 63) * 2;
                float bv = bp2[r];
                *(uint32_t*)(cv + (long long)r * ldc2 + n0 + c) =
                    bf2pack(smf[r * 130 + c] + bv, smf[r * 130 + c + 1] + bv);
            }
        } else {                 // Q/K: packed bf16x2 trans store + bias (2 rows/thread)
            int r2 = (tid & 63) * 2, hf = tid >> 6;
            const float* bp2 = bias + (z >> zshA) * bstride + m0;
            float b0v = bp2[r2], b1v = bp2[r2 + 1];
            ush* ch2 = Ch + zC * bsC;
            int j0 = hf * 32;
#pragma unroll 4
            for (int j = j0; j < j0 + 32; j++) {
                float v0 = smf[r2 * 130 + j] + b0v;
                float v1 = smf[(r2 + 1) * 130 + j] + b1v;
                *(uint32_t*)(ch2 + (long long)(n0 + j) * ldc + m0 + r2) = bf2pack(v0, v1);
            }
        }
    } else {                     // fp32 row store + bias (final)
        float* cf = Cf + zC * bsC;
#pragma unroll 4
        for (int i = tid; i < 16384; i += 256) {
            int r = i >> 7, c = i & 127;
            cf[(long long)(m0 + r) * ldc + n0 + c] =
                smf[r * 130 + c] + bias[(z >> zshA) * bstride + m0 + r];
        }
    }
}

// ===== merged prep kernel: bn_dw (2048) | tres (4096) | pack_wqkv (384) | packw (512) =====
__global__ void __launch_bounds__(256) prep_k(
    const float* __restrict__ F_i, const float* __restrict__ F_w,
    const float* __restrict__ g0, const float* __restrict__ g1,
    const float* __restrict__ b0, const float* __restrict__ b1,
    const float* __restrict__ m0p, const float* __restrict__ m1p,
    const float* __restrict__ v0, const float* __restrict__ v1,
    const float* __restrict__ w0p, const float* __restrict__ w1p,
    const float* __restrict__ d0, const float* __restrict__ d1,
    ush* __restrict__ dwraw, ush* __restrict__ xh,
    const float* __restrict__ wq1, const float* __restrict__ wk1, const float* __restrict__ wv1,
    const float* __restrict__ wq2, const float* __restrict__ wk2, const float* __restrict__ wv2,
    const float* __restrict__ bq1, const float* __restrict__ bk1, const float* __restrict__ bv1,
    const float* __restrict__ bq2, const float* __restrict__ bk2, const float* __restrict__ bv2,
    ush* __restrict__ wAh, ush* __restrict__ wAl, float* __restrict__ bqkv,
    const float* __restrict__ wp, const float* __restrict__ bp,
    const float* __restrict__ w1r, const float* __restrict__ b1r,
    const float* __restrict__ w2r, const float* __restrict__ b2r,
    ush* __restrict__ wh, float* __restrict__ bc)
{
    __shared__ float buf[34 * 66];
    int bid = blockIdx.x, tid = threadIdx.x;

    if (bid < 2048) {
        int bc2 = bid >> 1, half = bid & 1;
        int sel = bc2 >> 9, lc = bc2 & 511, c = bc2 & 127;
        int r0 = half * 32;
        const float* xp = (sel ? F_w : F_i) + (size_t)lc * HW;
        const float* g = sel ? g1 : g0; const float* b = sel ? b1 : b0;
        const float* m = sel ? m1p : m0p; const float* v = sel ? v1 : v0;
        const float* wdw = sel ? w1p : w0p; const float* bdw = sel ? d1 : d0;
        float sc = g[c] * rsqrtf(v[c] + EPSf), sh = b[c] - m[c] * sc;
        for (int i = tid; i < 34 * 66; i += 256) {
            int r = i / 66 - 1 + r0, cl = i % 66 - 1;
            buf[i] = (r >= 0 && r < 64 && cl >= 0 && cl < 64) ? xp[r * 64 + cl] * sc + sh : 0.f;
        }
        __syncthreads();
        float w0 = wdw[c*9], w1 = wdw[c*9+1], w2 = wdw[c*9+2], w3 = wdw[c*9+3], w4 = wdw[c*9+4];
        float w5 = wdw[c*9+5], w6 = wdw[c*9+6], w7 = wdw[c*9+7], w8 = wdw[c*9+8], bb = bdw[c];
        ush* yp = dwraw + (size_t)bc2 * HW + r0 * 64;
        for (int i = tid; i < 2048; i += 256) {
            const float* t = &buf[(i >> 6) * 66 + (i & 63)];
            float s = bb + t[0]*w0 + t[1]*w1 + t[2]*w2 + t[66]*w3 + t[67]*w4 + t[68]*w5
                         + t[132]*w6 + t[133]*w7 + t[134]*w8;
            yp[i] = (ush)(bfh(s) >> 16);
        }
    } else if (bid < 6144) {
        int idx = bid - 2048;
        int px = idx & 127, cy = (idx >> 7) & 3, z = idx >> 9;
        int br = z >> 2, bb = z & 3;
        const float* src = (br ? F_w : F_i) + (long long)bb * Cc * HW;
        float (*t)[33] = (float(*)[33])buf;
        int p0 = px * 32, c0 = cy * 32;
        int x = tid & 31, y = tid >> 5;
#pragma unroll
        for (int i = 0; i < 32; i += 8) t[y + i][x] = src[(long long)(c0 + y + i) * HW + p0 + x];
        __syncthreads();
#pragma unroll
        for (int i = 0; i < 32; i += 8) {
            long long o = ((long long)bb * HW + p0 + y + i) * 512 + 256 + br * 128 + c0 + x;
            xh[o] = f16b(t[x][y + i]);
        }
    } else if (bid < 6528) {
        int i = (bid - 6144) * 256 + tid;
        int br = i / 49152, rem = i % 49152, r = rem >> 7, c = rem & 127;
        const float* w; const float* bs;
        if (br == 0) { w = r < 128 ? wq1 : r < 256 ? wk1 : wv1; bs = r < 128 ? bq1 : r < 256 ? bk1 : bv1; }
        else         { w = r < 128 ? wq2 : r < 256 ? wk2 : wv2; bs = r < 128 ? bq2 : r < 256 ? bk2 : bv2; }
        float scl = (r >= 128 && r < 256) ? 1.44269504088896f : 1.f;
        float v = w[(r & 127) * 128 + c] * scl;
        uint32_t hb = bfh(v);
        wAh[i] = (ush)(hb >> 16);
        wAl[i] = (ush)(bfh(v - __int_as_float(hb)) >> 16);
        if (c == 0) bqkv[br * 384 + r] = bs[r & 127] * scl;
    } else {
        int i = (bid - 6528) * 256 + tid;
        if (i < OUTC * 512) {
            int o = i >> 9, k = i & 511;
            float v = (k < 256) ? wp[o * 256 + k] : (k < 384) ? w1r[o * 128 + k - 256] : w2r[o * 128 + k - 384];
            wh[i] = f16b(v);
            if (k == 0) bc[o] = bp[o] + b1r[o] + b2r[o];
        }
    }
}

// ---- transpose ush [128][HW] -> [HW][128] ----
__global__ void __launch_bounds__(256) tsplit_k(
    const ush* __restrict__ src, ush* __restrict__ dh, long long bs)
{
    __shared__ ush t[32][34];
    src += blockIdx.z * bs; dh += blockIdx.z * bs;
    int p0 = blockIdx.x * 32, c0 = blockIdx.y * 32;
    int x = threadIdx.x & 31, y = threadIdx.x >> 5;
#pragma unroll
    for (int i = 0; i < 32; i += 8) t[y + i][x] = src[(long long)(c0 + y + i) * HW + p0 + x];
    __syncthreads();
#pragma unroll
    for (int i = 0; i < 32; i += 8)
        dh[(long long)(p0 + y + i) * 128 + c0 + x] = t[x][y + i];
}

// ---- reduce 128 partial colsums -> reciprocal ----
__global__ void __launch_bounds__(256) rcpsum(const float* __restrict__ part, float* __restrict__ sums)
{
    int i = blockIdx.x * 256 + threadIdx.x;    // 32768
    float s = 0.f;
#pragma unroll
    for (int k = 0; k < 128; k++) s += part[(long long)k * 32768 + i];
    sums[i] = 1.f / s;
}

// ---- fold rs into V (bf16 in, bf16 out); 524288 uint4 total ----
__global__ void __launch_bounds__(256) vscale(
    const uint4* __restrict__ vraw, const float4* __restrict__ rs4,
    uint4* __restrict__ vh)
{
    int i = blockIdx.x * 256 + threadIdx.x;
    int n8 = i & 511, tb = i >> 16;
    uint4 a = vraw[i];
    float4 r0 = rs4[(((tb ^ 4) << 10)) + n8 * 2];
    float4 r1 = rs4[(((tb ^ 4) << 10)) + n8 * 2 + 1];
    uint4 o;
    {
        float f0 = __int_as_float((a.x & 0xFFFFu) << 16) * r0.x;
        float f1 = __int_as_float(a.x & 0xFFFF0000u) * r0.y;
        o.x = bf2pack(f0, f1);
        float f2 = __int_as_float((a.y & 0xFFFFu) << 16) * r0.z;
        float f3 = __int_as_float(a.y & 0xFFFF0000u) * r0.w;
        o.y = bf2pack(f2, f3);
        float f4 = __int_as_float((a.z & 0xFFFFu) << 16) * r1.x;
        float f5 = __int_as_float(a.z & 0xFFFF0000u) * r1.y;
        o.z = bf2pack(f4, f5);
        float f6 = __int_as_float((a.w & 0xFFFFu) << 16) * r1.z;
        float f7 = __int_as_float(a.w & 0xFFFF0000u) * r1.w;
        o.w = bf2pack(f6, f7);
    }
    vh[i] = o;
}

extern "C" void kernel_launch(void* const* d_in, const int* in_sizes, int n_in,
                              void* d_out, int out_size)
{
    const float *F_i = (const float*)d_in[0], *F_w = (const float*)d_in[1];
    const float *bn1g = (const float*)d_in[2], *bn1b = (const float*)d_in[3];
    const float *bn1m = (const float*)d_in[4], *bn1v = (const float*)d_in[5];
    const float *bn2g = (const float*)d_in[6], *bn2b = (const float*)d_in[7];
    const float *bn2m = (const float*)d_in[8], *bn2v = (const float*)d_in[9];
    const float *wq1 = (const float*)d_in[10], *bq1 = (const float*)d_in[11];
    const float *wk1 = (const float*)d_in[12], *bk1 = (const float*)d_in[13];
    const float *wv1 = (const float*)d_in[14], *bv1 = (const float*)d_in[15];
    const float *wq2 = (const float*)d_in[16], *bq2 = (const float*)d_in[17];
    const float *wk2 = (const float*)d_in[18], *bk2 = (const float*)d_in[19];
    const float *wv2 = (const float*)d_in[20], *bv2 = (const float*)d_in[21];
    const float *wd1 = (const float*)d_in[22], *bd1 = (const float*)d_in[23];
    const float *wd2 = (const float*)d_in[24], *bd2 = (const float*)d_in[25];
    const float *wpj = (const float*)d_in[26], *bpj = (const float*)d_in[27];
    const float *wr1 = (const float*)d_in[28], *br1 = (const float*)d_in[29];
    const float *wr2 = (const float*)d_in[30], *br2 = (const float*)d_in[31];

    float *part, *sum, *bqkv, *bc;
    ush *dwraw, *dwTh, *wAh, *wAl, *qTh, *qTl, *vraw, *vh, *Eh, *xTh, *wch;
    cudaGetSymbolAddress((void**)&dwraw, g_dwraw);
    cudaGetSymbolAddress((void**)&dwTh, g_dwTh);
    cudaGetSymbolAddress((void**)&wAh, g_wAh);   cudaGetSymbolAddress((void**)&wAl, g_wAl);
    cudaGetSymbolAddress((void**)&bqkv, g_bqkv);
    cudaGetSymbolAddress((void**)&qTh, g_qkvTh); cudaGetSymbolAddress((void**)&qTl, g_qkvTl);
    cudaGetSymbolAddress((void**)&vraw, g_vraw);
    cudaGetSymbolAddress((void**)&vh, g_vh);
    cudaGetSymbolAddress((void**)&Eh, g_Eh);
    cudaGetSymbolAddress((void**)&part, g_part); cudaGetSymbolAddress((void**)&sum, g_sum);
    cudaGetSymbolAddress((void**)&xTh, g_xTh);
    cudaGetSymbolAddress((void**)&wch, g_wch);
    cudaGetSymbolAddress((void**)&bc, g_bcat);

    const int SM_QKV = 4 * 2 * PL;
    const int SM_SAV = 4 * 2 * PL;
    const int SM_FIN = 66560;

    cudaFuncSetAttribute(mma_k<0,0,4,2,80,0,1>, cudaFuncAttributeMaxDynamicSharedMemorySize, SM_QKV);
    cudaFuncSetAttribute(mma_k<0,0,4,2,2,0,1>,  cudaFuncAttributeMaxDynamicSharedMemorySize, SM_SAV);
    cudaFuncSetAttribute(mma_k<0,0,4,2,96,0,0>, cudaFuncAttributeMaxDynamicSharedMemorySize, SM_SAV);
    cudaFuncSetAttribute(mma_k<0,0,3,2,8,1,0>,  cudaFuncAttributeMaxDynamicSharedMemorySize, SM_FIN);

    const long long TT = (long long)HW * Cc;
    const long long TT384 = (long long)HW * 384;
    const long long SS = (long long)HW * HW;
    const long long XS = (long long)HW * 512;

    prep_k<<<7040, 256>>>(
        F_i, F_w, bn1g, bn2g, bn1b, bn2b, bn1m, bn2m, bn1v, bn2v,
        wd1, wd2, bd1, bd2, dwraw, xTh,
        wq1, wk1, wv1, wq2, wk2, wv2, bq1, bk1, bv1, bq2, bk2, bv2,
        wAh, wAl, bqkv,
        wpj, bpj, wr1, br1, wr2, br2, wch, bc);

    tsplit_k<<<dim3(128, 4, 8), 256>>>(dwraw, dwTh, TT);

    // QKV merged: M=384, N=4096, K=128, z = branch*4+batch  (1-pass, FULLK)
    mma_k<0,0,4,2,80,0,1><<<dim3(32, 3, 8), 256, SM_QKV>>>(
        wAh, wAh, dwTh, dwTh, (float*)vraw, qTh, qTl, bqkv, 0,
        128, 128, 384, 128, 49152, TT, TT384,
        2, 0, 255, 0, TT, HW, 384);

    // S merged: z = attn*4+batch  (1-pass, FULLK, packed epilogue)
    mma_k<0,0,4,2,2,0,1><<<dim3(32, 32, 8), 256, SM_SAV>>>(
        qTh, qTh, qTh + 128, qTh + 128, 0, Eh, 0, 0, part,
        384, 384, HW, 128, TT384, TT384, SS,
        0, 4, 255, 0, 0, 0, 0);

    rcpsum<<<128, 256>>>(part, sum);
    vscale<<<2048, 256>>>((const uint4*)vraw, (const float4*)sum, (uint4*)vh);

    // AV merged (flipped): D[m][c] = sum_n Eh[m][n]*Vh[c][n]; fp16x2 store -> xT
    mma_k<0,0,4,2,96,0,0><<<dim3(1, 32, 8), 256, SM_SAV>>>(
        Eh, Eh, vh, vh, 0, xTh, xTh, 0, 0,
        HW, HW, 512, HW, SS, TT, XS,
        0, 4, 3, 128, 0, 0, 0);

    // out = wcat(fp16) @ xT^T(fp16) + bcat : M=256, N=4096, K=512  (1-pass fp16)
    mma_k<0,0,3,2,8,1,0><<<dim3(32, 2, 4), 256, SM_FIN>>>(
        wch, wch, xTh, xTh, (float*)d_out, 0, 0, bc, 0,
        512, 512, HW, 512, 0, XS, (long long)OUTC * HW,
        0, 0, 255, 0, 0, 0, 0);
}

// round 17
// speedup vs baseline: 7.1846x; 1.0387x over previous
#include <cuda_runtime.h>
#include <cuda_fp16.h>
#include <cstdint>
#include <math.h>

typedef unsigned short ush;
#define HW 4096
#define Cc 128
#define Bn 4
#define OUTC 256
#define EPSf 1e-5f
#define PL 10240

// ---------------- scratch ----------------
__device__ ush   g_dwraw[2*Bn*Cc*HW];
__device__ ush   g_dwTh[2*Bn*Cc*HW];
__device__ ush   g_wAh[2*384*128],   g_wAl[2*384*128];
__device__ float g_bqkv[2*384];
__device__ ush   g_qkvTh[2ll*Bn*HW*384], g_qkvTl[2ll*Bn*HW*384];
__device__ ush   g_vraw[2*Bn*Cc*HW];
__device__ ush   g_vh[2*Bn*Cc*HW];
__device__ ush   g_Eh[134217728];                 // [attn][B][key][query] bf16
__device__ float g_part[128*8*HW];
__device__ float g_sum[8*HW];
__device__ ush   g_xTh[Bn*HW*512];                // fp16 plane
__device__ ush   g_wch[OUTC*512];                 // fp16 plane
__device__ float g_bcat[OUTC];

__device__ __forceinline__ uint32_t smem_u32(const void* p) {
    uint32_t a;
    asm("{ .reg .u64 t; cvta.to.shared.u64 t, %1; cvt.u32.u64 %0, t; }" : "=r"(a) : "l"(p));
    return a;
}
__device__ __forceinline__ uint32_t bfh(float x) {
    uint32_t u = __float_as_uint(x);
    return (u + 0x7FFFu + ((u >> 16) & 1)) & 0xFFFF0000u;
}
__device__ __forceinline__ ush f16b(float x) {
    return __half_as_ushort(__float2half_rn(x));
}
__device__ __forceinline__ uint32_t bf2pack(float lo, float hi) {
    uint32_t r;
    asm("cvt.rn.bf16x2.f32 %0, %1, %2;" : "=r"(r) : "f"(hi), "f"(lo));
    return r;
}
__device__ __forceinline__ ush bf1(float x) {
    ush u;
    asm("cvt.rn.bf16.f32 %0, %1;" : "=h"(u) : "f"(x));
    return u;
}
__device__ __forceinline__ float ex2f(float x) {
    float y;
    asm("ex2.approx.ftz.f32 %0, %1;" : "=f"(y) : "f"(x));
    return y;
}
__device__ __forceinline__ void ldmx4(uint32_t* r, uint32_t a) {
    asm volatile("ldmatrix.sync.aligned.m8n8.x4.shared.b16 {%0,%1,%2,%3}, [%4];"
        : "=r"(r[0]), "=r"(r[1]), "=r"(r[2]), "=r"(r[3]) : "r"(a));
}
__device__ __forceinline__ void mma_bf(float* d, const uint32_t* a, const uint32_t* b) {
    asm volatile("mma.sync.aligned.m16n8k16.row.col.f32.bf16.bf16.f32 "
        "{%0,%1,%2,%3}, {%4,%5,%6,%7}, {%8,%9}, {%0,%1,%2,%3};"
        : "+f"(d[0]), "+f"(d[1]), "+f"(d[2]), "+f"(d[3])
        : "r"(a[0]), "r"(a[1]), "r"(a[2]), "r"(a[3]), "r"(b[0]), "r"(b[1]));
}
__device__ __forceinline__ void mma_hf(float* d, const uint32_t* a, const uint32_t* b) {
    asm volatile("mma.sync.aligned.m16n8k16.row.col.f32.f16.f16.f32 "
        "{%0,%1,%2,%3}, {%4,%5,%6,%7}, {%8,%9}, {%0,%1,%2,%3};"
        : "+f"(d[0]), "+f"(d[1]), "+f"(d[2]), "+f"(d[3])
        : "r"(a[0]), "r"(a[1]), "r"(a[2]), "r"(a[3]), "r"(b[0]), "r"(b[1]));
}
#define CP16(d, s) asm volatile("cp.async.cg.shared.global [%0], [%1], 16;" :: "r"(d), "l"(s))
#define CPCOMMIT() asm volatile("cp.async.commit_group;" ::: "memory")
template <int N>
__device__ __forceinline__ void cp_wait() {
    asm volatile("cp.async.wait_group %0;" :: "n"(N) : "memory");
}

// ===== cp.async pipelined warp-MMA GEMM: D[m][n] = sum_k A[m][k]*B[n][k] =====
// AL/BL: extra passes; NST: stages; MB: min blocks/SM; H16: fp16 mma; FK: K==NST*32 barrier-free
// FLG: 2=S direct epilogue (exp2+colsum+bf16 trans) | 16=QKV mixed (smem path)
//      | 32=AV direct fp16x2 row | 8=final direct fp32 row
template <int AL, int BL, int NST, int MB, int FLG, int H16, int FK>
__global__ void __launch_bounds__(256, MB) mma_k(
    const ush* __restrict__ Ah, const ush* __restrict__ Al,
    const ush* __restrict__ Bh, const ush* __restrict__ Bl,
    float* __restrict__ Cf, ush* __restrict__ Ch, ush* __restrict__ Cl,
    const float* __restrict__ bias, float* __restrict__ part,
    int lda, int ldb, int ldc, int K,
    long long bsA, long long bsB, long long bsC,
    int zshA, int zxB, int zmC, int cshift,
    long long bsC2, int ldc2, int bstride)
{
    constexpr int BHO  = (1 + AL) * PL;
    constexpr int STGB = (2 + AL + BL) * PL;
    extern __shared__ char sm[];
    float* smf = (float*)sm;
    uint32_t su = smem_u32(sm);
    int tid = threadIdx.x, lane = tid & 31, w = tid >> 5;
    int wm = w & 3, wn = w >> 2;
    int lr = lane >> 2, lq = lane & 3;
    int m0 = blockIdx.y * 128, n0 = blockIdx.x * 128;
    long long z = blockIdx.z;

    const ush* pAh = Ah + (z >> zshA) * bsA;
    const ush* pAl = Al + (z >> zshA) * bsA;
    long long zB = z ^ zxB;
    const ush* pBh = Bh + zB * bsB;
    const ush* pBl = Bl + zB * bsB;
    long long zC = z & zmC;
    int colofs = (int)(z >> 2) * cshift;

    float acc[2][8][4];
#pragma unroll
    for (int a = 0; a < 2; a++)
#pragma unroll
        for (int b = 0; b < 8; b++)
#pragma unroll
            for (int c = 0; c < 4; c++) acc[a][b][c] = 0.f;

    int nch = K >> 5;

    auto cpstage = [&](int ch) {
        uint32_t dst = su + (ch % NST) * STGB;
        int k0 = ch << 5;
#pragma unroll
        for (int i = 0; i < 2; i++) {
            int idx = tid + (i << 8);
            int r = idx >> 2, c8 = (idx & 3) << 3;
            uint32_t doff = r * 80 + (c8 << 1);
            CP16(dst + doff,       pAh + (long long)(m0 + r) * lda + k0 + c8);
            if (AL)
                CP16(dst + PL + doff,  pAl + (long long)(m0 + r) * lda + k0 + c8);
            CP16(dst + BHO + doff, pBh + (long long)(n0 + r) * ldb + k0 + c8);
            if (BL)
                CP16(dst + BHO + PL + doff, pBl + (long long)(n0 + r) * ldb + k0 + c8);
        }
    };
    auto consume = [&](int ch) {
        uint32_t sst = su + (ch % NST) * STGB;
#pragma unroll
        for (int kk = 0; kk < 32; kk += 16) {
            uint32_t ah[2][4], al[2][4], bh[4][4], bl[4][4];
            int rA = (lane & 7) + ((lane >> 3) & 1) * 8;
            int kA = kk + (lane >> 4) * 8;
#pragma unroll
            for (int mt = 0; mt < 2; mt++) {
                uint32_t ad = sst + (wm * 32 + mt * 16 + rA) * 80 + kA * 2;
                ldmx4(ah[mt], ad);
                if (AL) ldmx4(al[mt], ad + PL);
            }
            int rB = (lane & 7) + (lane >> 4) * 8;
            int kB = kk + ((lane >> 3) & 1) * 8;
#pragma unroll
            for (int nt = 0; nt < 4; nt++) {
                uint32_t bd = sst + BHO + (wn * 64 + nt * 16 + rB) * 80 + kB * 2;
                ldmx4(bh[nt], bd);
                if (BL) ldmx4(bl[nt], bd + PL);
            }
#pragma unroll
            for (int mt = 0; mt < 2; mt++)
#pragma unroll
                for (int nt = 0; nt < 8; nt++) {
                    const uint32_t* ph = &bh[nt >> 1][(nt & 1) * 2];
                    const uint32_t* pl = &bl[nt >> 1][(nt & 1) * 2];
                    if (H16) {
                        mma_hf(acc[mt][nt], ah[mt], ph);
                        if (BL) mma_hf(acc[mt][nt], ah[mt], pl);
                        if (AL) mma_hf(acc[mt][nt], al[mt], ph);
                    } else {
                        mma_bf(acc[mt][nt], ah[mt], ph);
                        if (BL) mma_bf(acc[mt][nt], ah[mt], pl);
                        if (AL) mma_bf(acc[mt][nt], al[mt], ph);
                    }
                }
        }
    };

    if (FK) {
#pragma unroll
        for (int s = 0; s < NST; s++) { cpstage(s); CPCOMMIT(); }
        cp_wait<0>();
        __syncthreads();
#pragma unroll
        for (int ch = 0; ch < NST; ch++) consume(ch);
    } else {
#pragma unroll
        for (int s = 0; s < NST - 1; s++) { cpstage(s); CPCOMMIT(); }
        for (int ch = 0; ch < nch; ch++) {
            cp_wait<NST - 2>();
            __syncthreads();
            consume(ch);
            if (ch + NST - 1 < nch) cpstage(ch + NST - 1);
            CPCOMMIT();
        }
    }

    if (FLG & 2) {
        // ===== S direct epilogue: exp2 + colsum(shfl) + bf16 trans store (ldc==HW) =====
        ush* base = Ch + zC * bsC
                  + (long long)(n0 + wn * 64 + 2 * lq) * HW + m0 + wm * 32 + lr;
        float rsm[2][2] = {{0.f, 0.f}, {0.f, 0.f}};
#pragma unroll
        for (int mt = 0; mt < 2; mt++)
#pragma unroll
            for (int nt = 0; nt < 8; nt++) {
                float e0 = ex2f(fminf(acc[mt][nt][0], 86.f));
                float e1 = ex2f(fminf(acc[mt][nt][1], 86.f));
                float e2 = ex2f(fminf(acc[mt][nt][2], 86.f));
                float e3 = ex2f(fminf(acc[mt][nt][3], 86.f));
                rsm[mt][0] += e0 + e1;
                rsm[mt][1] += e2 + e3;
                ush* p = base + nt * 8 * HW + mt * 16;
                p[0]      = bf1(e0);
                p[HW]     = bf1(e1);
                p[8]      = bf1(e2);
                p[HW + 8] = bf1(e3);
            }
#pragma unroll
        for (int mt = 0; mt < 2; mt++)
#pragma unroll
            for (int h = 0; h < 2; h++) {
                float s = rsm[mt][h];
                s += __shfl_xor_sync(0xffffffffu, s, 1);
                s += __shfl_xor_sync(0xffffffffu, s, 2);
                if (lq == 0)
                    part[((long long)blockIdx.x * 2 + wn) * (8 * HW) + z * HW
                         + m0 + wm * 32 + mt * 16 + h * 8 + lr] = s;
            }
    } else if (FLG & 32) {
        // ===== AV direct epilogue: fp16x2 row store (ldc==512) =====
        ush* base = Ch + zC * bsC
                  + (long long)(m0 + wm * 32 + lr) * 512 + colofs + n0 + wn * 64 + 2 * lq;
#pragma unroll
        for (int mt = 0; mt < 2; mt++)
#pragma unroll
            for (int nt = 0; nt < 8; nt++) {
                ush* p = base + mt * 16 * 512 + nt * 8;
                *(__half2*)p            = __floats2half2_rn(acc[mt][nt][0], acc[mt][nt][1]);
                *(__half2*)(p + 8*512)  = __floats2half2_rn(acc[mt][nt][2], acc[mt][nt][3]);
            }
    } else if (FLG & 16) {
        // ===== QKV: smem roundtrip epilogue (trans pack crosses lanes) =====
        __syncthreads();
#pragma unroll
        for (int mt = 0; mt < 2; mt++)
#pragma unroll
            for (int nt = 0; nt < 8; nt++) {
                int r = wm * 32 + mt * 16 + lr;
                int c = wn * 64 + nt * 8 + 2 * lq;
                *(float2*)&smf[r * 130 + c]       = make_float2(acc[mt][nt][0], acc[mt][nt][1]);
                *(float2*)&smf[(r + 8) * 130 + c] = make_float2(acc[mt][nt][2], acc[mt][nt][3]);
            }
        __syncthreads();
        if (blockIdx.y == 2) {   // V rows: bf16x2 packed row store
            ush* cv = (ush*)Cf + z * bsC2;
            const float* bp2 = bias + (z >> zshA) * bstride + m0;
#pragma unroll 4
            for (int i2 = tid; i2 < 8192; i2 += 256) {
                int r = i2 >> 6, c = (i2 & 63) * 2;
                float bv = bp2[r];
                *(uint32_t*)(cv + (long long)r * ldc2 + n0 + c) =
                    bf2pack(smf[r * 130 + c] + bv, smf[r * 130 + c + 1] + bv);
            }
        } else {                 // Q/K: packed bf16x2 trans store + bias
            int r2 = (tid & 63) * 2, hf = tid >> 6;
            const float* bp2 = bias + (z >> zshA) * bstride + m0;
            float b0v = bp2[r2], b1v = bp2[r2 + 1];
            ush* ch2 = Ch + zC * bsC;
            int j0 = hf * 32;
#pragma unroll 4
            for (int j = j0; j < j0 + 32; j++) {
                float v0 = smf[r2 * 130 + j] + b0v;
                float v1 = smf[(r2 + 1) * 130 + j] + b1v;
                *(uint32_t*)(ch2 + (long long)(n0 + j) * ldc + m0 + r2) = bf2pack(v0, v1);
            }
        }
    } else {
        // ===== final direct epilogue: fp32 float2 row store + bias =====
        float* cf = Cf + zC * bsC;
        int c0b = n0 + wn * 64 + 2 * lq;
#pragma unroll
        for (int mt = 0; mt < 2; mt++)
#pragma unroll
            for (int h = 0; h < 2; h++) {
                int r = m0 + wm * 32 + mt * 16 + h * 8 + lr;
                float bv = bias[r];
                float* p = cf + (long long)r * ldc + c0b;
#pragma unroll
                for (int nt = 0; nt < 8; nt++)
                    *(float2*)(p + nt * 8) =
                        make_float2(acc[mt][nt][2*h] + bv, acc[mt][nt][2*h + 1] + bv);
            }
    }
}

// ===== merged prep kernel: bn_dw (2048) | tres (4096) | pack_wqkv (384) | packw (512) =====
__global__ void __launch_bounds__(256) prep_k(
    const float* __restrict__ F_i, const float* __restrict__ F_w,
    const float* __restrict__ g0, const float* __restrict__ g1,
    const float* __restrict__ b0, const float* __restrict__ b1,
    const float* __restrict__ m0p, const float* __restrict__ m1p,
    const float* __restrict__ v0, const float* __restrict__ v1,
    const float* __restrict__ w0p, const float* __restrict__ w1p,
    const float* __restrict__ d0, const float* __restrict__ d1,
    ush* __restrict__ dwraw, ush* __restrict__ xh,
    const float* __restrict__ wq1, const float* __restrict__ wk1, const float* __restrict__ wv1,
    const float* __restrict__ wq2, const float* __restrict__ wk2, const float* __restrict__ wv2,
    const float* __restrict__ bq1, const float* __restrict__ bk1, const float* __restrict__ bv1,
    const float* __restrict__ bq2, const float* __restrict__ bk2, const float* __restrict__ bv2,
    ush* __restrict__ wAh, ush* __restrict__ wAl, float* __restrict__ bqkv,
    const float* __restrict__ wp, const float* __restrict__ bp,
    const float* __restrict__ w1r, const float* __restrict__ b1r,
    const float* __restrict__ w2r, const float* __restrict__ b2r,
    ush* __restrict__ wh, float* __restrict__ bc)
{
    __shared__ float buf[34 * 66];
    int bid = blockIdx.x, tid = threadIdx.x;

    if (bid < 2048) {
        int bc2 = bid >> 1, half = bid & 1;
        int sel = bc2 >> 9, lc = bc2 & 511, c = bc2 & 127;
        int r0 = half * 32;
        const float* xp = (sel ? F_w : F_i) + (size_t)lc * HW;
        const float* g = sel ? g1 : g0; const float* b = sel ? b1 : b0;
        const float* m = sel ? m1p : m0p; const float* v = sel ? v1 : v0;
        const float* wdw = sel ? w1p : w0p; const float* bdw = sel ? d1 : d0;
        float sc = g[c] * rsqrtf(v[c] + EPSf), sh = b[c] - m[c] * sc;
        for (int i = tid; i < 34 * 66; i += 256) {
            int r = i / 66 - 1 + r0, cl = i % 66 - 1;
            buf[i] = (r >= 0 && r < 64 && cl >= 0 && cl < 64) ? xp[r * 64 + cl] * sc + sh : 0.f;
        }
        __syncthreads();
        float w0 = wdw[c*9], w1 = wdw[c*9+1], w2 = wdw[c*9+2], w3 = wdw[c*9+3], w4 = wdw[c*9+4];
        float w5 = wdw[c*9+5], w6 = wdw[c*9+6], w7 = wdw[c*9+7], w8 = wdw[c*9+8], bb = bdw[c];
        ush* yp = dwraw + (size_t)bc2 * HW + r0 * 64;
        for (int i = tid; i < 2048; i += 256) {
            const float* t = &buf[(i >> 6) * 66 + (i & 63)];
            float s = bb + t[0]*w0 + t[1]*w1 + t[2]*w2 + t[66]*w3 + t[67]*w4 + t[68]*w5
                         + t[132]*w6 + t[133]*w7 + t[134]*w8;
            yp[i] = (ush)(bfh(s) >> 16);
        }
    } else if (bid < 6144) {
        int idx = bid - 2048;
        int px = idx & 127, cy = (idx >> 7) & 3, z = idx >> 9;
        int br = z >> 2, bb = z & 3;
        const float* src = (br ? F_w : F_i) + (long long)bb * Cc * HW;
        float (*t)[33] = (float(*)[33])buf;
        int p0 = px * 32, c0 = cy * 32;
        int x = tid & 31, y = tid >> 5;
#pragma unroll
        for (int i = 0; i < 32; i += 8) t[y + i][x] = src[(long long)(c0 + y + i) * HW + p0 + x];
        __syncthreads();
#pragma unroll
        for (int i = 0; i < 32; i += 8) {
            long long o = ((long long)bb * HW + p0 + y + i) * 512 + 256 + br * 128 + c0 + x;
            xh[o] = f16b(t[x][y + i]);
        }
    } else if (bid < 6528) {
        int i = (bid - 6144) * 256 + tid;
        int br = i / 49152, rem = i % 49152, r = rem >> 7, c = rem & 127;
        const float* w; const float* bs;
        if (br == 0) { w = r < 128 ? wq1 : r < 256 ? wk1 : wv1; bs = r < 128 ? bq1 : r < 256 ? bk1 : bv1; }
        else         { w = r < 128 ? wq2 : r < 256 ? wk2 : wv2; bs = r < 128 ? bq2 : r < 256 ? bk2 : bv2; }
        float scl = (r >= 128 && r < 256) ? 1.44269504088896f : 1.f;
        float v = w[(r & 127) * 128 + c] * scl;
        uint32_t hb = bfh(v);
        wAh[i] = (ush)(hb >> 16);
        wAl[i] = (ush)(bfh(v - __int_as_float(hb)) >> 16);
        if (c == 0) bqkv[br * 384 + r] = bs[r & 127] * scl;
    } else {
        int i = (bid - 6528) * 256 + tid;
        if (i < OUTC * 512) {
            int o = i >> 9, k = i & 511;
            float v = (k < 256) ? wp[o * 256 + k] : (k < 384) ? w1r[o * 128 + k - 256] : w2r[o * 128 + k - 384];
            wh[i] = f16b(v);
            if (k == 0) bc[o] = bp[o] + b1r[o] + b2r[o];
        }
    }
}

// ---- transpose ush [128][HW] -> [HW][128] ----
__global__ void __launch_bounds__(256) tsplit_k(
    const ush* __restrict__ src, ush* __restrict__ dh, long long bs)
{
    __shared__ ush t[32][34];
    src += blockIdx.z * bs; dh += blockIdx.z * bs;
    int p0 = blockIdx.x * 32, c0 = blockIdx.y * 32;
    int x = threadIdx.x & 31, y = threadIdx.x >> 5;
#pragma unroll
    for (int i = 0; i < 32; i += 8) t[y + i][x] = src[(long long)(c0 + y + i) * HW + p0 + x];
    __syncthreads();
#pragma unroll
    for (int i = 0; i < 32; i += 8)
        dh[(long long)(p0 + y + i) * 128 + c0 + x] = t[x][y + i];
}

// ---- reduce 64 partial colsums -> reciprocal ----
__global__ void __launch_bounds__(256) rcpsum(const float* __restrict__ part, float* __restrict__ sums)
{
    int i = blockIdx.x * 256 + threadIdx.x;    // 32768
    float s = 0.f;
#pragma unroll
    for (int k = 0; k < 64; k++) s += part[(long long)k * 32768 + i];
    sums[i] = 1.f / s;
}

// ---- fold rs into V (bf16 in, bf16 out); 524288 uint4 total ----
__global__ void __launch_bounds__(256) vscale(
    const uint4* __restrict__ vraw, const float4* __restrict__ rs4,
    uint4* __restrict__ vh)
{
    int i = blockIdx.x * 256 + threadIdx.x;
    int n8 = i & 511, tb = i >> 16;
    uint4 a = vraw[i];
    float4 r0 = rs4[(((tb ^ 4) << 10)) + n8 * 2];
    float4 r1 = rs4[(((tb ^ 4) << 10)) + n8 * 2 + 1];
    uint4 o;
    {
        float f0 = __int_as_float((a.x & 0xFFFFu) << 16) * r0.x;
        float f1 = __int_as_float(a.x & 0xFFFF0000u) * r0.y;
        o.x = bf2pack(f0, f1);
        float f2 = __int_as_float((a.y & 0xFFFFu) << 16) * r0.z;
        float f3 = __int_as_float(a.y & 0xFFFF0000u) * r0.w;
        o.y = bf2pack(f2, f3);
        float f4 = __int_as_float((a.z & 0xFFFFu) << 16) * r1.x;
        float f5 = __int_as_float(a.z & 0xFFFF0000u) * r1.y;
        o.z = bf2pack(f4, f5);
        float f6 = __int_as_float((a.w & 0xFFFFu) << 16) * r1.z;
        float f7 = __int_as_float(a.w & 0xFFFF0000u) * r1.w;
        o.w = bf2pack(f6, f7);
    }
    vh[i] = o;
}

extern "C" void kernel_launch(void* const* d_in, const int* in_sizes, int n_in,
                              void* d_out, int out_size)
{
    const float *F_i = (const float*)d_in[0], *F_w = (const float*)d_in[1];
    const float *bn1g = (const float*)d_in[2], *bn1b = (const float*)d_in[3];
    const float *bn1m = (const float*)d_in[4], *bn1v = (const float*)d_in[5];
    const float *bn2g = (const float*)d_in[6], *bn2b = (const float*)d_in[7];
    const float *bn2m = (const float*)d_in[8], *bn2v = (const float*)d_in[9];
    const float *wq1 = (const float*)d_in[10], *bq1 = (const float*)d_in[11];
    const float *wk1 = (const float*)d_in[12], *bk1 = (const float*)d_in[13];
    const float *wv1 = (const float*)d_in[14], *bv1 = (const float*)d_in[15];
    const float *wq2 = (const float*)d_in[16], *bq2 = (const float*)d_in[17];
    const float *wk2 = (const float*)d_in[18], *bk2 = (const float*)d_in[19];
    const float *wv2 = (const float*)d_in[20], *bv2 = (const float*)d_in[21];
    const float *wd1 = (const float*)d_in[22], *bd1 = (const float*)d_in[23];
    const float *wd2 = (const float*)d_in[24], *bd2 = (const float*)d_in[25];
    const float *wpj = (const float*)d_in[26], *bpj = (const float*)d_in[27];
    const float *wr1 = (const float*)d_in[28], *br1 = (const float*)d_in[29];
    const float *wr2 = (const float*)d_in[30], *br2 = (const float*)d_in[31];

    float *part, *sum, *bqkv, *bc;
    ush *dwraw, *dwTh, *wAh, *wAl, *qTh, *qTl, *vraw, *vh, *Eh, *xTh, *wch;
    cudaGetSymbolAddress((void**)&dwraw, g_dwraw);
    cudaGetSymbolAddress((void**)&dwTh, g_dwTh);
    cudaGetSymbolAddress((void**)&wAh, g_wAh);   cudaGetSymbolAddress((void**)&wAl, g_wAl);
    cudaGetSymbolAddress((void**)&bqkv, g_bqkv);
    cudaGetSymbolAddress((void**)&qTh, g_qkvTh); cudaGetSymbolAddress((void**)&qTl, g_qkvTl);
    cudaGetSymbolAddress((void**)&vraw, g_vraw);
    cudaGetSymbolAddress((void**)&vh, g_vh);
    cudaGetSymbolAddress((void**)&Eh, g_Eh);
    cudaGetSymbolAddress((void**)&part, g_part); cudaGetSymbolAddress((void**)&sum, g_sum);
    cudaGetSymbolAddress((void**)&xTh, g_xTh);
    cudaGetSymbolAddress((void**)&wch, g_wch);
    cudaGetSymbolAddress((void**)&bc, g_bcat);

    const int SM_QKV = 4 * 2 * PL;
    const int SM_SAV = 4 * 2 * PL;
    const int SM_FIN = 3 * 2 * PL;

    cudaFuncSetAttribute(mma_k<0,0,4,2,80,0,1>, cudaFuncAttributeMaxDynamicSharedMemorySize, SM_QKV);
    cudaFuncSetAttribute(mma_k<0,0,4,2,2,0,1>,  cudaFuncAttributeMaxDynamicSharedMemorySize, SM_SAV);
    cudaFuncSetAttribute(mma_k<0,0,4,2,32,0,0>, cudaFuncAttributeMaxDynamicSharedMemorySize, SM_SAV);
    cudaFuncSetAttribute(mma_k<0,0,3,2,8,1,0>,  cudaFuncAttributeMaxDynamicSharedMemorySize, SM_FIN);

    const long long TT = (long long)HW * Cc;
    const long long TT384 = (long long)HW * 384;
    const long long SS = (long long)HW * HW;
    const long long XS = (long long)HW * 512;

    prep_k<<<7040, 256>>>(
        F_i, F_w, bn1g, bn2g, bn1b, bn2b, bn1m, bn2m, bn1v, bn2v,
        wd1, wd2, bd1, bd2, dwraw, xTh,
        wq1, wk1, wv1, wq2, wk2, wv2, bq1, bk1, bv1, bq2, bk2, bv2,
        wAh, wAl, bqkv,
        wpj, bpj, wr1, br1, wr2, br2, wch, bc);

    tsplit_k<<<dim3(128, 4, 8), 256>>>(dwraw, dwTh, TT);

    // QKV merged: M=384, N=4096, K=128, z = branch*4+batch  (1-pass, FULLK, smem epi)
    mma_k<0,0,4,2,80,0,1><<<dim3(32, 3, 8), 256, SM_QKV>>>(
        wAh, wAh, dwTh, dwTh, (float*)vraw, qTh, qTl, bqkv, 0,
        128, 128, 384, 128, 49152, TT, TT384,
        2, 0, 255, 0, TT, HW, 384);

    // S merged: z = attn*4+batch  (1-pass, FULLK, direct register epilogue)
    mma_k<0,0,4,2,2,0,1><<<dim3(32, 32, 8), 256, SM_SAV>>>(
        qTh, qTh, qTh + 128, qTh + 128, 0, Eh, 0, 0, part,
        384, 384, HW, 128, TT384, TT384, SS,
        0, 4, 255, 0, 0, 0, 0);

    rcpsum<<<128, 256>>>(part, sum);
    vscale<<<2048, 256>>>((const uint4*)vraw, (const float4*)sum, (uint4*)vh);

    // AV merged (flipped): direct fp16x2 register epilogue -> xT
    mma_k<0,0,4,2,32,0,0><<<dim3(1, 32, 8), 256, SM_SAV>>>(
        Eh, Eh, vh, vh, 0, xTh, xTh, 0, 0,
        HW, HW, 512, HW, SS, TT, XS,
        0, 4, 3, 128, 0, 0, 0);

    // out: M=256, N=4096, K=512  (1-pass fp16, direct fp32 epilogue)
    mma_k<0,0,3,2,8,1,0><<<dim3(32, 2, 4), 256, SM_FIN>>>(
        wch, wch, xTh, xTh, (float*)d_out, 0, 0, bc, 0,
        512, 512, HW, 512, 0, XS, (long long)OUTC * HW,
        0, 0, 255, 0, 0, 0, 0);
}